// round 3
// baseline (speedup 1.0000x reference)
#include <cuda_runtime.h>

#define NT 16384   // x rows
#define MS 4096    // sonata rows
#define NB 8       // batches
#define NH 8       // heads
#define DH 64      // head dim
#define NG 64      // slice groups
#define DM 512     // model dim
#define SCL 0.125f // D^-0.5

typedef unsigned long long u64;

__device__ __forceinline__ u64 pack2(float lo, float hi) {
    u64 r;
    asm("mov.b64 %0, {%1,%2};" : "=l"(r) : "f"(lo), "f"(hi));
    return r;
}
__device__ __forceinline__ float2 unpk2(u64 v) {
    float2 f;
    asm("mov.b64 {%0,%1}, %2;" : "=f"(f.x), "=f"(f.y) : "l"(v));
    return f;
}
__device__ __forceinline__ void fma2(u64& d, u64 a, u64 b) {
    asm("fma.rn.f32x2 %0, %1, %2, %3;" : "=l"(d) : "l"(a), "l"(b), "l"(d));
}

// ---------------- device scratch ----------------
__device__ float g_Wcomb[DM * DM];
__device__ float g_bcomb[DM];
__device__ float g_fx[(size_t)NT * DM];
__device__ float g_w[(size_t)NT * DM];        // logits, then softmax weights
__device__ float g_tokens[NB * NH * NG * DH];
__device__ float g_norms[NB * NH * NG];
__device__ float g_qkv[3 * NB * NH * NG * DH];
__device__ float g_outtok[NB * NH * NG * DH];
__device__ float g_ks[(size_t)MS * DM];
__device__ float g_vs[(size_t)MS * DM];
__device__ float g_scores[(size_t)NB * NH * NG * MS];  // 64 MB
__device__ float g_P[(size_t)NB * DM * DM];
__device__ int g_rowlist[NT], g_rowcnt[NB], g_rowstart[NB + 1], g_rowcur[NB];
__device__ int g_mlist[MS], g_mcnt[NB], g_mstart[NB + 1], g_mcur[NB];

// ---------------- setup kernels ----------------
__global__ void k_zero() {
    int i = blockIdx.x * 256 + threadIdx.x;
    if (i < NB * NH * NG * DH) g_tokens[i] = 0.f;
    if (i < NB * NH * NG) g_norms[i] = 0.f;
    if (i < NB) {
        g_rowcnt[i] = 0; g_mcnt[i] = 0;
        g_rowcur[i] = 0; g_mcur[i] = 0;
    }
}

// W_comb[c, h*64+g] = sum_d W_x[c, h*64+d] * W_slice[d, g]
__global__ void k_wcomb(const float* __restrict__ Wx, const float* __restrict__ Wsl) {
    __shared__ float s_sl[64 * 64];
    int t = threadIdx.x;
    for (int i = t; i < 4096; i += 256) s_sl[i] = Wsl[i];
    __syncthreads();
    int c = blockIdx.x;
    for (int o = t; o < 512; o += 256) {
        int h = o >> 6, g = o & 63;
        const float* wxr = Wx + (size_t)c * DM + h * 64;
        float acc = 0.f;
        for (int d = 0; d < 64; d++) acc = fmaf(wxr[d], s_sl[d * 64 + g], acc);
        g_Wcomb[(size_t)c * DM + o] = acc;
    }
}

__global__ void k_bcomb(const float* __restrict__ bx, const float* __restrict__ Wsl,
                        const float* __restrict__ bsl) {
    int o = threadIdx.x;  // 512
    int h = o >> 6, g = o & 63;
    float acc = bsl[g];
    for (int d = 0; d < 64; d++) acc = fmaf(bx[h * 64 + d], Wsl[d * 64 + g], acc);
    g_bcomb[o] = acc;
}

__global__ void k_count(const int* __restrict__ bi, const int* __restrict__ sbi) {
    int i = blockIdx.x * 256 + threadIdx.x;
    if (i < NT) atomicAdd(&g_rowcnt[bi[i]], 1);
    else if (i < NT + MS) atomicAdd(&g_mcnt[sbi[i - NT]], 1);
}

__global__ void k_prefix() {
    if (threadIdx.x == 0) {
        int s = 0;
        for (int b = 0; b < NB; b++) { g_rowstart[b] = s; s += g_rowcnt[b]; }
        g_rowstart[NB] = s;
        s = 0;
        for (int b = 0; b < NB; b++) { g_mstart[b] = s; s += g_mcnt[b]; }
        g_mstart[NB] = s;
    }
}

__global__ void k_scatter(const int* __restrict__ bi, const int* __restrict__ sbi) {
    int i = blockIdx.x * 256 + threadIdx.x;
    if (i < NT) {
        int b = bi[i];
        int p = atomicAdd(&g_rowcur[b], 1);
        g_rowlist[g_rowstart[b] + p] = i;
    } else if (i < NT + MS) {
        int j = i - NT;
        int b = sbi[j];
        int p = atomicAdd(&g_mcur[b], 1);
        g_mlist[g_mstart[b] + p] = j;
    }
}

// ---------------- front GEMM: [16384x512] @ [512x1024] -> fx | logits ----------------
// f32x2 packed-FMA mainloop: A tile stored broadcast-duplicated as u64 (a,a),
// B tile read as ulonglong2 (two packed f32x2 lanes per LDS.128).
__global__ void k_gemm_x(const float* __restrict__ x, const float* __restrict__ Wfx,
                         const float* __restrict__ bfx) {
    __shared__ u64 As2[16][64];
    __shared__ float Bs[16][64];
    int t = threadIdx.x;
    int tx = t & 15, ty = t >> 4;
    int row0 = blockIdx.y * 64;
    int col0 = blockIdx.x * 64;
    bool is_fx = (col0 < DM);
    const float* Bbase = is_fx ? (Wfx + col0) : (g_Wcomb + (col0 - DM));
    int ar = t >> 2;
    int akq = (t & 3) * 4;
    int bc = t & 63;
    int bk0 = t >> 6;
    u64 acc2[4][2] = {};
    for (int k0 = 0; k0 < DM; k0 += 16) {
        float4 a4 = *(const float4*)(x + (size_t)(row0 + ar) * DM + k0 + akq);
        As2[akq + 0][ar] = pack2(a4.x, a4.x);
        As2[akq + 1][ar] = pack2(a4.y, a4.y);
        As2[akq + 2][ar] = pack2(a4.z, a4.z);
        As2[akq + 3][ar] = pack2(a4.w, a4.w);
#pragma unroll
        for (int q = 0; q < 4; q++)
            Bs[bk0 + q * 4][bc] = Bbase[(size_t)(k0 + bk0 + q * 4) * DM + bc];
        __syncthreads();
#pragma unroll
        for (int kk = 0; kk < 16; kk++) {
            ulonglong2 bb = *(const ulonglong2*)&Bs[kk][tx * 4];
            u64 a0 = As2[kk][ty * 4 + 0];
            u64 a1 = As2[kk][ty * 4 + 1];
            u64 a2v = As2[kk][ty * 4 + 2];
            u64 a3 = As2[kk][ty * 4 + 3];
            fma2(acc2[0][0], a0, bb.x); fma2(acc2[0][1], a0, bb.y);
            fma2(acc2[1][0], a1, bb.x); fma2(acc2[1][1], a1, bb.y);
            fma2(acc2[2][0], a2v, bb.x); fma2(acc2[2][1], a2v, bb.y);
            fma2(acc2[3][0], a3, bb.x); fma2(acc2[3][1], a3, bb.y);
        }
        __syncthreads();
    }
#pragma unroll
    for (int i = 0; i < 4; i++) {
        int r = row0 + ty * 4 + i;
        int c = col0 + tx * 4;
        float2 p0 = unpk2(acc2[i][0]);
        float2 p1 = unpk2(acc2[i][1]);
        if (is_fx) {
            float4 o;
            o.x = p0.x + bfx[c + 0]; o.y = p0.y + bfx[c + 1];
            o.z = p1.x + bfx[c + 2]; o.w = p1.y + bfx[c + 3];
            *(float4*)&g_fx[(size_t)r * DM + c] = o;
        } else {
            int cw = c - DM;
            float4 o;
            o.x = p0.x + g_bcomb[cw + 0]; o.y = p0.y + g_bcomb[cw + 1];
            o.z = p1.x + g_bcomb[cw + 2]; o.w = p1.y + g_bcomb[cw + 3];
            *(float4*)&g_w[(size_t)r * DM + cw] = o;
        }
    }
}

// per-(n,h) softmax over 64 slice logits, in place in g_w
__global__ void k_softmax(const float* __restrict__ temp) {
    int n = blockIdx.x;
    int wid = threadIdx.x >> 5, lane = threadIdx.x & 31;
    float* p = g_w + (size_t)n * DM + wid * 64;
    float it = 1.f / temp[wid];
    float v0 = p[lane] * it, v1 = p[lane + 32] * it;
    float m = fmaxf(v0, v1);
#pragma unroll
    for (int o = 16; o; o >>= 1) m = fmaxf(m, __shfl_xor_sync(0xFFFFFFFFu, m, o));
    float e0 = __expf(v0 - m), e1 = __expf(v1 - m);
    float s = e0 + e1;
#pragma unroll
    for (int o = 16; o; o >>= 1) s += __shfl_xor_sync(0xFFFFFFFFu, s, o);
    float inv = 1.f / s;
    p[lane] = e0 * inv;
    p[lane + 32] = e1 * inv;
}

// tokens[b,h,g,d] = sum_{n in b} w[n,h,g] * fx[n,h,d]; norms[b,h,g] = sum w
__global__ void k_tokens() {
    int bh = blockIdx.x;
    int b = bh >> 3, h = bh & 7;
    int cnt = g_rowcnt[b], start = g_rowstart[b];
    int c0 = (int)(((long long)cnt * blockIdx.y) >> 4);
    int c1 = (int)(((long long)cnt * (blockIdx.y + 1)) >> 4);
    int t = threadIdx.x;
    int tg = (t >> 4) * 4, td = (t & 15) * 4;
    float acc[4][4] = {};
    float nacc[4] = {};
    __shared__ float ws[8][64], fs[8][64];
    __shared__ int rid[8];
    for (int i0 = c0; i0 < c1; i0 += 8) {
        int nr = c1 - i0; if (nr > 8) nr = 8;
        if (t < nr) rid[t] = g_rowlist[start + i0 + t];
        __syncthreads();
        for (int idx = t; idx < nr * 64; idx += 256) {
            int r = idx >> 6, c = idx & 63;
            size_t off = (size_t)rid[r] * DM + h * 64 + c;
            ws[r][c] = g_w[off];
            fs[r][c] = g_fx[off];
        }
        __syncthreads();
        for (int r = 0; r < nr; r++) {
            float wv[4], fv[4];
#pragma unroll
            for (int i = 0; i < 4; i++) { wv[i] = ws[r][tg + i]; fv[i] = fs[r][td + i]; }
#pragma unroll
            for (int i = 0; i < 4; i++) {
                if (td == 0) nacc[i] += wv[i];
#pragma unroll
                for (int j = 0; j < 4; j++) acc[i][j] = fmaf(wv[i], fv[j], acc[i][j]);
            }
        }
        __syncthreads();
    }
    float* tok = g_tokens + (size_t)bh * NG * DH;
#pragma unroll
    for (int i = 0; i < 4; i++) {
#pragma unroll
        for (int j = 0; j < 4; j++) atomicAdd(&tok[(tg + i) * DH + td + j], acc[i][j]);
        if (td == 0) atomicAdd(&g_norms[bh * NG + tg + i], nacc[i]);
    }
}

// q/k/v = normalized tokens @ W + b  (per (b,h), 64x64x64)
__global__ void k_qkv(const float* __restrict__ Wq, const float* __restrict__ bq,
                      const float* __restrict__ Wk, const float* __restrict__ bk,
                      const float* __restrict__ Wv, const float* __restrict__ bv) {
    int bh = blockIdx.x, sel = blockIdx.y;
    const float* W = sel == 0 ? Wq : (sel == 1 ? Wk : Wv);
    const float* bias = sel == 0 ? bq : (sel == 1 ? bk : bv);
    __shared__ float s_a[64][65];
    __shared__ float s_b[64][64];
    int t = threadIdx.x;
    for (int i = t; i < 4096; i += 256) {
        int g = i >> 6, d = i & 63;
        s_a[g][d] = g_tokens[(size_t)bh * 4096 + i] / (g_norms[bh * 64 + g] + 1e-5f);
        s_b[g][d] = W[i];
    }
    __syncthreads();
    int tx = t & 15, ty = t >> 4;
    float acc[4][4] = {};
    for (int k = 0; k < 64; k++) {
        float av[4], bv2[4];
#pragma unroll
        for (int i = 0; i < 4; i++) av[i] = s_a[ty * 4 + i][k];
#pragma unroll
        for (int j = 0; j < 4; j++) bv2[j] = s_b[k][tx * 4 + j];
#pragma unroll
        for (int i = 0; i < 4; i++)
#pragma unroll
            for (int j = 0; j < 4; j++) acc[i][j] = fmaf(av[i], bv2[j], acc[i][j]);
    }
    float* dst = g_qkv + ((size_t)sel * 64 + bh) * 4096;
#pragma unroll
    for (int i = 0; i < 4; i++)
#pragma unroll
        for (int j = 0; j < 4; j++)
            dst[(ty * 4 + i) * 64 + tx * 4 + j] = acc[i][j] + bias[tx * 4 + j];
}

// per-(b,h) 64x64 attention: out_tok = softmax(q k^T * SCL) @ v
__global__ void k_attn() {
    int bh = blockIdx.x;
    __shared__ float s_x[64][64];  // q, then v
    __shared__ float s_k[64][64];
    __shared__ float s_s[64][64];
    int t = threadIdx.x;
    const float* q = g_qkv + (size_t)bh * 4096;
    const float* kk_ = g_qkv + (size_t)(64 + bh) * 4096;
    const float* vv = g_qkv + (size_t)(128 + bh) * 4096;
    for (int i = t; i < 4096; i += 256) { s_x[i >> 6][i & 63] = q[i]; s_k[i >> 6][i & 63] = kk_[i]; }
    __syncthreads();
    int tx = t & 15, ty = t >> 4;
    {
        float acc[4][4] = {};
        for (int d = 0; d < 64; d++) {
            float av[4], bv[4];
#pragma unroll
            for (int i = 0; i < 4; i++) av[i] = s_x[ty * 4 + i][d];
#pragma unroll
            for (int j = 0; j < 4; j++) bv[j] = s_k[tx * 4 + j][d];
#pragma unroll
            for (int i = 0; i < 4; i++)
#pragma unroll
                for (int j = 0; j < 4; j++) acc[i][j] = fmaf(av[i], bv[j], acc[i][j]);
        }
#pragma unroll
        for (int i = 0; i < 4; i++)
#pragma unroll
            for (int j = 0; j < 4; j++) s_s[ty * 4 + i][tx * 4 + j] = acc[i][j] * SCL;
    }
    __syncthreads();
    for (int i = t; i < 4096; i += 256) s_x[i >> 6][i & 63] = vv[i];  // v over q
    if (t < 64) {
        float m = -1e30f;
        for (int j = 0; j < 64; j++) m = fmaxf(m, s_s[t][j]);
        float s = 0.f;
        for (int j = 0; j < 64; j++) { float e = __expf(s_s[t][j] - m); s_s[t][j] = e; s += e; }
        float inv = 1.f / s;
        for (int j = 0; j < 64; j++) s_s[t][j] *= inv;
    }
    __syncthreads();
    float acc[4][4] = {};
    for (int k2 = 0; k2 < 64; k2++) {
        float av[4], bv[4];
#pragma unroll
        for (int i = 0; i < 4; i++) av[i] = s_s[ty * 4 + i][k2];
#pragma unroll
        for (int j = 0; j < 4; j++) bv[j] = s_x[k2][tx * 4 + j];
#pragma unroll
        for (int i = 0; i < 4; i++)
#pragma unroll
            for (int j = 0; j < 4; j++) acc[i][j] = fmaf(av[i], bv[j], acc[i][j]);
    }
#pragma unroll
    for (int i = 0; i < 4; i++)
#pragma unroll
        for (int j = 0; j < 4; j++)
            g_outtok[(size_t)bh * 4096 + (ty * 4 + i) * 64 + tx * 4 + j] = acc[i][j];
}

// sonata ks/vs projection: [32768x64] @ [64x64] + bias
__global__ void k_skv(const float* __restrict__ son,
                      const float* __restrict__ Wck, const float* __restrict__ bck,
                      const float* __restrict__ Wcv, const float* __restrict__ bcv) {
    int rt = blockIdx.x;
    int sel = blockIdx.y;
    const float* W = sel ? Wcv : Wck;
    const float* bias = sel ? bcv : bck;
    float* dst = sel ? g_vs : g_ks;
    __shared__ float s_at[64][65];
    __shared__ float s_b[64][64];
    int t = threadIdx.x;
    size_t base = (size_t)rt * 64 * 64;
    for (int i = t; i < 4096; i += 256) {
        s_at[i & 63][i >> 6] = son[base + i];
        s_b[i >> 6][i & 63] = W[i];
    }
    __syncthreads();
    int tx = t & 15, ty = t >> 4;
    float acc[4][4] = {};
    for (int k = 0; k < 64; k++) {
        float av[4], bv2[4];
#pragma unroll
        for (int i = 0; i < 4; i++) av[i] = s_at[k][ty * 4 + i];
#pragma unroll
        for (int j = 0; j < 4; j++) bv2[j] = s_b[k][tx * 4 + j];
#pragma unroll
        for (int i = 0; i < 4; i++)
#pragma unroll
            for (int j = 0; j < 4; j++) acc[i][j] = fmaf(av[i], bv2[j], acc[i][j]);
    }
#pragma unroll
    for (int i = 0; i < 4; i++)
#pragma unroll
        for (int j = 0; j < 4; j++)
            dst[base + (size_t)(ty * 4 + i) * 64 + tx * 4 + j] = acc[i][j] + bias[tx * 4 + j];
}

// per-(b,h): masked cross attention over sonata rows of batch b, out_tok += cw @ vs
__global__ void k_cross() {
    int bh = blockIdx.x, b = bh >> 3, h = bh & 7;
    int cnt = g_mcnt[b], start = g_mstart[b];
    if (cnt == 0) return;
    __shared__ float s_q[64][65];
    __shared__ float s_kv[32][64];
    __shared__ float s_cw[64][33];
    __shared__ float red[64][4];
    __shared__ int mid[32];
    int t = threadIdx.x;
    for (int i = t; i < 4096; i += 256) s_q[i >> 6][i & 63] = g_outtok[(size_t)bh * 4096 + i];
    __syncthreads();
    float* sc = g_scores + (size_t)bh * 64 * MS;
    // phase B: scores
    for (int j0 = 0; j0 < cnt; j0 += 32) {
        int nj = cnt - j0; if (nj > 32) nj = 32;
        if (t < nj) mid[t] = g_mlist[start + j0 + t];
        __syncthreads();
        for (int i = t; i < nj * 64; i += 256) {
            int r = i >> 6, c = i & 63;
            s_kv[r][c] = g_ks[(size_t)mid[r] * DM + h * 64 + c];
        }
        __syncthreads();
        int g = t & 63, jp = t >> 6;
        for (int j = jp; j < nj; j += 4) {
            float a = 0.f;
#pragma unroll 16
            for (int d = 0; d < 64; d++) a = fmaf(s_q[g][d], s_kv[j][d], a);
            sc[(size_t)g * MS + j0 + j] = a * SCL;
        }
        __syncthreads();
    }
    // phase C: row softmax over cnt entries
    {
        int g = t >> 2, part = t & 3;
        float m = -1e30f;
        for (int j = part; j < cnt; j += 4) m = fmaxf(m, sc[(size_t)g * MS + j]);
        red[g][part] = m;
        __syncthreads();
        m = fmaxf(fmaxf(red[g][0], red[g][1]), fmaxf(red[g][2], red[g][3]));
        float s = 0.f;
        for (int j = part; j < cnt; j += 4) s += __expf(sc[(size_t)g * MS + j] - m);
        __syncthreads();
        red[g][part] = s;
        __syncthreads();
        s = red[g][0] + red[g][1] + red[g][2] + red[g][3];
        float inv = 1.f / s;
        for (int j = part; j < cnt; j += 4)
            sc[(size_t)g * MS + j] = __expf(sc[(size_t)g * MS + j] - m) * inv;
    }
    __syncthreads();
    // phase D: out_tok += cw @ vs
    int tx = t & 15, ty = t >> 4;
    float acc[4][4] = {};
    for (int j0 = 0; j0 < cnt; j0 += 32) {
        int nj = cnt - j0; if (nj > 32) nj = 32;
        if (t < nj) mid[t] = g_mlist[start + j0 + t];
        __syncthreads();
        for (int i = t; i < nj * 64; i += 256) {
            int r = i >> 6, c = i & 63;
            s_kv[r][c] = g_vs[(size_t)mid[r] * DM + h * 64 + c];
        }
        for (int i = t; i < 64 * 32; i += 256) {
            int g = i >> 5, j = i & 31;
            s_cw[g][j] = (j < nj) ? sc[(size_t)g * MS + j0 + j] : 0.f;
        }
        __syncthreads();
        for (int j = 0; j < nj; j++) {
            float vvv[4];
#pragma unroll
            for (int jj = 0; jj < 4; jj++) vvv[jj] = s_kv[j][tx * 4 + jj];
#pragma unroll
            for (int i = 0; i < 4; i++) {
                float c = s_cw[ty * 4 + i][j];
#pragma unroll
                for (int jj = 0; jj < 4; jj++) acc[i][jj] = fmaf(c, vvv[jj], acc[i][jj]);
            }
        }
        __syncthreads();
    }
#pragma unroll
    for (int i = 0; i < 4; i++)
#pragma unroll
        for (int jj = 0; jj < 4; jj++) {
            size_t o = (size_t)bh * 4096 + (ty * 4 + i) * 64 + tx * 4 + jj;
            g_outtok[o] += acc[i][jj];
        }
}

// P[b, h*64+g, c] = sum_d out_tok[b,h,g,d] * W_out[h*64+d, c]
__global__ void k_P(const float* __restrict__ Wout) {
    int bh = blockIdx.x, b = bh >> 3, h = bh & 7;
    int col0 = blockIdx.y * 64;
    __shared__ float s_a[64][65];
    __shared__ float s_b[64][64];
    int t = threadIdx.x;
    for (int i = t; i < 4096; i += 256) {
        int r = i >> 6, c = i & 63;
        s_a[r][c] = g_outtok[(size_t)bh * 4096 + i];
        s_b[r][c] = Wout[(size_t)(h * 64 + r) * DM + col0 + c];
    }
    __syncthreads();
    int tx = t & 15, ty = t >> 4;
    float acc[4][4] = {};
    for (int d = 0; d < 64; d++) {
        float av[4], bv[4];
#pragma unroll
        for (int i = 0; i < 4; i++) av[i] = s_a[ty * 4 + i][d];
#pragma unroll
        for (int j = 0; j < 4; j++) bv[j] = s_b[d][tx * 4 + j];
#pragma unroll
        for (int i = 0; i < 4; i++)
#pragma unroll
            for (int j = 0; j < 4; j++) acc[i][j] = fmaf(av[i], bv[j], acc[i][j]);
    }
    float* dst = g_P + (size_t)b * DM * DM;
#pragma unroll
    for (int i = 0; i < 4; i++)
#pragma unroll
        for (int j = 0; j < 4; j++)
            dst[(size_t)(h * 64 + ty * 4 + i) * DM + col0 + tx * 4 + j] = acc[i][j];
}

// out[n, :] = w[n, :] @ P[batch(n)]   (gathered rows per batch)
// f32x2 packed-FMA mainloop, same scheme as k_gemm_x.
__global__ void k_final(float* __restrict__ out) {
    int b = blockIdx.z;
    int cnt = g_rowcnt[b];
    int r0 = blockIdx.y * 64;
    if (r0 >= cnt) return;
    int nr = cnt - r0; if (nr > 64) nr = 64;
    int start = g_rowstart[b];
    __shared__ int rid[64];
    __shared__ u64 As2[16][64];
    __shared__ float Bs[16][64];
    int t = threadIdx.x;
    if (t < 64) {
        int ii = t < nr ? t : nr - 1;
        rid[t] = g_rowlist[start + r0 + ii];
    }
    __syncthreads();
    int tx = t & 15, ty = t >> 4;
    int col0 = blockIdx.x * 64;
    int ar = t >> 2;
    int akq = (t & 3) * 4;
    int bc = t & 63;
    int bk0 = t >> 6;
    const float* P = g_P + (size_t)b * DM * DM;
    u64 acc2[4][2] = {};
    for (int k0 = 0; k0 < DM; k0 += 16) {
        float4 a4 = *(const float4*)(g_w + (size_t)rid[ar] * DM + k0 + akq);
        As2[akq + 0][ar] = pack2(a4.x, a4.x);
        As2[akq + 1][ar] = pack2(a4.y, a4.y);
        As2[akq + 2][ar] = pack2(a4.z, a4.z);
        As2[akq + 3][ar] = pack2(a4.w, a4.w);
#pragma unroll
        for (int q = 0; q < 4; q++)
            Bs[bk0 + q * 4][bc] = P[(size_t)(k0 + bk0 + q * 4) * DM + col0 + bc];
        __syncthreads();
#pragma unroll
        for (int kk = 0; kk < 16; kk++) {
            ulonglong2 bb = *(const ulonglong2*)&Bs[kk][tx * 4];
            u64 a0 = As2[kk][ty * 4 + 0];
            u64 a1 = As2[kk][ty * 4 + 1];
            u64 a2v = As2[kk][ty * 4 + 2];
            u64 a3 = As2[kk][ty * 4 + 3];
            fma2(acc2[0][0], a0, bb.x); fma2(acc2[0][1], a0, bb.y);
            fma2(acc2[1][0], a1, bb.x); fma2(acc2[1][1], a1, bb.y);
            fma2(acc2[2][0], a2v, bb.x); fma2(acc2[2][1], a2v, bb.y);
            fma2(acc2[3][0], a3, bb.x); fma2(acc2[3][1], a3, bb.y);
        }
        __syncthreads();
    }
#pragma unroll
    for (int i = 0; i < 4; i++) {
        int rl = ty * 4 + i;
        if (rl < nr) {
            size_t r = rid[rl];
            float2 p0 = unpk2(acc2[i][0]);
            float2 p1 = unpk2(acc2[i][1]);
            float4 o; o.x = p0.x; o.y = p0.y; o.z = p1.x; o.w = p1.y;
            *(float4*)&out[r * DM + col0 + tx * 4] = o;
        }
    }
}

extern "C" void kernel_launch(void* const* d_in, const int* in_sizes, int n_in,
                              void* d_out, int out_size) {
    const float* x    = (const float*)d_in[0];
    const int*   bi   = (const int*)d_in[1];
    const float* son  = (const float*)d_in[2];
    const int*   sbi  = (const int*)d_in[3];
    const float* temp = (const float*)d_in[4];
    const float* Wfx  = (const float*)d_in[5];
    const float* bfx  = (const float*)d_in[6];
    const float* Wx   = (const float*)d_in[7];
    const float* bx   = (const float*)d_in[8];
    const float* Wsl  = (const float*)d_in[9];
    const float* bsl  = (const float*)d_in[10];
    const float* Wq   = (const float*)d_in[11];
    const float* bq   = (const float*)d_in[12];
    const float* Wk   = (const float*)d_in[13];
    const float* bk   = (const float*)d_in[14];
    const float* Wv   = (const float*)d_in[15];
    const float* bv   = (const float*)d_in[16];
    const float* Wck  = (const float*)d_in[17];
    const float* bck  = (const float*)d_in[18];
    const float* Wcv  = (const float*)d_in[19];
    const float* bcv  = (const float*)d_in[20];
    const float* Wout = (const float*)d_in[21];
    float* out = (float*)d_out;

    k_zero<<<1024, 256>>>();
    k_wcomb<<<512, 256>>>(Wx, Wsl);
    k_bcomb<<<1, 512>>>(bx, Wsl, bsl);
    k_count<<<80, 256>>>(bi, sbi);
    k_prefix<<<1, 1>>>();
    k_scatter<<<80, 256>>>(bi, sbi);
    k_gemm_x<<<dim3(16, 256), 256>>>(x, Wfx, bfx);
    k_softmax<<<NT, 256>>>(temp);
    k_tokens<<<dim3(64, 16), 256>>>();
    k_qkv<<<dim3(64, 3), 256>>>(Wq, bq, Wk, bk, Wv, bv);
    k_attn<<<64, 256>>>();
    k_skv<<<dim3(512, 2), 256>>>(son, Wck, bck, Wcv, bcv);
    k_cross<<<64, 256>>>();
    k_P<<<dim3(64, 8), 256>>>(Wout);
    k_final<<<dim3(8, 256, 8), 256>>>(out);
}

// round 4
// speedup vs baseline: 1.2305x; 1.2305x over previous
#include <cuda_runtime.h>

#define NT 16384   // x rows
#define MS 4096    // sonata rows
#define NB 8       // batches
#define NH 8       // heads
#define DH 64      // head dim
#define NG 64      // slice groups
#define DM 512     // model dim
#define SCL 0.125f // D^-0.5

// ---------------- device scratch ----------------
__device__ float g_Wcomb[DM * DM];
__device__ float g_bcomb[DM];
__device__ float g_fx[(size_t)NT * DM];
__device__ float g_w[(size_t)NT * DM];        // logits, then softmax weights
__device__ float g_tokens[NB * NH * NG * DH];
__device__ float g_norms[NB * NH * NG];
__device__ float g_qkv[3 * NB * NH * NG * DH];
__device__ float g_outtok[NB * NH * NG * DH];
__device__ float g_ks[(size_t)MS * DM];
__device__ float g_vs[(size_t)MS * DM];
__device__ float g_scores[(size_t)NB * NH * NG * MS];  // 64 MB
__device__ float g_P[(size_t)NB * DM * DM];
__device__ int g_rowlist[NT], g_rowcnt[NB], g_rowstart[NB + 1], g_rowcur[NB];
__device__ int g_mlist[MS], g_mcnt[NB], g_mstart[NB + 1], g_mcur[NB];

// ---------------- setup kernels ----------------
__global__ void k_zero() {
    int i = blockIdx.x * 256 + threadIdx.x;
    if (i < NB * NH * NG * DH) g_tokens[i] = 0.f;
    if (i < NB * NH * NG) g_norms[i] = 0.f;
    if (i < NB) {
        g_rowcnt[i] = 0; g_mcnt[i] = 0;
        g_rowcur[i] = 0; g_mcur[i] = 0;
    }
}

// W_comb[c, h*64+g] = sum_d W_x[c, h*64+d] * W_slice[d, g]
__global__ void k_wcomb(const float* __restrict__ Wx, const float* __restrict__ Wsl) {
    __shared__ float s_sl[64 * 64];
    int t = threadIdx.x;
    for (int i = t; i < 4096; i += 256) s_sl[i] = Wsl[i];
    __syncthreads();
    int c = blockIdx.x;
    for (int o = t; o < 512; o += 256) {
        int h = o >> 6, g = o & 63;
        const float* wxr = Wx + (size_t)c * DM + h * 64;
        float acc = 0.f;
        for (int d = 0; d < 64; d++) acc = fmaf(wxr[d], s_sl[d * 64 + g], acc);
        g_Wcomb[(size_t)c * DM + o] = acc;
    }
}

__global__ void k_bcomb(const float* __restrict__ bx, const float* __restrict__ Wsl,
                        const float* __restrict__ bsl) {
    int o = threadIdx.x;  // 512
    int h = o >> 6, g = o & 63;
    float acc = bsl[g];
    for (int d = 0; d < 64; d++) acc = fmaf(bx[h * 64 + d], Wsl[d * 64 + g], acc);
    g_bcomb[o] = acc;
}

__global__ void k_count(const int* __restrict__ bi, const int* __restrict__ sbi) {
    int i = blockIdx.x * 256 + threadIdx.x;
    if (i < NT) atomicAdd(&g_rowcnt[bi[i]], 1);
    else if (i < NT + MS) atomicAdd(&g_mcnt[sbi[i - NT]], 1);
}

__global__ void k_prefix() {
    if (threadIdx.x == 0) {
        int s = 0;
        for (int b = 0; b < NB; b++) { g_rowstart[b] = s; s += g_rowcnt[b]; }
        g_rowstart[NB] = s;
        s = 0;
        for (int b = 0; b < NB; b++) { g_mstart[b] = s; s += g_mcnt[b]; }
        g_mstart[NB] = s;
    }
}

__global__ void k_scatter(const int* __restrict__ bi, const int* __restrict__ sbi) {
    int i = blockIdx.x * 256 + threadIdx.x;
    if (i < NT) {
        int b = bi[i];
        int p = atomicAdd(&g_rowcur[b], 1);
        g_rowlist[g_rowstart[b] + p] = i;
    } else if (i < NT + MS) {
        int j = i - NT;
        int b = sbi[j];
        int p = atomicAdd(&g_mcur[b], 1);
        g_mlist[g_mstart[b] + p] = j;
    }
}

// ---------------- front GEMM: [16384x512] @ [512x1024] -> fx | logits ----------------
// Double-buffered shared tiles + register prefetch: next tile's LDGs issue
// before the 256-FMA compute block, STS into the ping-pong buffer after.
__global__ void k_gemm_x(const float* __restrict__ x, const float* __restrict__ Wfx,
                         const float* __restrict__ bfx) {
    __shared__ float As[2][16][64];
    __shared__ float Bs[2][16][64];
    int t = threadIdx.x;
    int tx = t & 15, ty = t >> 4;
    int row0 = blockIdx.y * 64;
    int col0 = blockIdx.x * 64;
    bool is_fx = (col0 < DM);
    const float* Bbase = is_fx ? (Wfx + col0) : (g_Wcomb + (col0 - DM));
    int ar = t >> 2;          // 0..63 row in A tile
    int akq = (t & 3) * 4;    // 0,4,8,12 k-quad
    int bk = t >> 4;          // 0..15 k-row in B tile
    int bcq = (t & 15) * 4;   // col quad
    const float* aptr = x + (size_t)(row0 + ar) * DM + akq;
    const float* bptr = Bbase + (size_t)bk * DM + bcq;
    float acc[4][4] = {};
    float4 a4 = *(const float4*)(aptr);
    float4 b4 = *(const float4*)(bptr);
    As[0][akq + 0][ar] = a4.x; As[0][akq + 1][ar] = a4.y;
    As[0][akq + 2][ar] = a4.z; As[0][akq + 3][ar] = a4.w;
    *(float4*)&Bs[0][bk][bcq] = b4;
    __syncthreads();
#pragma unroll 1
    for (int it = 0; it < DM / 16; it++) {
        int buf = it & 1;
        if (it + 1 < DM / 16) {
            a4 = *(const float4*)(aptr + (it + 1) * 16);
            b4 = *(const float4*)(bptr + (size_t)(it + 1) * 16 * DM);
        }
#pragma unroll
        for (int kk = 0; kk < 16; kk++) {
            float4 av4 = *(const float4*)&As[buf][kk][ty * 4];
            float4 bv4 = *(const float4*)&Bs[buf][kk][tx * 4];
            float av[4] = {av4.x, av4.y, av4.z, av4.w};
            float bv[4] = {bv4.x, bv4.y, bv4.z, bv4.w};
#pragma unroll
            for (int i = 0; i < 4; i++)
#pragma unroll
                for (int j = 0; j < 4; j++) acc[i][j] = fmaf(av[i], bv[j], acc[i][j]);
        }
        if (it + 1 < DM / 16) {
            int nb = buf ^ 1;
            As[nb][akq + 0][ar] = a4.x; As[nb][akq + 1][ar] = a4.y;
            As[nb][akq + 2][ar] = a4.z; As[nb][akq + 3][ar] = a4.w;
            *(float4*)&Bs[nb][bk][bcq] = b4;
        }
        __syncthreads();
    }
#pragma unroll
    for (int i = 0; i < 4; i++) {
        int r = row0 + ty * 4 + i;
        int c = col0 + tx * 4;
        if (is_fx) {
            float4 o;
            o.x = acc[i][0] + bfx[c + 0]; o.y = acc[i][1] + bfx[c + 1];
            o.z = acc[i][2] + bfx[c + 2]; o.w = acc[i][3] + bfx[c + 3];
            *(float4*)&g_fx[(size_t)r * DM + c] = o;
        } else {
            int cw = c - DM;
            float4 o;
            o.x = acc[i][0] + g_bcomb[cw + 0]; o.y = acc[i][1] + g_bcomb[cw + 1];
            o.z = acc[i][2] + g_bcomb[cw + 2]; o.w = acc[i][3] + g_bcomb[cw + 3];
            *(float4*)&g_w[(size_t)r * DM + cw] = o;
        }
    }
}

// per-(n,h) softmax over 64 slice logits, in place in g_w
__global__ void k_softmax(const float* __restrict__ temp) {
    int n = blockIdx.x;
    int wid = threadIdx.x >> 5, lane = threadIdx.x & 31;
    float* p = g_w + (size_t)n * DM + wid * 64;
    float it = 1.f / temp[wid];
    float v0 = p[lane] * it, v1 = p[lane + 32] * it;
    float m = fmaxf(v0, v1);
#pragma unroll
    for (int o = 16; o; o >>= 1) m = fmaxf(m, __shfl_xor_sync(0xFFFFFFFFu, m, o));
    float e0 = __expf(v0 - m), e1 = __expf(v1 - m);
    float s = e0 + e1;
#pragma unroll
    for (int o = 16; o; o >>= 1) s += __shfl_xor_sync(0xFFFFFFFFu, s, o);
    float inv = 1.f / s;
    p[lane] = e0 * inv;
    p[lane + 32] = e1 * inv;
}

// tokens[b,h,g,d] = sum_{n in b} w[n,h,g] * fx[n,h,d]; norms[b,h,g] = sum w
__global__ void k_tokens() {
    int bh = blockIdx.x;
    int b = bh >> 3, h = bh & 7;
    int cnt = g_rowcnt[b], start = g_rowstart[b];
    int c0 = (int)(((long long)cnt * blockIdx.y) >> 4);
    int c1 = (int)(((long long)cnt * (blockIdx.y + 1)) >> 4);
    int t = threadIdx.x;
    int tg = (t >> 4) * 4, td = (t & 15) * 4;
    float acc[4][4] = {};
    float nacc[4] = {};
    __shared__ float ws[8][64], fs[8][64];
    __shared__ int rid[8];
    for (int i0 = c0; i0 < c1; i0 += 8) {
        int nr = c1 - i0; if (nr > 8) nr = 8;
        if (t < nr) rid[t] = g_rowlist[start + i0 + t];
        __syncthreads();
        for (int idx = t; idx < nr * 64; idx += 256) {
            int r = idx >> 6, c = idx & 63;
            size_t off = (size_t)rid[r] * DM + h * 64 + c;
            ws[r][c] = g_w[off];
            fs[r][c] = g_fx[off];
        }
        __syncthreads();
        for (int r = 0; r < nr; r++) {
            float wv[4], fv[4];
#pragma unroll
            for (int i = 0; i < 4; i++) { wv[i] = ws[r][tg + i]; fv[i] = fs[r][td + i]; }
#pragma unroll
            for (int i = 0; i < 4; i++) {
                if (td == 0) nacc[i] += wv[i];
#pragma unroll
                for (int j = 0; j < 4; j++) acc[i][j] = fmaf(wv[i], fv[j], acc[i][j]);
            }
        }
        __syncthreads();
    }
    float* tok = g_tokens + (size_t)bh * NG * DH;
#pragma unroll
    for (int i = 0; i < 4; i++) {
#pragma unroll
        for (int j = 0; j < 4; j++) atomicAdd(&tok[(tg + i) * DH + td + j], acc[i][j]);
        if (td == 0) atomicAdd(&g_norms[bh * NG + tg + i], nacc[i]);
    }
}

// q/k/v = normalized tokens @ W + b  (per (b,h), 64x64x64)
__global__ void k_qkv(const float* __restrict__ Wq, const float* __restrict__ bq,
                      const float* __restrict__ Wk, const float* __restrict__ bk,
                      const float* __restrict__ Wv, const float* __restrict__ bv) {
    int bh = blockIdx.x, sel = blockIdx.y;
    const float* W = sel == 0 ? Wq : (sel == 1 ? Wk : Wv);
    const float* bias = sel == 0 ? bq : (sel == 1 ? bk : bv);
    __shared__ float s_a[64][65];
    __shared__ float s_b[64][64];
    int t = threadIdx.x;
    for (int i = t; i < 4096; i += 256) {
        int g = i >> 6, d = i & 63;
        s_a[g][d] = g_tokens[(size_t)bh * 4096 + i] / (g_norms[bh * 64 + g] + 1e-5f);
        s_b[g][d] = W[i];
    }
    __syncthreads();
    int tx = t & 15, ty = t >> 4;
    float acc[4][4] = {};
    for (int k = 0; k < 64; k++) {
        float av[4], bv2[4];
#pragma unroll
        for (int i = 0; i < 4; i++) av[i] = s_a[ty * 4 + i][k];
#pragma unroll
        for (int j = 0; j < 4; j++) bv2[j] = s_b[k][tx * 4 + j];
#pragma unroll
        for (int i = 0; i < 4; i++)
#pragma unroll
            for (int j = 0; j < 4; j++) acc[i][j] = fmaf(av[i], bv2[j], acc[i][j]);
    }
    float* dst = g_qkv + ((size_t)sel * 64 + bh) * 4096;
#pragma unroll
    for (int i = 0; i < 4; i++)
#pragma unroll
        for (int j = 0; j < 4; j++)
            dst[(ty * 4 + i) * 64 + tx * 4 + j] = acc[i][j] + bias[tx * 4 + j];
}

// per-(b,h) 64x64 attention: out_tok = softmax(q k^T * SCL) @ v
__global__ void k_attn() {
    int bh = blockIdx.x;
    __shared__ float s_x[64][64];  // q, then v
    __shared__ float s_k[64][64];
    __shared__ float s_s[64][64];
    int t = threadIdx.x;
    const float* q = g_qkv + (size_t)bh * 4096;
    const float* kk_ = g_qkv + (size_t)(64 + bh) * 4096;
    const float* vv = g_qkv + (size_t)(128 + bh) * 4096;
    for (int i = t; i < 4096; i += 256) { s_x[i >> 6][i & 63] = q[i]; s_k[i >> 6][i & 63] = kk_[i]; }
    __syncthreads();
    int tx = t & 15, ty = t >> 4;
    {
        float acc[4][4] = {};
        for (int d = 0; d < 64; d++) {
            float av[4], bv[4];
#pragma unroll
            for (int i = 0; i < 4; i++) av[i] = s_x[ty * 4 + i][d];
#pragma unroll
            for (int j = 0; j < 4; j++) bv[j] = s_k[tx * 4 + j][d];
#pragma unroll
            for (int i = 0; i < 4; i++)
#pragma unroll
                for (int j = 0; j < 4; j++) acc[i][j] = fmaf(av[i], bv[j], acc[i][j]);
        }
#pragma unroll
        for (int i = 0; i < 4; i++)
#pragma unroll
            for (int j = 0; j < 4; j++) s_s[ty * 4 + i][tx * 4 + j] = acc[i][j] * SCL;
    }
    __syncthreads();
    for (int i = t; i < 4096; i += 256) s_x[i >> 6][i & 63] = vv[i];  // v over q
    if (t < 64) {
        float m = -1e30f;
        for (int j = 0; j < 64; j++) m = fmaxf(m, s_s[t][j]);
        float s = 0.f;
        for (int j = 0; j < 64; j++) { float e = __expf(s_s[t][j] - m); s_s[t][j] = e; s += e; }
        float inv = 1.f / s;
        for (int j = 0; j < 64; j++) s_s[t][j] *= inv;
    }
    __syncthreads();
    float acc[4][4] = {};
    for (int k2 = 0; k2 < 64; k2++) {
        float av[4], bv[4];
#pragma unroll
        for (int i = 0; i < 4; i++) av[i] = s_s[ty * 4 + i][k2];
#pragma unroll
        for (int j = 0; j < 4; j++) bv[j] = s_x[k2][tx * 4 + j];
#pragma unroll
        for (int i = 0; i < 4; i++)
#pragma unroll
            for (int j = 0; j < 4; j++) acc[i][j] = fmaf(av[i], bv[j], acc[i][j]);
    }
#pragma unroll
    for (int i = 0; i < 4; i++)
#pragma unroll
        for (int j = 0; j < 4; j++)
            g_outtok[(size_t)bh * 4096 + (ty * 4 + i) * 64 + tx * 4 + j] = acc[i][j];
}

// sonata ks/vs projection: [32768x64] @ [64x64] + bias
__global__ void k_skv(const float* __restrict__ son,
                      const float* __restrict__ Wck, const float* __restrict__ bck,
                      const float* __restrict__ Wcv, const float* __restrict__ bcv) {
    int rt = blockIdx.x;
    int sel = blockIdx.y;
    const float* W = sel ? Wcv : Wck;
    const float* bias = sel ? bcv : bck;
    float* dst = sel ? g_vs : g_ks;
    __shared__ float s_at[64][65];
    __shared__ float s_b[64][64];
    int t = threadIdx.x;
    size_t base = (size_t)rt * 64 * 64;
    for (int i = t; i < 4096; i += 256) {
        s_at[i & 63][i >> 6] = son[base + i];
        s_b[i >> 6][i & 63] = W[i];
    }
    __syncthreads();
    int tx = t & 15, ty = t >> 4;
    float acc[4][4] = {};
    for (int k = 0; k < 64; k++) {
        float av[4], bv2[4];
#pragma unroll
        for (int i = 0; i < 4; i++) av[i] = s_at[k][ty * 4 + i];
#pragma unroll
        for (int j = 0; j < 4; j++) bv2[j] = s_b[k][tx * 4 + j];
#pragma unroll
        for (int i = 0; i < 4; i++)
#pragma unroll
            for (int j = 0; j < 4; j++) acc[i][j] = fmaf(av[i], bv2[j], acc[i][j]);
    }
#pragma unroll
    for (int i = 0; i < 4; i++)
#pragma unroll
        for (int j = 0; j < 4; j++)
            dst[base + (size_t)(ty * 4 + i) * 64 + tx * 4 + j] = acc[i][j] + bias[tx * 4 + j];
}

// per-(b,h): masked cross attention over sonata rows of batch b, out_tok += cw @ vs
__global__ void k_cross() {
    int bh = blockIdx.x, b = bh >> 3, h = bh & 7;
    int cnt = g_mcnt[b], start = g_mstart[b];
    if (cnt == 0) return;
    __shared__ float s_q[64][65];
    __shared__ float s_kv[32][64];
    __shared__ float s_cw[64][33];
    __shared__ float red[64][4];
    __shared__ int mid[32];
    int t = threadIdx.x;
    for (int i = t; i < 4096; i += 256) s_q[i >> 6][i & 63] = g_outtok[(size_t)bh * 4096 + i];
    __syncthreads();
    float* sc = g_scores + (size_t)bh * 64 * MS;
    // phase B: scores
    for (int j0 = 0; j0 < cnt; j0 += 32) {
        int nj = cnt - j0; if (nj > 32) nj = 32;
        if (t < nj) mid[t] = g_mlist[start + j0 + t];
        __syncthreads();
        for (int i = t; i < nj * 64; i += 256) {
            int r = i >> 6, c = i & 63;
            s_kv[r][c] = g_ks[(size_t)mid[r] * DM + h * 64 + c];
        }
        __syncthreads();
        int g = t & 63, jp = t >> 6;
        for (int j = jp; j < nj; j += 4) {
            float a = 0.f;
#pragma unroll 16
            for (int d = 0; d < 64; d++) a = fmaf(s_q[g][d], s_kv[j][d], a);
            sc[(size_t)g * MS + j0 + j] = a * SCL;
        }
        __syncthreads();
    }
    // phase C: row softmax over cnt entries
    {
        int g = t >> 2, part = t & 3;
        float m = -1e30f;
        for (int j = part; j < cnt; j += 4) m = fmaxf(m, sc[(size_t)g * MS + j]);
        red[g][part] = m;
        __syncthreads();
        m = fmaxf(fmaxf(red[g][0], red[g][1]), fmaxf(red[g][2], red[g][3]));
        float s = 0.f;
        for (int j = part; j < cnt; j += 4) s += __expf(sc[(size_t)g * MS + j] - m);
        __syncthreads();
        red[g][part] = s;
        __syncthreads();
        s = red[g][0] + red[g][1] + red[g][2] + red[g][3];
        float inv = 1.f / s;
        for (int j = part; j < cnt; j += 4)
            sc[(size_t)g * MS + j] = __expf(sc[(size_t)g * MS + j] - m) * inv;
    }
    __syncthreads();
    // phase D: out_tok += cw @ vs
    int tx = t & 15, ty = t >> 4;
    float acc[4][4] = {};
    for (int j0 = 0; j0 < cnt; j0 += 32) {
        int nj = cnt - j0; if (nj > 32) nj = 32;
        if (t < nj) mid[t] = g_mlist[start + j0 + t];
        __syncthreads();
        for (int i = t; i < nj * 64; i += 256) {
            int r = i >> 6, c = i & 63;
            s_kv[r][c] = g_vs[(size_t)mid[r] * DM + h * 64 + c];
        }
        for (int i = t; i < 64 * 32; i += 256) {
            int g = i >> 5, j = i & 31;
            s_cw[g][j] = (j < nj) ? sc[(size_t)g * MS + j0 + j] : 0.f;
        }
        __syncthreads();
        for (int j = 0; j < nj; j++) {
            float vvv[4];
#pragma unroll
            for (int jj = 0; jj < 4; jj++) vvv[jj] = s_kv[j][tx * 4 + jj];
#pragma unroll
            for (int i = 0; i < 4; i++) {
                float c = s_cw[ty * 4 + i][j];
#pragma unroll
                for (int jj = 0; jj < 4; jj++) acc[i][jj] = fmaf(c, vvv[jj], acc[i][jj]);
            }
        }
        __syncthreads();
    }
#pragma unroll
    for (int i = 0; i < 4; i++)
#pragma unroll
        for (int jj = 0; jj < 4; jj++) {
            size_t o = (size_t)bh * 4096 + (ty * 4 + i) * 64 + tx * 4 + jj;
            g_outtok[o] += acc[i][jj];
        }
}

// P[b, h*64+g, c] = sum_d out_tok[b,h,g,d] * W_out[h*64+d, c]
__global__ void k_P(const float* __restrict__ Wout) {
    int bh = blockIdx.x, b = bh >> 3, h = bh & 7;
    int col0 = blockIdx.y * 64;
    __shared__ float s_a[64][65];
    __shared__ float s_b[64][64];
    int t = threadIdx.x;
    for (int i = t; i < 4096; i += 256) {
        int r = i >> 6, c = i & 63;
        s_a[r][c] = g_outtok[(size_t)bh * 4096 + i];
        s_b[r][c] = Wout[(size_t)(h * 64 + r) * DM + col0 + c];
    }
    __syncthreads();
    int tx = t & 15, ty = t >> 4;
    float acc[4][4] = {};
    for (int d = 0; d < 64; d++) {
        float av[4], bv[4];
#pragma unroll
        for (int i = 0; i < 4; i++) av[i] = s_a[ty * 4 + i][d];
#pragma unroll
        for (int j = 0; j < 4; j++) bv[j] = s_b[d][tx * 4 + j];
#pragma unroll
        for (int i = 0; i < 4; i++)
#pragma unroll
            for (int j = 0; j < 4; j++) acc[i][j] = fmaf(av[i], bv[j], acc[i][j]);
    }
    float* dst = g_P + (size_t)b * DM * DM;
#pragma unroll
    for (int i = 0; i < 4; i++)
#pragma unroll
        for (int j = 0; j < 4; j++)
            dst[(size_t)(h * 64 + ty * 4 + i) * DM + col0 + tx * 4 + j] = acc[i][j];
}

// out[n, :] = w[n, :] @ P[batch(n)]   (gathered rows per batch)
// Double-buffered + register-prefetch mainloop (same scheme as k_gemm_x).
__global__ void k_final(float* __restrict__ out) {
    int b = blockIdx.z;
    int cnt = g_rowcnt[b];
    int r0 = blockIdx.y * 64;
    if (r0 >= cnt) return;
    int nr = cnt - r0; if (nr > 64) nr = 64;
    int start = g_rowstart[b];
    __shared__ int rid[64];
    __shared__ float As[2][16][64];
    __shared__ float Bs[2][16][64];
    int t = threadIdx.x;
    if (t < 64) {
        int ii = t < nr ? t : nr - 1;
        rid[t] = g_rowlist[start + r0 + ii];
    }
    __syncthreads();
    int tx = t & 15, ty = t >> 4;
    int col0 = blockIdx.x * 64;
    int ar = t >> 2;
    int akq = (t & 3) * 4;
    int bk = t >> 4;
    int bcq = (t & 15) * 4;
    const float* P = g_P + (size_t)b * DM * DM;
    const float* aptr = g_w + (size_t)rid[ar] * DM + akq;
    const float* bptr = P + (size_t)bk * DM + col0 + bcq;
    float acc[4][4] = {};
    float4 a4 = *(const float4*)(aptr);
    float4 b4 = *(const float4*)(bptr);
    As[0][akq + 0][ar] = a4.x; As[0][akq + 1][ar] = a4.y;
    As[0][akq + 2][ar] = a4.z; As[0][akq + 3][ar] = a4.w;
    *(float4*)&Bs[0][bk][bcq] = b4;
    __syncthreads();
#pragma unroll 1
    for (int it = 0; it < DM / 16; it++) {
        int buf = it & 1;
        if (it + 1 < DM / 16) {
            a4 = *(const float4*)(aptr + (it + 1) * 16);
            b4 = *(const float4*)(bptr + (size_t)(it + 1) * 16 * DM);
        }
#pragma unroll
        for (int kk = 0; kk < 16; kk++) {
            float4 av4 = *(const float4*)&As[buf][kk][ty * 4];
            float4 bv4 = *(const float4*)&Bs[buf][kk][tx * 4];
            float av[4] = {av4.x, av4.y, av4.z, av4.w};
            float bv[4] = {bv4.x, bv4.y, bv4.z, bv4.w};
#pragma unroll
            for (int i = 0; i < 4; i++)
#pragma unroll
                for (int j = 0; j < 4; j++) acc[i][j] = fmaf(av[i], bv[j], acc[i][j]);
        }
        if (it + 1 < DM / 16) {
            int nb = buf ^ 1;
            As[nb][akq + 0][ar] = a4.x; As[nb][akq + 1][ar] = a4.y;
            As[nb][akq + 2][ar] = a4.z; As[nb][akq + 3][ar] = a4.w;
            *(float4*)&Bs[nb][bk][bcq] = b4;
        }
        __syncthreads();
    }
#pragma unroll
    for (int i = 0; i < 4; i++) {
        int rl = ty * 4 + i;
        if (rl < nr) {
            size_t r = rid[rl];
            float4 o; o.x = acc[i][0]; o.y = acc[i][1]; o.z = acc[i][2]; o.w = acc[i][3];
            *(float4*)&out[r * DM + col0 + tx * 4] = o;
        }
    }
}

extern "C" void kernel_launch(void* const* d_in, const int* in_sizes, int n_in,
                              void* d_out, int out_size) {
    const float* x    = (const float*)d_in[0];
    const int*   bi   = (const int*)d_in[1];
    const float* son  = (const float*)d_in[2];
    const int*   sbi  = (const int*)d_in[3];
    const float* temp = (const float*)d_in[4];
    const float* Wfx  = (const float*)d_in[5];
    const float* bfx  = (const float*)d_in[6];
    const float* Wx   = (const float*)d_in[7];
    const float* bx   = (const float*)d_in[8];
    const float* Wsl  = (const float*)d_in[9];
    const float* bsl  = (const float*)d_in[10];
    const float* Wq   = (const float*)d_in[11];
    const float* bq   = (const float*)d_in[12];
    const float* Wk   = (const float*)d_in[13];
    const float* bk   = (const float*)d_in[14];
    const float* Wv   = (const float*)d_in[15];
    const float* bv   = (const float*)d_in[16];
    const float* Wck  = (const float*)d_in[17];
    const float* bck  = (const float*)d_in[18];
    const float* Wcv  = (const float*)d_in[19];
    const float* bcv  = (const float*)d_in[20];
    const float* Wout = (const float*)d_in[21];
    float* out = (float*)d_out;

    // k_gemm_x moved to launch index 3 so the ncu capture window lands on it.
    k_zero<<<1024, 256>>>();
    k_wcomb<<<512, 256>>>(Wx, Wsl);
    k_bcomb<<<1, 512>>>(bx, Wsl, bsl);
    k_gemm_x<<<dim3(16, 256), 256>>>(x, Wfx, bfx);
    k_count<<<80, 256>>>(bi, sbi);
    k_prefix<<<1, 1>>>();
    k_scatter<<<80, 256>>>(bi, sbi);
    k_softmax<<<NT, 256>>>(temp);
    k_tokens<<<dim3(64, 16), 256>>>();
    k_qkv<<<dim3(64, 3), 256>>>(Wq, bq, Wk, bk, Wv, bv);
    k_attn<<<64, 256>>>();
    k_skv<<<dim3(512, 2), 256>>>(son, Wck, bck, Wcv, bcv);
    k_cross<<<64, 256>>>();
    k_P<<<dim3(64, 8), 256>>>(Wout);
    k_final<<<dim3(8, 256, 8), 256>>>(out);
}

// round 5
// speedup vs baseline: 1.4578x; 1.1847x over previous
#include <cuda_runtime.h>

#define NT 16384   // x rows
#define MS 4096    // sonata rows
#define NB 8       // batches
#define NH 8       // heads
#define DH 64      // head dim
#define NG 64      // slice groups
#define DM 512     // model dim
#define SCL 0.125f // D^-0.5

// ---------------- device scratch ----------------
__device__ float g_Wcomb[DM * DM];
__device__ float g_bcomb[DM];
__device__ float g_fx[(size_t)NT * DM];
__device__ float g_w[(size_t)NT * DM];        // logits, then softmax weights
__device__ float g_tokens[NB * NH * NG * DH];
__device__ float g_norms[NB * NH * NG];
__device__ float g_qkv[3 * NB * NH * NG * DH];
__device__ float g_outtok[NB * NH * NG * DH];
__device__ float g_ks[(size_t)MS * DM];
__device__ float g_vs[(size_t)MS * DM];
__device__ float g_scores[(size_t)NB * NH * NG * MS];  // 64 MB
__device__ float g_P[(size_t)NB * DM * DM];
__device__ int g_rowlist[NT], g_rowcnt[NB], g_rowstart[NB + 1], g_rowcur[NB];
__device__ int g_mlist[MS], g_mcnt[NB], g_mstart[NB + 1], g_mcur[NB];

// ---------------- setup kernels ----------------
__global__ void k_zero() {
    int i = blockIdx.x * 256 + threadIdx.x;
    if (i < NB * NH * NG * DH) g_tokens[i] = 0.f;
    if (i < NB * NH * NG) g_norms[i] = 0.f;
    if (i < NB) {
        g_rowcnt[i] = 0; g_mcnt[i] = 0;
        g_rowcur[i] = 0; g_mcur[i] = 0;
    }
}

// W_comb[c, h*64+g] = sum_d W_x[c, h*64+d] * W_slice[d, g]
__global__ void k_wcomb(const float* __restrict__ Wx, const float* __restrict__ Wsl) {
    __shared__ float s_sl[64 * 64];
    int t = threadIdx.x;
    for (int i = t; i < 4096; i += 256) s_sl[i] = Wsl[i];
    __syncthreads();
    int c = blockIdx.x;
    for (int o = t; o < 512; o += 256) {
        int h = o >> 6, g = o & 63;
        const float* wxr = Wx + (size_t)c * DM + h * 64;
        float acc = 0.f;
        for (int d = 0; d < 64; d++) acc = fmaf(wxr[d], s_sl[d * 64 + g], acc);
        g_Wcomb[(size_t)c * DM + o] = acc;
    }
}

__global__ void k_bcomb(const float* __restrict__ bx, const float* __restrict__ Wsl,
                        const float* __restrict__ bsl) {
    int o = threadIdx.x;  // 512
    int h = o >> 6, g = o & 63;
    float acc = bsl[g];
    for (int d = 0; d < 64; d++) acc = fmaf(bx[h * 64 + d], Wsl[d * 64 + g], acc);
    g_bcomb[o] = acc;
}

__global__ void k_count(const int* __restrict__ bi, const int* __restrict__ sbi) {
    int i = blockIdx.x * 256 + threadIdx.x;
    if (i < NT) atomicAdd(&g_rowcnt[bi[i]], 1);
    else if (i < NT + MS) atomicAdd(&g_mcnt[sbi[i - NT]], 1);
}

__global__ void k_prefix() {
    if (threadIdx.x == 0) {
        int s = 0;
        for (int b = 0; b < NB; b++) { g_rowstart[b] = s; s += g_rowcnt[b]; }
        g_rowstart[NB] = s;
        s = 0;
        for (int b = 0; b < NB; b++) { g_mstart[b] = s; s += g_mcnt[b]; }
        g_mstart[NB] = s;
    }
}

__global__ void k_scatter(const int* __restrict__ bi, const int* __restrict__ sbi) {
    int i = blockIdx.x * 256 + threadIdx.x;
    if (i < NT) {
        int b = bi[i];
        int p = atomicAdd(&g_rowcur[b], 1);
        g_rowlist[g_rowstart[b] + p] = i;
    } else if (i < NT + MS) {
        int j = i - NT;
        int b = sbi[j];
        int p = atomicAdd(&g_mcur[b], 1);
        g_mlist[g_mstart[b] + p] = j;
    }
}

// ---------------- front GEMM: [16384x512] @ [512x1024] -> fx | logits ----------------
// 128x128 tile, 8x8 microtile (split 4+4 fragments), K-slab 8, double buffered.
// 1 byte of LDS per FMA -> L1 no longer the binding resource.
__global__ void __launch_bounds__(256, 2)
k_gemm_x(const float* __restrict__ x, const float* __restrict__ Wfx,
         const float* __restrict__ bfx) {
    __shared__ float As[2][8][128];
    __shared__ float Bs[2][8][128];
    int t = threadIdx.x;
    int tx = t & 15, ty = t >> 4;
    int row0 = blockIdx.y * 128;
    int col0 = blockIdx.x * 128;
    bool is_fx = (col0 < DM);
    const float* Bbase = is_fx ? (Wfx + col0) : (g_Wcomb + (col0 - DM));
    int arow = t >> 1, akq = (t & 1) * 4;   // A: row 0..127, k-quad 0|4
    int bkr = t >> 5, bcol = (t & 31) * 4;  // B: k 0..7, col-quad
    const float* aptr = x + (size_t)(row0 + arow) * DM + akq;
    const float* bptr = Bbase + (size_t)bkr * DM + bcol;
    float acc[8][8] = {};
    float4 a4 = *(const float4*)aptr;
    float4 b4 = *(const float4*)bptr;
    As[0][akq + 0][arow] = a4.x; As[0][akq + 1][arow] = a4.y;
    As[0][akq + 2][arow] = a4.z; As[0][akq + 3][arow] = a4.w;
    *(float4*)&Bs[0][bkr][bcol] = b4;
    __syncthreads();
#pragma unroll 1
    for (int it = 0; it < DM / 8; it++) {
        int buf = it & 1;
        if (it + 1 < DM / 8) {
            a4 = *(const float4*)(aptr + (it + 1) * 8);
            b4 = *(const float4*)(bptr + (size_t)(it + 1) * 8 * DM);
        }
#pragma unroll
        for (int kk = 0; kk < 8; kk++) {
            float a[8], b[8];
            *(float4*)&a[0] = *(const float4*)&As[buf][kk][ty * 4];
            *(float4*)&a[4] = *(const float4*)&As[buf][kk][64 + ty * 4];
            *(float4*)&b[0] = *(const float4*)&Bs[buf][kk][tx * 4];
            *(float4*)&b[4] = *(const float4*)&Bs[buf][kk][64 + tx * 4];
#pragma unroll
            for (int i = 0; i < 8; i++)
#pragma unroll
                for (int j = 0; j < 8; j++) acc[i][j] = fmaf(a[i], b[j], acc[i][j]);
        }
        if (it + 1 < DM / 8) {
            int nb = buf ^ 1;
            As[nb][akq + 0][arow] = a4.x; As[nb][akq + 1][arow] = a4.y;
            As[nb][akq + 2][arow] = a4.z; As[nb][akq + 3][arow] = a4.w;
            *(float4*)&Bs[nb][bkr][bcol] = b4;
        }
        __syncthreads();
    }
#pragma unroll
    for (int i = 0; i < 8; i++) {
        int r = row0 + ((i < 4) ? ty * 4 + i : 64 + ty * 4 + i - 4);
#pragma unroll
        for (int half = 0; half < 2; half++) {
            int c = col0 + half * 64 + tx * 4;
            float4 o;
            o.x = acc[i][half * 4 + 0]; o.y = acc[i][half * 4 + 1];
            o.z = acc[i][half * 4 + 2]; o.w = acc[i][half * 4 + 3];
            if (is_fx) {
                o.x += bfx[c + 0]; o.y += bfx[c + 1]; o.z += bfx[c + 2]; o.w += bfx[c + 3];
                *(float4*)&g_fx[(size_t)r * DM + c] = o;
            } else {
                int cw = c - DM;
                o.x += g_bcomb[cw + 0]; o.y += g_bcomb[cw + 1];
                o.z += g_bcomb[cw + 2]; o.w += g_bcomb[cw + 3];
                *(float4*)&g_w[(size_t)r * DM + cw] = o;
            }
        }
    }
}

// per-(n,h) softmax over 64 slice logits, in place in g_w
__global__ void k_softmax(const float* __restrict__ temp) {
    int n = blockIdx.x;
    int wid = threadIdx.x >> 5, lane = threadIdx.x & 31;
    float* p = g_w + (size_t)n * DM + wid * 64;
    float it = 1.f / temp[wid];
    float v0 = p[lane] * it, v1 = p[lane + 32] * it;
    float m = fmaxf(v0, v1);
#pragma unroll
    for (int o = 16; o; o >>= 1) m = fmaxf(m, __shfl_xor_sync(0xFFFFFFFFu, m, o));
    float e0 = __expf(v0 - m), e1 = __expf(v1 - m);
    float s = e0 + e1;
#pragma unroll
    for (int o = 16; o; o >>= 1) s += __shfl_xor_sync(0xFFFFFFFFu, s, o);
    float inv = 1.f / s;
    p[lane] = e0 * inv;
    p[lane + 32] = e1 * inv;
}

// tokens[b,h,g,d] = sum_{n in b} w[n,h,g] * fx[n,h,d]; norms[b,h,g] = sum w
__global__ void k_tokens() {
    int bh = blockIdx.x;
    int b = bh >> 3, h = bh & 7;
    int cnt = g_rowcnt[b], start = g_rowstart[b];
    int c0 = (int)(((long long)cnt * blockIdx.y) >> 4);
    int c1 = (int)(((long long)cnt * (blockIdx.y + 1)) >> 4);
    int t = threadIdx.x;
    int tg = (t >> 4) * 4, td = (t & 15) * 4;
    float acc[4][4] = {};
    float nacc[4] = {};
    __shared__ float ws[8][64], fs[8][64];
    __shared__ int rid[8];
    for (int i0 = c0; i0 < c1; i0 += 8) {
        int nr = c1 - i0; if (nr > 8) nr = 8;
        if (t < nr) rid[t] = g_rowlist[start + i0 + t];
        __syncthreads();
        for (int idx = t; idx < nr * 64; idx += 256) {
            int r = idx >> 6, c = idx & 63;
            size_t off = (size_t)rid[r] * DM + h * 64 + c;
            ws[r][c] = g_w[off];
            fs[r][c] = g_fx[off];
        }
        __syncthreads();
        for (int r = 0; r < nr; r++) {
            float wv[4], fv[4];
#pragma unroll
            for (int i = 0; i < 4; i++) { wv[i] = ws[r][tg + i]; fv[i] = fs[r][td + i]; }
#pragma unroll
            for (int i = 0; i < 4; i++) {
                if (td == 0) nacc[i] += wv[i];
#pragma unroll
                for (int j = 0; j < 4; j++) acc[i][j] = fmaf(wv[i], fv[j], acc[i][j]);
            }
        }
        __syncthreads();
    }
    float* tok = g_tokens + (size_t)bh * NG * DH;
#pragma unroll
    for (int i = 0; i < 4; i++) {
#pragma unroll
        for (int j = 0; j < 4; j++) atomicAdd(&tok[(tg + i) * DH + td + j], acc[i][j]);
        if (td == 0) atomicAdd(&g_norms[bh * NG + tg + i], nacc[i]);
    }
}

// q/k/v = normalized tokens @ W + b  (per (b,h), 64x64x64)
__global__ void k_qkv(const float* __restrict__ Wq, const float* __restrict__ bq,
                      const float* __restrict__ Wk, const float* __restrict__ bk,
                      const float* __restrict__ Wv, const float* __restrict__ bv) {
    int bh = blockIdx.x, sel = blockIdx.y;
    const float* W = sel == 0 ? Wq : (sel == 1 ? Wk : Wv);
    const float* bias = sel == 0 ? bq : (sel == 1 ? bk : bv);
    __shared__ float s_a[64][65];
    __shared__ float s_b[64][64];
    int t = threadIdx.x;
    for (int i = t; i < 4096; i += 256) {
        int g = i >> 6, d = i & 63;
        s_a[g][d] = g_tokens[(size_t)bh * 4096 + i] / (g_norms[bh * 64 + g] + 1e-5f);
        s_b[g][d] = W[i];
    }
    __syncthreads();
    int tx = t & 15, ty = t >> 4;
    float acc[4][4] = {};
    for (int k = 0; k < 64; k++) {
        float av[4], bv2[4];
#pragma unroll
        for (int i = 0; i < 4; i++) av[i] = s_a[ty * 4 + i][k];
#pragma unroll
        for (int j = 0; j < 4; j++) bv2[j] = s_b[k][tx * 4 + j];
#pragma unroll
        for (int i = 0; i < 4; i++)
#pragma unroll
            for (int j = 0; j < 4; j++) acc[i][j] = fmaf(av[i], bv2[j], acc[i][j]);
    }
    float* dst = g_qkv + ((size_t)sel * 64 + bh) * 4096;
#pragma unroll
    for (int i = 0; i < 4; i++)
#pragma unroll
        for (int j = 0; j < 4; j++)
            dst[(ty * 4 + i) * 64 + tx * 4 + j] = acc[i][j] + bias[tx * 4 + j];
}

// per-(b,h) 64x64 attention: out_tok = softmax(q k^T * SCL) @ v
__global__ void k_attn() {
    int bh = blockIdx.x;
    __shared__ float s_x[64][64];  // q, then v
    __shared__ float s_k[64][64];
    __shared__ float s_s[64][64];
    int t = threadIdx.x;
    const float* q = g_qkv + (size_t)bh * 4096;
    const float* kk_ = g_qkv + (size_t)(64 + bh) * 4096;
    const float* vv = g_qkv + (size_t)(128 + bh) * 4096;
    for (int i = t; i < 4096; i += 256) { s_x[i >> 6][i & 63] = q[i]; s_k[i >> 6][i & 63] = kk_[i]; }
    __syncthreads();
    int tx = t & 15, ty = t >> 4;
    {
        float acc[4][4] = {};
        for (int d = 0; d < 64; d++) {
            float av[4], bv[4];
#pragma unroll
            for (int i = 0; i < 4; i++) av[i] = s_x[ty * 4 + i][d];
#pragma unroll
            for (int j = 0; j < 4; j++) bv[j] = s_k[tx * 4 + j][d];
#pragma unroll
            for (int i = 0; i < 4; i++)
#pragma unroll
                for (int j = 0; j < 4; j++) acc[i][j] = fmaf(av[i], bv[j], acc[i][j]);
        }
#pragma unroll
        for (int i = 0; i < 4; i++)
#pragma unroll
            for (int j = 0; j < 4; j++) s_s[ty * 4 + i][tx * 4 + j] = acc[i][j] * SCL;
    }
    __syncthreads();
    for (int i = t; i < 4096; i += 256) s_x[i >> 6][i & 63] = vv[i];  // v over q
    if (t < 64) {
        float m = -1e30f;
        for (int j = 0; j < 64; j++) m = fmaxf(m, s_s[t][j]);
        float s = 0.f;
        for (int j = 0; j < 64; j++) { float e = __expf(s_s[t][j] - m); s_s[t][j] = e; s += e; }
        float inv = 1.f / s;
        for (int j = 0; j < 64; j++) s_s[t][j] *= inv;
    }
    __syncthreads();
    float acc[4][4] = {};
    for (int k2 = 0; k2 < 64; k2++) {
        float av[4], bv[4];
#pragma unroll
        for (int i = 0; i < 4; i++) av[i] = s_s[ty * 4 + i][k2];
#pragma unroll
        for (int j = 0; j < 4; j++) bv[j] = s_x[k2][tx * 4 + j];
#pragma unroll
        for (int i = 0; i < 4; i++)
#pragma unroll
            for (int j = 0; j < 4; j++) acc[i][j] = fmaf(av[i], bv[j], acc[i][j]);
    }
#pragma unroll
    for (int i = 0; i < 4; i++)
#pragma unroll
        for (int j = 0; j < 4; j++)
            g_outtok[(size_t)bh * 4096 + (ty * 4 + i) * 64 + tx * 4 + j] = acc[i][j];
}

// sonata ks/vs projection: [32768x64] @ [64x64] + bias
__global__ void k_skv(const float* __restrict__ son,
                      const float* __restrict__ Wck, const float* __restrict__ bck,
                      const float* __restrict__ Wcv, const float* __restrict__ bcv) {
    int rt = blockIdx.x;
    int sel = blockIdx.y;
    const float* W = sel ? Wcv : Wck;
    const float* bias = sel ? bcv : bck;
    float* dst = sel ? g_vs : g_ks;
    __shared__ float s_at[64][65];
    __shared__ float s_b[64][64];
    int t = threadIdx.x;
    size_t base = (size_t)rt * 64 * 64;
    for (int i = t; i < 4096; i += 256) {
        s_at[i & 63][i >> 6] = son[base + i];
        s_b[i >> 6][i & 63] = W[i];
    }
    __syncthreads();
    int tx = t & 15, ty = t >> 4;
    float acc[4][4] = {};
    for (int k = 0; k < 64; k++) {
        float av[4], bv2[4];
#pragma unroll
        for (int i = 0; i < 4; i++) av[i] = s_at[k][ty * 4 + i];
#pragma unroll
        for (int j = 0; j < 4; j++) bv2[j] = s_b[k][tx * 4 + j];
#pragma unroll
        for (int i = 0; i < 4; i++)
#pragma unroll
            for (int j = 0; j < 4; j++) acc[i][j] = fmaf(av[i], bv2[j], acc[i][j]);
    }
#pragma unroll
    for (int i = 0; i < 4; i++)
#pragma unroll
        for (int j = 0; j < 4; j++)
            dst[base + (size_t)(ty * 4 + i) * 64 + tx * 4 + j] = acc[i][j] + bias[tx * 4 + j];
}

// per-(b,h): masked cross attention over sonata rows of batch b, out_tok += cw @ vs
__global__ void k_cross() {
    int bh = blockIdx.x, b = bh >> 3, h = bh & 7;
    int cnt = g_mcnt[b], start = g_mstart[b];
    if (cnt == 0) return;
    __shared__ float s_q[64][65];
    __shared__ float s_kv[32][64];
    __shared__ float s_cw[64][33];
    __shared__ float red[64][4];
    __shared__ int mid[32];
    int t = threadIdx.x;
    for (int i = t; i < 4096; i += 256) s_q[i >> 6][i & 63] = g_outtok[(size_t)bh * 4096 + i];
    __syncthreads();
    float* sc = g_scores + (size_t)bh * 64 * MS;
    // phase B: scores
    for (int j0 = 0; j0 < cnt; j0 += 32) {
        int nj = cnt - j0; if (nj > 32) nj = 32;
        if (t < nj) mid[t] = g_mlist[start + j0 + t];
        __syncthreads();
        for (int i = t; i < nj * 64; i += 256) {
            int r = i >> 6, c = i & 63;
            s_kv[r][c] = g_ks[(size_t)mid[r] * DM + h * 64 + c];
        }
        __syncthreads();
        int g = t & 63, jp = t >> 6;
        for (int j = jp; j < nj; j += 4) {
            float a = 0.f;
#pragma unroll 16
            for (int d = 0; d < 64; d++) a = fmaf(s_q[g][d], s_kv[j][d], a);
            sc[(size_t)g * MS + j0 + j] = a * SCL;
        }
        __syncthreads();
    }
    // phase C: row softmax over cnt entries
    {
        int g = t >> 2, part = t & 3;
        float m = -1e30f;
        for (int j = part; j < cnt; j += 4) m = fmaxf(m, sc[(size_t)g * MS + j]);
        red[g][part] = m;
        __syncthreads();
        m = fmaxf(fmaxf(red[g][0], red[g][1]), fmaxf(red[g][2], red[g][3]));
        float s = 0.f;
        for (int j = part; j < cnt; j += 4) s += __expf(sc[(size_t)g * MS + j] - m);
        __syncthreads();
        red[g][part] = s;
        __syncthreads();
        s = red[g][0] + red[g][1] + red[g][2] + red[g][3];
        float inv = 1.f / s;
        for (int j = part; j < cnt; j += 4)
            sc[(size_t)g * MS + j] = __expf(sc[(size_t)g * MS + j] - m) * inv;
    }
    __syncthreads();
    // phase D: out_tok += cw @ vs
    int tx = t & 15, ty = t >> 4;
    float acc[4][4] = {};
    for (int j0 = 0; j0 < cnt; j0 += 32) {
        int nj = cnt - j0; if (nj > 32) nj = 32;
        if (t < nj) mid[t] = g_mlist[start + j0 + t];
        __syncthreads();
        for (int i = t; i < nj * 64; i += 256) {
            int r = i >> 6, c = i & 63;
            s_kv[r][c] = g_vs[(size_t)mid[r] * DM + h * 64 + c];
        }
        for (int i = t; i < 64 * 32; i += 256) {
            int g = i >> 5, j = i & 31;
            s_cw[g][j] = (j < nj) ? sc[(size_t)g * MS + j0 + j] : 0.f;
        }
        __syncthreads();
        for (int j = 0; j < nj; j++) {
            float vvv[4];
#pragma unroll
            for (int jj = 0; jj < 4; jj++) vvv[jj] = s_kv[j][tx * 4 + jj];
#pragma unroll
            for (int i = 0; i < 4; i++) {
                float c = s_cw[ty * 4 + i][j];
#pragma unroll
                for (int jj = 0; jj < 4; jj++) acc[i][jj] = fmaf(c, vvv[jj], acc[i][jj]);
            }
        }
        __syncthreads();
    }
#pragma unroll
    for (int i = 0; i < 4; i++)
#pragma unroll
        for (int jj = 0; jj < 4; jj++) {
            size_t o = (size_t)bh * 4096 + (ty * 4 + i) * 64 + tx * 4 + jj;
            g_outtok[o] += acc[i][jj];
        }
}

// P[b, h*64+g, c] = sum_d out_tok[b,h,g,d] * W_out[h*64+d, c]
__global__ void k_P(const float* __restrict__ Wout) {
    int bh = blockIdx.x, b = bh >> 3, h = bh & 7;
    int col0 = blockIdx.y * 64;
    __shared__ float s_a[64][65];
    __shared__ float s_b[64][64];
    int t = threadIdx.x;
    for (int i = t; i < 4096; i += 256) {
        int r = i >> 6, c = i & 63;
        s_a[r][c] = g_outtok[(size_t)bh * 4096 + i];
        s_b[r][c] = Wout[(size_t)(h * 64 + r) * DM + col0 + c];
    }
    __syncthreads();
    int tx = t & 15, ty = t >> 4;
    float acc[4][4] = {};
    for (int d = 0; d < 64; d++) {
        float av[4], bv[4];
#pragma unroll
        for (int i = 0; i < 4; i++) av[i] = s_a[ty * 4 + i][d];
#pragma unroll
        for (int j = 0; j < 4; j++) bv[j] = s_b[d][tx * 4 + j];
#pragma unroll
        for (int i = 0; i < 4; i++)
#pragma unroll
            for (int j = 0; j < 4; j++) acc[i][j] = fmaf(av[i], bv[j], acc[i][j]);
    }
    float* dst = g_P + (size_t)b * DM * DM;
#pragma unroll
    for (int i = 0; i < 4; i++)
#pragma unroll
        for (int j = 0; j < 4; j++)
            dst[(size_t)(h * 64 + ty * 4 + i) * DM + col0 + tx * 4 + j] = acc[i][j];
}

// out[n, :] = w[n, :] @ P[batch(n)]   (gathered rows per batch)
// 128x128 tile, 8x8 microtile, same scheme as k_gemm_x.
__global__ void __launch_bounds__(256, 2)
k_final(float* __restrict__ out) {
    int b = blockIdx.z;
    int cnt = g_rowcnt[b];
    int r0 = blockIdx.y * 128;
    if (r0 >= cnt) return;
    int nr = cnt - r0; if (nr > 128) nr = 128;
    int start = g_rowstart[b];
    __shared__ int rid[128];
    __shared__ float As[2][8][128];
    __shared__ float Bs[2][8][128];
    int t = threadIdx.x;
    if (t < 128) {
        int ii = t < nr ? t : nr - 1;
        rid[t] = g_rowlist[start + r0 + ii];
    }
    __syncthreads();
    int tx = t & 15, ty = t >> 4;
    int col0 = blockIdx.x * 128;
    int arow = t >> 1, akq = (t & 1) * 4;
    int bkr = t >> 5, bcol = (t & 31) * 4;
    const float* P = g_P + (size_t)b * DM * DM;
    const float* aptr = g_w + (size_t)rid[arow] * DM + akq;
    const float* bptr = P + (size_t)bkr * DM + col0 + bcol;
    float acc[8][8] = {};
    float4 a4 = *(const float4*)aptr;
    float4 b4 = *(const float4*)bptr;
    As[0][akq + 0][arow] = a4.x; As[0][akq + 1][arow] = a4.y;
    As[0][akq + 2][arow] = a4.z; As[0][akq + 3][arow] = a4.w;
    *(float4*)&Bs[0][bkr][bcol] = b4;
    __syncthreads();
#pragma unroll 1
    for (int it = 0; it < DM / 8; it++) {
        int buf = it & 1;
        if (it + 1 < DM / 8) {
            a4 = *(const float4*)(aptr + (it + 1) * 8);
            b4 = *(const float4*)(bptr + (size_t)(it + 1) * 8 * DM);
        }
#pragma unroll
        for (int kk = 0; kk < 8; kk++) {
            float a[8], bb[8];
            *(float4*)&a[0] = *(const float4*)&As[buf][kk][ty * 4];
            *(float4*)&a[4] = *(const float4*)&As[buf][kk][64 + ty * 4];
            *(float4*)&bb[0] = *(const float4*)&Bs[buf][kk][tx * 4];
            *(float4*)&bb[4] = *(const float4*)&Bs[buf][kk][64 + tx * 4];
#pragma unroll
            for (int i = 0; i < 8; i++)
#pragma unroll
                for (int j = 0; j < 8; j++) acc[i][j] = fmaf(a[i], bb[j], acc[i][j]);
        }
        if (it + 1 < DM / 8) {
            int nb = buf ^ 1;
            As[nb][akq + 0][arow] = a4.x; As[nb][akq + 1][arow] = a4.y;
            As[nb][akq + 2][arow] = a4.z; As[nb][akq + 3][arow] = a4.w;
            *(float4*)&Bs[nb][bkr][bcol] = b4;
        }
        __syncthreads();
    }
#pragma unroll
    for (int i = 0; i < 8; i++) {
        int rl = (i < 4) ? ty * 4 + i : 64 + ty * 4 + i - 4;
        if (rl < nr) {
            size_t r = rid[rl];
#pragma unroll
            for (int half = 0; half < 2; half++) {
                int c = col0 + half * 64 + tx * 4;
                float4 o;
                o.x = acc[i][half * 4 + 0]; o.y = acc[i][half * 4 + 1];
                o.z = acc[i][half * 4 + 2]; o.w = acc[i][half * 4 + 3];
                *(float4*)&out[r * DM + c] = o;
            }
        }
    }
}

extern "C" void kernel_launch(void* const* d_in, const int* in_sizes, int n_in,
                              void* d_out, int out_size) {
    const float* x    = (const float*)d_in[0];
    const int*   bi   = (const int*)d_in[1];
    const float* son  = (const float*)d_in[2];
    const int*   sbi  = (const int*)d_in[3];
    const float* temp = (const float*)d_in[4];
    const float* Wfx  = (const float*)d_in[5];
    const float* bfx  = (const float*)d_in[6];
    const float* Wx   = (const float*)d_in[7];
    const float* bx   = (const float*)d_in[8];
    const float* Wsl  = (const float*)d_in[9];
    const float* bsl  = (const float*)d_in[10];
    const float* Wq   = (const float*)d_in[11];
    const float* bq   = (const float*)d_in[12];
    const float* Wk   = (const float*)d_in[13];
    const float* bk   = (const float*)d_in[14];
    const float* Wv   = (const float*)d_in[15];
    const float* bv   = (const float*)d_in[16];
    const float* Wck  = (const float*)d_in[17];
    const float* bck  = (const float*)d_in[18];
    const float* Wcv  = (const float*)d_in[19];
    const float* bcv  = (const float*)d_in[20];
    const float* Wout = (const float*)d_in[21];
    float* out = (float*)d_out;

    // k_gemm_x at launch index 3 so the ncu capture window lands on it.
    k_zero<<<1024, 256>>>();
    k_wcomb<<<512, 256>>>(Wx, Wsl);
    k_bcomb<<<1, 512>>>(bx, Wsl, bsl);
    k_gemm_x<<<dim3(8, 128), 256>>>(x, Wfx, bfx);
    k_count<<<80, 256>>>(bi, sbi);
    k_prefix<<<1, 1>>>();
    k_scatter<<<80, 256>>>(bi, sbi);
    k_softmax<<<NT, 256>>>(temp);
    k_tokens<<<dim3(64, 16), 256>>>();
    k_qkv<<<dim3(64, 3), 256>>>(Wq, bq, Wk, bk, Wv, bv);
    k_attn<<<64, 256>>>();
    k_skv<<<dim3(512, 2), 256>>>(son, Wck, bck, Wcv, bcv);
    k_cross<<<64, 256>>>();
    k_P<<<dim3(64, 8), 256>>>(Wout);
    k_final<<<dim3(4, 128, 8), 256>>>(out);
}

// round 7
// speedup vs baseline: 2.0256x; 1.3894x over previous
#include <cuda_runtime.h>
#include <cuda_bf16.h>
#include <cstdint>

#define NT 16384   // x rows
#define MS 4096    // sonata rows
#define NB 8       // batches
#define NH 8       // heads
#define DH 64      // head dim
#define NG 64      // slice groups
#define DM 512     // model dim
#define SCL 0.125f // D^-0.5

#define SMEM_SWIZZLE_128B(byte_offset) \
    ((byte_offset) ^ (((byte_offset) >> 3) & 0x70))

__device__ __forceinline__ uint32_t smem_to_u32(const void* p) {
    uint32_t a;
    asm("{ .reg .u64 tmp; cvta.to.shared.u64 tmp, %1; cvt.u32.u64 %0, tmp; }"
        : "=r"(a) : "l"(p));
    return a;
}
__device__ __forceinline__ void ldsm4(uint32_t a[4], uint32_t addr) {
    asm volatile("ldmatrix.sync.aligned.m8n8.x4.shared.b16 {%0,%1,%2,%3}, [%4];"
                 : "=r"(a[0]), "=r"(a[1]), "=r"(a[2]), "=r"(a[3]) : "r"(addr));
}
__device__ __forceinline__ void mma16816(float c[4], const uint32_t a[4],
                                         uint32_t b0, uint32_t b1) {
    asm volatile(
        "mma.sync.aligned.m16n8k16.row.col.f32.bf16.bf16.f32 "
        "{%0,%1,%2,%3}, {%4,%5,%6,%7}, {%8,%9}, {%0,%1,%2,%3};"
        : "+f"(c[0]), "+f"(c[1]), "+f"(c[2]), "+f"(c[3])
        : "r"(a[0]), "r"(a[1]), "r"(a[2]), "r"(a[3]), "r"(b0), "r"(b1));
}
__device__ __forceinline__ void bsplit(float v, __nv_bfloat16& h, __nv_bfloat16& l) {
    h = __float2bfloat16(v);
    l = __float2bfloat16(v - __bfloat162float(h));
}

// dynamic smem layout for MMA kernels: AH 16K | AL 16K | BH 16K | BL 16K
#define OFF_AH 0
#define OFF_AL 16384
#define OFF_BH 32768
#define OFF_BL 49152
#define SMEM_MMA 65536
#define KSLAB 64

// ---------------- device scratch ----------------
__device__ float g_bcomb[DM];
__device__ float g_fx[(size_t)NT * DM];
__device__ float g_w[(size_t)NT * DM];
__device__ __nv_bfloat16 g_xhi[(size_t)NT * DM], g_xlo[(size_t)NT * DM];
__device__ __nv_bfloat16 g_Bthi[(size_t)2 * DM * DM], g_Btlo[(size_t)2 * DM * DM]; // [1024][512]
__device__ __nv_bfloat16 g_whi[(size_t)NT * DM], g_wlo[(size_t)NT * DM];
__device__ __nv_bfloat16 g_Pthi[(size_t)NB * DM * DM], g_Ptlo[(size_t)NB * DM * DM]; // [b][c][k]
__device__ float g_tokens[NB * NH * NG * DH];
__device__ float g_norms[NB * NH * NG];
__device__ float g_qkv[3 * NB * NH * NG * DH];
__device__ float g_outtok[NB * NH * NG * DH];
__device__ float g_ks[(size_t)MS * DM];
__device__ float g_vs[(size_t)MS * DM];
__device__ float g_scores[(size_t)NB * NH * NG * MS];
__device__ int g_rowlist[NT], g_rowcnt[NB], g_rowstart[NB + 1], g_rowcur[NB];
__device__ int g_mlist[MS], g_mcnt[NB], g_mstart[NB + 1], g_mcur[NB];

// ---------------- setup kernels ----------------
__global__ void k_zero() {
    int i = blockIdx.x * 256 + threadIdx.x;
    if (i < NB * NH * NG * DH) g_tokens[i] = 0.f;
    if (i < NB * NH * NG) g_norms[i] = 0.f;
    if (i < NB) {
        g_rowcnt[i] = 0; g_mcnt[i] = 0;
        g_rowcur[i] = 0; g_mcur[i] = 0;
    }
}

__global__ void k_bcomb(const float* __restrict__ bx, const float* __restrict__ Wsl,
                        const float* __restrict__ bsl) {
    int o = threadIdx.x;  // 512
    int h = o >> 6, g = o & 63;
    float acc = bsl[g];
    for (int d = 0; d < 64; d++) acc = fmaf(bx[h * 64 + d], Wsl[d * 64 + g], acc);
    g_bcomb[o] = acc;
}

// x fp32 -> bf16 hi/lo split
__global__ void k_cvt_x(const float* __restrict__ x) {
    size_t i = (size_t)blockIdx.x * 256 + threadIdx.x;  // one float4 each
    float4 v = ((const float4*)x)[i];
    __nv_bfloat16 h0, h1, h2, h3, l0, l1, l2, l3;
    bsplit(v.x, h0, l0); bsplit(v.y, h1, l1);
    bsplit(v.z, h2, l2); bsplit(v.w, h3, l3);
    ((__nv_bfloat162*)g_xhi)[i * 2 + 0] = __halves2bfloat162(h0, h1);
    ((__nv_bfloat162*)g_xhi)[i * 2 + 1] = __halves2bfloat162(h2, h3);
    ((__nv_bfloat162*)g_xlo)[i * 2 + 0] = __halves2bfloat162(l0, l1);
    ((__nv_bfloat162*)g_xlo)[i * 2 + 1] = __halves2bfloat162(l2, l3);
}

// y==1: Bt rows 0..511 (transposed Wfx); y==0: Bt rows 512..1023 from Wcomb = Wx·Wsl
__global__ void k_wcomb(const float* __restrict__ Wx, const float* __restrict__ Wsl,
                        const float* __restrict__ Wfx) {
    int c = blockIdx.x;  // 0..511
    int t = threadIdx.x;
    if (blockIdx.y == 1) {
        for (int k = t; k < DM; k += 256) {
            __nv_bfloat16 h, l;
            bsplit(Wfx[(size_t)k * DM + c], h, l);
            g_Bthi[(size_t)c * DM + k] = h;
            g_Btlo[(size_t)c * DM + k] = l;
        }
        return;
    }
    __shared__ float s_sl[4096];
    for (int i = t; i < 4096; i += 256) s_sl[i] = Wsl[i];
    __syncthreads();
    for (int o = t; o < 512; o += 256) {
        int h = o >> 6, g = o & 63;
        const float* wxr = Wx + (size_t)c * DM + h * 64;
        float acc = 0.f;
        for (int d = 0; d < 64; d++) acc = fmaf(wxr[d], s_sl[d * 64 + g], acc);
        __nv_bfloat16 hh, ll;
        bsplit(acc, hh, ll);
        g_Bthi[(size_t)(DM + o) * DM + c] = hh;
        g_Btlo[(size_t)(DM + o) * DM + c] = ll;
    }
}

__global__ void k_count(const int* __restrict__ bi, const int* __restrict__ sbi) {
    int i = blockIdx.x * 256 + threadIdx.x;
    if (i < NT) atomicAdd(&g_rowcnt[bi[i]], 1);
    else if (i < NT + MS) atomicAdd(&g_mcnt[sbi[i - NT]], 1);
}

__global__ void k_prefix() {
    if (threadIdx.x == 0) {
        int s = 0;
        for (int b = 0; b < NB; b++) { g_rowstart[b] = s; s += g_rowcnt[b]; }
        g_rowstart[NB] = s;
        s = 0;
        for (int b = 0; b < NB; b++) { g_mstart[b] = s; s += g_mcnt[b]; }
        g_mstart[NB] = s;
    }
}

__global__ void k_scatter(const int* __restrict__ bi, const int* __restrict__ sbi) {
    int i = blockIdx.x * 256 + threadIdx.x;
    if (i < NT) {
        int b = bi[i];
        int p = atomicAdd(&g_rowcur[b], 1);
        g_rowlist[g_rowstart[b] + p] = i;
    } else if (i < NT + MS) {
        int j = i - NT;
        int b = sbi[j];
        int p = atomicAdd(&g_mcur[b], 1);
        g_mlist[g_mstart[b] + p] = j;
    }
}

// ---------------- front GEMM via mma.sync bf16x3 ----------------
// [16384x512] @ [512x1024] -> fx | w.  Tile 128x128, warp 32x64, K-slab 64.
__global__ void __launch_bounds__(256, 2)
k_gemm_mma(const float* __restrict__ bfx) {
    extern __shared__ char dynsmem[];
    uint32_t sb = smem_to_u32(dynsmem);
    int t = threadIdx.x;
    int lane = t & 31, wid = t >> 5;
    int wm = (wid & 3) * 32, wn = (wid >> 2) * 64;
    int row0 = blockIdx.y * 128, col0 = blockIdx.x * 128;
    float acc[2][8][4] = {};
    // ldmatrix per-lane byte offsets (tile-relative, k offset added per step)
    uint32_t a_row = wm + (lane & 15);
    uint32_t a_k8 = (lane >> 4) * 8;
    uint32_t b_row = wn + (lane & 7) + ((lane >> 4) << 3);
    uint32_t b_k8 = ((lane >> 3) & 1) * 8;
#pragma unroll 1
    for (int ch = 0; ch < DM / KSLAB; ch++) {
        int kc = ch * KSLAB;
        __syncthreads();
        for (int i = t; i < 1024; i += 256) {
            int r = i >> 3, k8 = i & 7;
            uint32_t sw = SMEM_SWIZZLE_128B((uint32_t)(r * 128 + k8 * 16));
            *(uint4*)(dynsmem + OFF_AH + sw) = ((const uint4*)(g_xhi + (size_t)(row0 + r) * DM + kc))[k8];
            *(uint4*)(dynsmem + OFF_AL + sw) = ((const uint4*)(g_xlo + (size_t)(row0 + r) * DM + kc))[k8];
            *(uint4*)(dynsmem + OFF_BH + sw) = ((const uint4*)(g_Bthi + (size_t)(col0 + r) * DM + kc))[k8];
            *(uint4*)(dynsmem + OFF_BL + sw) = ((const uint4*)(g_Btlo + (size_t)(col0 + r) * DM + kc))[k8];
        }
        __syncthreads();
#pragma unroll
        for (int ks = 0; ks < KSLAB / 16; ks++) {
            uint32_t ah[2][4], al[2][4];
#pragma unroll
            for (int mt = 0; mt < 2; mt++) {
                uint32_t off = SMEM_SWIZZLE_128B((a_row + mt * 16) * 128 + (ks * 16 + a_k8) * 2);
                ldsm4(ah[mt], sb + OFF_AH + off);
                ldsm4(al[mt], sb + OFF_AL + off);
            }
#pragma unroll
            for (int np = 0; np < 4; np++) {
                uint32_t bh[4], bl[4];
                uint32_t boff = SMEM_SWIZZLE_128B((b_row + np * 16) * 128 + (ks * 16 + b_k8) * 2);
                ldsm4(bh, sb + OFF_BH + boff);
                ldsm4(bl, sb + OFF_BL + boff);
#pragma unroll
                for (int mt = 0; mt < 2; mt++) {
                    mma16816(acc[mt][np * 2 + 0], ah[mt], bh[0], bh[1]);
                    mma16816(acc[mt][np * 2 + 0], ah[mt], bl[0], bl[1]);
                    mma16816(acc[mt][np * 2 + 0], al[mt], bh[0], bh[1]);
                    mma16816(acc[mt][np * 2 + 1], ah[mt], bh[2], bh[3]);
                    mma16816(acc[mt][np * 2 + 1], ah[mt], bl[2], bl[3]);
                    mma16816(acc[mt][np * 2 + 1], al[mt], bh[2], bh[3]);
                }
            }
        }
    }
    int g = lane >> 2, tig = lane & 3;
    bool isfx = (col0 < DM);
    float* dstb = isfx ? g_fx : g_w;
    int cbase = (isfx ? col0 : col0 - DM);
    const float* bias = isfx ? bfx : g_bcomb;
#pragma unroll
    for (int mt = 0; mt < 2; mt++)
#pragma unroll
        for (int nt = 0; nt < 8; nt++) {
            int r1 = row0 + wm + mt * 16 + g;
            int c = cbase + wn + nt * 8 + tig * 2;
            float b0v = bias[c], b1v = bias[c + 1];
            float2 v0 = make_float2(acc[mt][nt][0] + b0v, acc[mt][nt][1] + b1v);
            float2 v1 = make_float2(acc[mt][nt][2] + b0v, acc[mt][nt][3] + b1v);
            *(float2*)(dstb + (size_t)r1 * DM + c) = v0;
            *(float2*)(dstb + (size_t)(r1 + 8) * DM + c) = v1;
        }
}

// per-(n,h) softmax over 64 slice logits; writes fp32 w and bf16 hi/lo split
__global__ void k_softmax(const float* __restrict__ temp) {
    int n = blockIdx.x;
    int wid = threadIdx.x >> 5, lane = threadIdx.x & 31;
    size_t off = (size_t)n * DM + wid * 64;
    float* p = g_w + off;
    float it = 1.f / temp[wid];
    float v0 = p[lane] * it, v1 = p[lane + 32] * it;
    float m = fmaxf(v0, v1);
#pragma unroll
    for (int o = 16; o; o >>= 1) m = fmaxf(m, __shfl_xor_sync(0xFFFFFFFFu, m, o));
    float e0 = __expf(v0 - m), e1 = __expf(v1 - m);
    float s = e0 + e1;
#pragma unroll
    for (int o = 16; o; o >>= 1) s += __shfl_xor_sync(0xFFFFFFFFu, s, o);
    float inv = 1.f / s;
    float w0 = e0 * inv, w1 = e1 * inv;
    p[lane] = w0;
    p[lane + 32] = w1;
    __nv_bfloat16 h, l;
    bsplit(w0, h, l); g_whi[off + lane] = h; g_wlo[off + lane] = l;
    bsplit(w1, h, l); g_whi[off + lane + 32] = h; g_wlo[off + lane + 32] = l;
}

// tokens[b,h,g,d] = sum_{n in b} w[n,h,g] * fx[n,h,d]; norms[b,h,g] = sum w
__global__ void k_tokens() {
    int bh = blockIdx.x;
    int b = bh >> 3, h = bh & 7;
    int cnt = g_rowcnt[b], start = g_rowstart[b];
    int c0 = (int)(((long long)cnt * blockIdx.y) >> 4);
    int c1 = (int)(((long long)cnt * (blockIdx.y + 1)) >> 4);
    int t = threadIdx.x;
    int tg = (t >> 4) * 4, td = (t & 15) * 4;
    float acc[4][4] = {};
    float nacc[4] = {};
    __shared__ float ws[8][64], fs[8][64];
    __shared__ int rid[8];
    for (int i0 = c0; i0 < c1; i0 += 8) {
        int nr = c1 - i0; if (nr > 8) nr = 8;
        if (t < nr) rid[t] = g_rowlist[start + i0 + t];
        __syncthreads();
        for (int idx = t; idx < nr * 64; idx += 256) {
            int r = idx >> 6, c = idx & 63;
            size_t off = (size_t)rid[r] * DM + h * 64 + c;
            ws[r][c] = g_w[off];
            fs[r][c] = g_fx[off];
        }
        __syncthreads();
        for (int r = 0; r < nr; r++) {
            float wv[4], fv[4];
#pragma unroll
            for (int i = 0; i < 4; i++) { wv[i] = ws[r][tg + i]; fv[i] = fs[r][td + i]; }
#pragma unroll
            for (int i = 0; i < 4; i++) {
                if (td == 0) nacc[i] += wv[i];
#pragma unroll
                for (int j = 0; j < 4; j++) acc[i][j] = fmaf(wv[i], fv[j], acc[i][j]);
            }
        }
        __syncthreads();
    }
    float* tok = g_tokens + (size_t)bh * NG * DH;
#pragma unroll
    for (int i = 0; i < 4; i++) {
#pragma unroll
        for (int j = 0; j < 4; j++) atomicAdd(&tok[(tg + i) * DH + td + j], acc[i][j]);
        if (td == 0) atomicAdd(&g_norms[bh * NG + tg + i], nacc[i]);
    }
}

// q/k/v = normalized tokens @ W + b  (per (b,h), 64x64x64)
__global__ void k_qkv(const float* __restrict__ Wq, const float* __restrict__ bq,
                      const float* __restrict__ Wk, const float* __restrict__ bk,
                      const float* __restrict__ Wv, const float* __restrict__ bv) {
    int bh = blockIdx.x, sel = blockIdx.y;
    const float* W = sel == 0 ? Wq : (sel == 1 ? Wk : Wv);
    const float* bias = sel == 0 ? bq : (sel == 1 ? bk : bv);
    __shared__ float s_a[64][65];
    __shared__ float s_b[64][64];
    int t = threadIdx.x;
    for (int i = t; i < 4096; i += 256) {
        int g = i >> 6, d = i & 63;
        s_a[g][d] = g_tokens[(size_t)bh * 4096 + i] / (g_norms[bh * 64 + g] + 1e-5f);
        s_b[g][d] = W[i];
    }
    __syncthreads();
    int tx = t & 15, ty = t >> 4;
    float acc[4][4] = {};
    for (int k = 0; k < 64; k++) {
        float av[4], bv2[4];
#pragma unroll
        for (int i = 0; i < 4; i++) av[i] = s_a[ty * 4 + i][k];
#pragma unroll
        for (int j = 0; j < 4; j++) bv2[j] = s_b[k][tx * 4 + j];
#pragma unroll
        for (int i = 0; i < 4; i++)
#pragma unroll
            for (int j = 0; j < 4; j++) acc[i][j] = fmaf(av[i], bv2[j], acc[i][j]);
    }
    float* dst = g_qkv + ((size_t)sel * 64 + bh) * 4096;
#pragma unroll
    for (int i = 0; i < 4; i++)
#pragma unroll
        for (int j = 0; j < 4; j++)
            dst[(ty * 4 + i) * 64 + tx * 4 + j] = acc[i][j] + bias[tx * 4 + j];
}

// per-(b,h) 64x64 attention: out_tok = softmax(q k^T * SCL) @ v
__global__ void k_attn() {
    int bh = blockIdx.x;
    __shared__ float s_x[64][64];
    __shared__ float s_k[64][64];
    __shared__ float s_s[64][64];
    int t = threadIdx.x;
    const float* q = g_qkv + (size_t)bh * 4096;
    const float* kk_ = g_qkv + (size_t)(64 + bh) * 4096;
    const float* vv = g_qkv + (size_t)(128 + bh) * 4096;
    for (int i = t; i < 4096; i += 256) { s_x[i >> 6][i & 63] = q[i]; s_k[i >> 6][i & 63] = kk_[i]; }
    __syncthreads();
    int tx = t & 15, ty = t >> 4;
    {
        float acc[4][4] = {};
        for (int d = 0; d < 64; d++) {
            float av[4], bv[4];
#pragma unroll
            for (int i = 0; i < 4; i++) av[i] = s_x[ty * 4 + i][d];
#pragma unroll
            for (int j = 0; j < 4; j++) bv[j] = s_k[tx * 4 + j][d];
#pragma unroll
            for (int i = 0; i < 4; i++)
#pragma unroll
                for (int j = 0; j < 4; j++) acc[i][j] = fmaf(av[i], bv[j], acc[i][j]);
        }
#pragma unroll
        for (int i = 0; i < 4; i++)
#pragma unroll
            for (int j = 0; j < 4; j++) s_s[ty * 4 + i][tx * 4 + j] = acc[i][j] * SCL;
    }
    __syncthreads();
    for (int i = t; i < 4096; i += 256) s_x[i >> 6][i & 63] = vv[i];
    if (t < 64) {
        float m = -1e30f;
        for (int j = 0; j < 64; j++) m = fmaxf(m, s_s[t][j]);
        float s = 0.f;
        for (int j = 0; j < 64; j++) { float e = __expf(s_s[t][j] - m); s_s[t][j] = e; s += e; }
        float inv = 1.f / s;
        for (int j = 0; j < 64; j++) s_s[t][j] *= inv;
    }
    __syncthreads();
    float acc[4][4] = {};
    for (int k2 = 0; k2 < 64; k2++) {
        float av[4], bv[4];
#pragma unroll
        for (int i = 0; i < 4; i++) av[i] = s_s[ty * 4 + i][k2];
#pragma unroll
        for (int j = 0; j < 4; j++) bv[j] = s_x[k2][tx * 4 + j];
#pragma unroll
        for (int i = 0; i < 4; i++)
#pragma unroll
            for (int j = 0; j < 4; j++) acc[i][j] = fmaf(av[i], bv[j], acc[i][j]);
    }
#pragma unroll
    for (int i = 0; i < 4; i++)
#pragma unroll
        for (int j = 0; j < 4; j++)
            g_outtok[(size_t)bh * 4096 + (ty * 4 + i) * 64 + tx * 4 + j] = acc[i][j];
}

// sonata ks/vs projection: [32768x64] @ [64x64] + bias
__global__ void k_skv(const float* __restrict__ son,
                      const float* __restrict__ Wck, const float* __restrict__ bck,
                      const float* __restrict__ Wcv, const float* __restrict__ bcv) {
    int rt = blockIdx.x;
    int sel = blockIdx.y;
    const float* W = sel ? Wcv : Wck;
    const float* bias = sel ? bcv : bck;
    float* dst = sel ? g_vs : g_ks;
    __shared__ float s_at[64][65];
    __shared__ float s_b[64][64];
    int t = threadIdx.x;
    size_t base = (size_t)rt * 64 * 64;
    for (int i = t; i < 4096; i += 256) {
        s_at[i & 63][i >> 6] = son[base + i];
        s_b[i >> 6][i & 63] = W[i];
    }
    __syncthreads();
    int tx = t & 15, ty = t >> 4;
    float acc[4][4] = {};
    for (int k = 0; k < 64; k++) {
        float av[4], bv2[4];
#pragma unroll
        for (int i = 0; i < 4; i++) av[i] = s_at[k][ty * 4 + i];
#pragma unroll
        for (int j = 0; j < 4; j++) bv2[j] = s_b[k][tx * 4 + j];
#pragma unroll
        for (int i = 0; i < 4; i++)
#pragma unroll
            for (int j = 0; j < 4; j++) acc[i][j] = fmaf(av[i], bv2[j], acc[i][j]);
    }
#pragma unroll
    for (int i = 0; i < 4; i++)
#pragma unroll
        for (int j = 0; j < 4; j++)
            dst[base + (size_t)(ty * 4 + i) * 64 + tx * 4 + j] = acc[i][j] + bias[tx * 4 + j];
}

// per-(b,h): masked cross attention over sonata rows of batch b, out_tok += cw @ vs
__global__ void k_cross() {
    int bh = blockIdx.x, b = bh >> 3, h = bh & 7;
    int cnt = g_mcnt[b], start = g_mstart[b];
    if (cnt == 0) return;
    __shared__ float s_q[64][65];
    __shared__ float s_kv[32][64];
    __shared__ float s_cw[64][33];
    __shared__ float red[64][4];
    __shared__ int mid[32];
    int t = threadIdx.x;
    for (int i = t; i < 4096; i += 256) s_q[i >> 6][i & 63] = g_outtok[(size_t)bh * 4096 + i];
    __syncthreads();
    float* sc = g_scores + (size_t)bh * 64 * MS;
    for (int j0 = 0; j0 < cnt; j0 += 32) {
        int nj = cnt - j0; if (nj > 32) nj = 32;
        if (t < nj) mid[t] = g_mlist[start + j0 + t];
        __syncthreads();
        for (int i = t; i < nj * 64; i += 256) {
            int r = i >> 6, c = i & 63;
            s_kv[r][c] = g_ks[(size_t)mid[r] * DM + h * 64 + c];
        }
        __syncthreads();
        int g = t & 63, jp = t >> 6;
        for (int j = jp; j < nj; j += 4) {
            float a = 0.f;
#pragma unroll 16
            for (int d = 0; d < 64; d++) a = fmaf(s_q[g][d], s_kv[j][d], a);
            sc[(size_t)g * MS + j0 + j] = a * SCL;
        }
        __syncthreads();
    }
    {
        int g = t >> 2, part = t & 3;
        float m = -1e30f;
        for (int j = part; j < cnt; j += 4) m = fmaxf(m, sc[(size_t)g * MS + j]);
        red[g][part] = m;
        __syncthreads();
        m = fmaxf(fmaxf(red[g][0], red[g][1]), fmaxf(red[g][2], red[g][3]));
        float s = 0.f;
        for (int j = part; j < cnt; j += 4) s += __expf(sc[(size_t)g * MS + j] - m);
        __syncthreads();
        red[g][part] = s;
        __syncthreads();
        s = red[g][0] + red[g][1] + red[g][2] + red[g][3];
        float inv = 1.f / s;
        for (int j = part; j < cnt; j += 4)
            sc[(size_t)g * MS + j] = __expf(sc[(size_t)g * MS + j] - m) * inv;
    }
    __syncthreads();
    int tx = t & 15, ty = t >> 4;
    float acc[4][4] = {};
    for (int j0 = 0; j0 < cnt; j0 += 32) {
        int nj = cnt - j0; if (nj > 32) nj = 32;
        if (t < nj) mid[t] = g_mlist[start + j0 + t];
        __syncthreads();
        for (int i = t; i < nj * 64; i += 256) {
            int r = i >> 6, c = i & 63;
            s_kv[r][c] = g_vs[(size_t)mid[r] * DM + h * 64 + c];
        }
        for (int i = t; i < 64 * 32; i += 256) {
            int g = i >> 5, j = i & 31;
            s_cw[g][j] = (j < nj) ? sc[(size_t)g * MS + j0 + j] : 0.f;
        }
        __syncthreads();
        for (int j = 0; j < nj; j++) {
            float vvv[4];
#pragma unroll
            for (int jj = 0; jj < 4; jj++) vvv[jj] = s_kv[j][tx * 4 + jj];
#pragma unroll
            for (int i = 0; i < 4; i++) {
                float c = s_cw[ty * 4 + i][j];
#pragma unroll
                for (int jj = 0; jj < 4; jj++) acc[i][jj] = fmaf(c, vvv[jj], acc[i][jj]);
            }
        }
        __syncthreads();
    }
#pragma unroll
    for (int i = 0; i < 4; i++)
#pragma unroll
        for (int jj = 0; jj < 4; jj++) {
            size_t o = (size_t)bh * 4096 + (ty * 4 + i) * 64 + tx * 4 + jj;
            g_outtok[o] += acc[i][jj];
        }
}

// P[b, h*64+g, c] = sum_d out_tok[b,h,g,d] * W_out[h*64+d, c], stored transposed bf16 hi/lo
__global__ void k_P(const float* __restrict__ Wout) {
    int bh = blockIdx.x, b = bh >> 3, h = bh & 7;
    int col0 = blockIdx.y * 64;
    __shared__ float s_a[64][65];
    __shared__ float s_b[64][64];
    int t = threadIdx.x;
    for (int i = t; i < 4096; i += 256) {
        int r = i >> 6, c = i & 63;
        s_a[r][c] = g_outtok[(size_t)bh * 4096 + i];
        s_b[r][c] = Wout[(size_t)(h * 64 + r) * DM + col0 + c];
    }
    __syncthreads();
    int tx = t & 15, ty = t >> 4;
    float acc[4][4] = {};
    for (int d = 0; d < 64; d++) {
        float av[4], bv[4];
#pragma unroll
        for (int i = 0; i < 4; i++) av[i] = s_a[ty * 4 + i][d];
#pragma unroll
        for (int j = 0; j < 4; j++) bv[j] = s_b[d][tx * 4 + j];
#pragma unroll
        for (int i = 0; i < 4; i++)
#pragma unroll
            for (int j = 0; j < 4; j++) acc[i][j] = fmaf(av[i], bv[j], acc[i][j]);
    }
#pragma unroll
    for (int i = 0; i < 4; i++)
#pragma unroll
        for (int j = 0; j < 4; j++) {
            int r = h * 64 + ty * 4 + i;       // k index of P
            int c = col0 + tx * 4 + j;         // output col
            __nv_bfloat16 hh, ll;
            bsplit(acc[i][j], hh, ll);
            g_Pthi[((size_t)b * DM + c) * DM + r] = hh;
            g_Ptlo[((size_t)b * DM + c) * DM + r] = ll;
        }
}

// out[n, :] = w[n, :] @ P[batch(n)] via mma.sync bf16x3, gathered rows
__global__ void __launch_bounds__(256, 2)
k_final_mma(float* __restrict__ out) {
    int b = blockIdx.z;
    int cnt = g_rowcnt[b];
    int r0 = blockIdx.y * 128;
    if (r0 >= cnt) return;
    int nr = cnt - r0; if (nr > 128) nr = 128;
    extern __shared__ char dynsmem[];
    uint32_t sb = smem_to_u32(dynsmem);
    __shared__ int rid[128];
    int t = threadIdx.x;
    int lane = t & 31, wid = t >> 5;
    int wm = (wid & 3) * 32, wn = (wid >> 2) * 64;
    int col0 = blockIdx.x * 128;
    int start = g_rowstart[b];
    if (t < 128) rid[t] = g_rowlist[start + r0 + (t < nr ? t : nr - 1)];
    float acc[2][8][4] = {};
    uint32_t a_row = wm + (lane & 15);
    uint32_t a_k8 = (lane >> 4) * 8;
    uint32_t b_row = wn + (lane & 7) + ((lane >> 4) << 3);
    uint32_t b_k8 = ((lane >> 3) & 1) * 8;
    const __nv_bfloat16* Ph = g_Pthi + ((size_t)b * DM + col0) * DM;
    const __nv_bfloat16* Pl = g_Ptlo + ((size_t)b * DM + col0) * DM;
#pragma unroll 1
    for (int ch = 0; ch < DM / KSLAB; ch++) {
        int kc = ch * KSLAB;
        __syncthreads();
        for (int i = t; i < 1024; i += 256) {
            int r = i >> 3, k8 = i & 7;
            uint32_t sw = SMEM_SWIZZLE_128B((uint32_t)(r * 128 + k8 * 16));
            *(uint4*)(dynsmem + OFF_AH + sw) = ((const uint4*)(g_whi + (size_t)rid[r] * DM + kc))[k8];
            *(uint4*)(dynsmem + OFF_AL + sw) = ((const uint4*)(g_wlo + (size_t)rid[r] * DM + kc))[k8];
            *(uint4*)(dynsmem + OFF_BH + sw) = ((const uint4*)(Ph + (size_t)r * DM + kc))[k8];
            *(uint4*)(dynsmem + OFF_BL + sw) = ((const uint4*)(Pl + (size_t)r * DM + kc))[k8];
        }
        __syncthreads();
#pragma unroll
        for (int ks = 0; ks < KSLAB / 16; ks++) {
            uint32_t ah[2][4], al[2][4];
#pragma unroll
            for (int mt = 0; mt < 2; mt++) {
                uint32_t off = SMEM_SWIZZLE_128B((a_row + mt * 16) * 128 + (ks * 16 + a_k8) * 2);
                ldsm4(ah[mt], sb + OFF_AH + off);
                ldsm4(al[mt], sb + OFF_AL + off);
            }
#pragma unroll
            for (int np = 0; np < 4; np++) {
                uint32_t bh[4], bl[4];
                uint32_t boff = SMEM_SWIZZLE_128B((b_row + np * 16) * 128 + (ks * 16 + b_k8) * 2);
                ldsm4(bh, sb + OFF_BH + boff);
                ldsm4(bl, sb + OFF_BL + boff);
#pragma unroll
                for (int mt = 0; mt < 2; mt++) {
                    mma16816(acc[mt][np * 2 + 0], ah[mt], bh[0], bh[1]);
                    mma16816(acc[mt][np * 2 + 0], ah[mt], bl[0], bl[1]);
                    mma16816(acc[mt][np * 2 + 0], al[mt], bh[0], bh[1]);
                    mma16816(acc[mt][np * 2 + 1], ah[mt], bh[2], bh[3]);
                    mma16816(acc[mt][np * 2 + 1], ah[mt], bl[2], bl[3]);
                    mma16816(acc[mt][np * 2 + 1], al[mt], bh[2], bh[3]);
                }
            }
        }
    }
    int g = lane >> 2, tig = lane & 3;
#pragma unroll
    for (int mt = 0; mt < 2; mt++)
#pragma unroll
        for (int nt = 0; nt < 8; nt++) {
            int ml = wm + mt * 16 + g;
            int c = col0 + wn + nt * 8 + tig * 2;
            if (ml < nr)
                *(float2*)(out + (size_t)rid[ml] * DM + c) =
                    make_float2(acc[mt][nt][0], acc[mt][nt][1]);
            if (ml + 8 < nr)
                *(float2*)(out + (size_t)rid[ml + 8] * DM + c) =
                    make_float2(acc[mt][nt][2], acc[mt][nt][3]);
        }
}

extern "C" void kernel_launch(void* const* d_in, const int* in_sizes, int n_in,
                              void* d_out, int out_size) {
    const float* x    = (const float*)d_in[0];
    const int*   bi   = (const int*)d_in[1];
    const float* son  = (const float*)d_in[2];
    const int*   sbi  = (const int*)d_in[3];
    const float* temp = (const float*)d_in[4];
    const float* Wfx  = (const float*)d_in[5];
    const float* bfx  = (const float*)d_in[6];
    const float* Wx   = (const float*)d_in[7];
    const float* bx   = (const float*)d_in[8];
    const float* Wsl  = (const float*)d_in[9];
    const float* bsl  = (const float*)d_in[10];
    const float* Wq   = (const float*)d_in[11];
    const float* bq   = (const float*)d_in[12];
    const float* Wk   = (const float*)d_in[13];
    const float* bk   = (const float*)d_in[14];
    const float* Wv   = (const float*)d_in[15];
    const float* bv   = (const float*)d_in[16];
    const float* Wck  = (const float*)d_in[17];
    const float* bck  = (const float*)d_in[18];
    const float* Wcv  = (const float*)d_in[19];
    const float* bcv  = (const float*)d_in[20];
    const float* Wout = (const float*)d_in[21];
    float* out = (float*)d_out;

    cudaFuncSetAttribute(k_gemm_mma, cudaFuncAttributeMaxDynamicSharedMemorySize, SMEM_MMA);
    cudaFuncSetAttribute(k_final_mma, cudaFuncAttributeMaxDynamicSharedMemorySize, SMEM_MMA);

    k_bcomb<<<1, 512>>>(bx, Wsl, bsl);
    k_cvt_x<<<8192, 256>>>(x);
    k_wcomb<<<dim3(512, 2), 256>>>(Wx, Wsl, Wfx);
    k_gemm_mma<<<dim3(8, 128), 256, SMEM_MMA>>>(bfx);
    k_zero<<<1024, 256>>>();
    k_count<<<80, 256>>>(bi, sbi);
    k_prefix<<<1, 1>>>();
    k_scatter<<<80, 256>>>(bi, sbi);
    k_softmax<<<NT, 256>>>(temp);
    k_tokens<<<dim3(64, 16), 256>>>();
    k_qkv<<<dim3(64, 3), 256>>>(Wq, bq, Wk, bk, Wv, bv);
    k_attn<<<64, 256>>>();
    k_skv<<<dim3(512, 2), 256>>>(son, Wck, bck, Wcv, bcv);
    k_cross<<<64, 256>>>();
    k_P<<<dim3(64, 8), 256>>>(Wout);
    k_final_mma<<<dim3(4, 128, 8), 256, SMEM_MMA>>>(out);
}

// round 8
// speedup vs baseline: 2.0841x; 1.0289x over previous
#include <cuda_runtime.h>
#include <cuda_bf16.h>
#include <cstdint>

#define NT 16384   // x rows
#define MS 4096    // sonata rows
#define NB 8       // batches
#define NH 8       // heads
#define DH 64      // head dim
#define NG 64      // slice groups
#define DM 512     // model dim
#define SCL 0.125f // D^-0.5

#define SW64_(o) ((o) ^ (((o) >> 3) & 0x30))

__device__ __forceinline__ uint32_t smem_to_u32(const void* p) {
    uint32_t a;
    asm("{ .reg .u64 tmp; cvta.to.shared.u64 tmp, %1; cvt.u32.u64 %0, tmp; }"
        : "=r"(a) : "l"(p));
    return a;
}
__device__ __forceinline__ void ldsm4(uint32_t a[4], uint32_t addr) {
    asm volatile("ldmatrix.sync.aligned.m8n8.x4.shared.b16 {%0,%1,%2,%3}, [%4];"
                 : "=r"(a[0]), "=r"(a[1]), "=r"(a[2]), "=r"(a[3]) : "r"(addr));
}
__device__ __forceinline__ void mma16816(float c[4], const uint32_t a[4],
                                         uint32_t b0, uint32_t b1) {
    asm volatile(
        "mma.sync.aligned.m16n8k16.row.col.f32.bf16.bf16.f32 "
        "{%0,%1,%2,%3}, {%4,%5,%6,%7}, {%8,%9}, {%0,%1,%2,%3};"
        : "+f"(c[0]), "+f"(c[1]), "+f"(c[2]), "+f"(c[3])
        : "r"(a[0]), "r"(a[1]), "r"(a[2]), "r"(a[3]), "r"(b0), "r"(b1));
}
__device__ __forceinline__ void cp16(uint32_t dst, const void* src) {
    asm volatile("cp.async.cg.shared.global [%0], [%1], 16;" :: "r"(dst), "l"(src));
}
#define CP_COMMIT() asm volatile("cp.async.commit_group;" ::: "memory")
#define CP_WAIT1() asm volatile("cp.async.wait_group 1;" ::: "memory")
#define CP_WAIT0() asm volatile("cp.async.wait_group 0;" ::: "memory")

__device__ __forceinline__ void bsplit(float v, __nv_bfloat16& h, __nv_bfloat16& l) {
    h = __float2bfloat16(v);
    l = __float2bfloat16(v - __bfloat162float(h));
}

// pipelined MMA smem: 2 stages x (AH 8K | AL 8K | BH 8K | BL 8K) = 64KB
#define STG_BYTES 32768
#define OFFS_AH 0
#define OFFS_AL 8192
#define OFFS_BH 16384
#define OFFS_BL 24576
#define SMEM_MMA 65536
#define KSLAB 32

// ---------------- device scratch ----------------
__device__ float g_bcomb[DM];
__device__ float g_fx[(size_t)NT * DM];
__device__ float g_w[(size_t)NT * DM];
__device__ __nv_bfloat16 g_xhi[(size_t)NT * DM], g_xlo[(size_t)NT * DM];
__device__ __nv_bfloat16 g_Bthi[(size_t)2 * DM * DM], g_Btlo[(size_t)2 * DM * DM]; // [1024][512]
__device__ __nv_bfloat16 g_whi[(size_t)NT * DM], g_wlo[(size_t)NT * DM];
__device__ __nv_bfloat16 g_Pthi[(size_t)NB * DM * DM], g_Ptlo[(size_t)NB * DM * DM]; // [b][c][k]
__device__ float g_tokens[NB * NH * NG * DH];
__device__ float g_norms[NB * NH * NG];
__device__ float g_qkv[3 * NB * NH * NG * DH];
__device__ float g_outtok[NB * NH * NG * DH];
__device__ float g_ks[(size_t)MS * DM];
__device__ float g_vs[(size_t)MS * DM];
__device__ float g_scores[(size_t)NB * NH * NG * MS];
__device__ int g_rowlist[NT], g_rowcnt[NB], g_rowstart[NB + 1], g_rowcur[NB];
__device__ int g_mlist[MS], g_mcnt[NB], g_mstart[NB + 1], g_mcur[NB];

// ---------------- setup kernels ----------------
__global__ void k_zero() {
    int i = blockIdx.x * 256 + threadIdx.x;
    if (i < NB * NH * NG * DH) g_tokens[i] = 0.f;
    if (i < NB * NH * NG) g_norms[i] = 0.f;
    if (i < NB) {
        g_rowcnt[i] = 0; g_mcnt[i] = 0;
        g_rowcur[i] = 0; g_mcur[i] = 0;
    }
}

__global__ void k_bcomb(const float* __restrict__ bx, const float* __restrict__ Wsl,
                        const float* __restrict__ bsl) {
    int o = threadIdx.x;  // 512
    int h = o >> 6, g = o & 63;
    float acc = bsl[g];
    for (int d = 0; d < 64; d++) acc = fmaf(bx[h * 64 + d], Wsl[d * 64 + g], acc);
    g_bcomb[o] = acc;
}

// x fp32 -> bf16 hi/lo split
__global__ void k_cvt_x(const float* __restrict__ x) {
    size_t i = (size_t)blockIdx.x * 256 + threadIdx.x;  // one float4 each
    float4 v = ((const float4*)x)[i];
    __nv_bfloat16 h0, h1, h2, h3, l0, l1, l2, l3;
    bsplit(v.x, h0, l0); bsplit(v.y, h1, l1);
    bsplit(v.z, h2, l2); bsplit(v.w, h3, l3);
    ((__nv_bfloat162*)g_xhi)[i * 2 + 0] = __halves2bfloat162(h0, h1);
    ((__nv_bfloat162*)g_xhi)[i * 2 + 1] = __halves2bfloat162(h2, h3);
    ((__nv_bfloat162*)g_xlo)[i * 2 + 0] = __halves2bfloat162(l0, l1);
    ((__nv_bfloat162*)g_xlo)[i * 2 + 1] = __halves2bfloat162(l2, l3);
}

// y==1: Bt rows 0..511 (transposed Wfx); y==0: Bt rows 512..1023 from Wcomb = Wx·Wsl
__global__ void k_wcomb(const float* __restrict__ Wx, const float* __restrict__ Wsl,
                        const float* __restrict__ Wfx) {
    int c = blockIdx.x;  // 0..511
    int t = threadIdx.x;
    if (blockIdx.y == 1) {
        for (int k = t; k < DM; k += 256) {
            __nv_bfloat16 h, l;
            bsplit(Wfx[(size_t)k * DM + c], h, l);
            g_Bthi[(size_t)c * DM + k] = h;
            g_Btlo[(size_t)c * DM + k] = l;
        }
        return;
    }
    __shared__ float s_sl[4096];
    for (int i = t; i < 4096; i += 256) s_sl[i] = Wsl[i];
    __syncthreads();
    for (int o = t; o < 512; o += 256) {
        int h = o >> 6, g = o & 63;
        const float* wxr = Wx + (size_t)c * DM + h * 64;
        float acc = 0.f;
        for (int d = 0; d < 64; d++) acc = fmaf(wxr[d], s_sl[d * 64 + g], acc);
        __nv_bfloat16 hh, ll;
        bsplit(acc, hh, ll);
        g_Bthi[(size_t)(DM + o) * DM + c] = hh;
        g_Btlo[(size_t)(DM + o) * DM + c] = ll;
    }
}

__global__ void k_count(const int* __restrict__ bi, const int* __restrict__ sbi) {
    int i = blockIdx.x * 256 + threadIdx.x;
    if (i < NT) atomicAdd(&g_rowcnt[bi[i]], 1);
    else if (i < NT + MS) atomicAdd(&g_mcnt[sbi[i - NT]], 1);
}

__global__ void k_prefix() {
    if (threadIdx.x == 0) {
        int s = 0;
        for (int b = 0; b < NB; b++) { g_rowstart[b] = s; s += g_rowcnt[b]; }
        g_rowstart[NB] = s;
        s = 0;
        for (int b = 0; b < NB; b++) { g_mstart[b] = s; s += g_mcnt[b]; }
        g_mstart[NB] = s;
    }
}

__global__ void k_scatter(const int* __restrict__ bi, const int* __restrict__ sbi) {
    int i = blockIdx.x * 256 + threadIdx.x;
    if (i < NT) {
        int b = bi[i];
        int p = atomicAdd(&g_rowcur[b], 1);
        g_rowlist[g_rowstart[b] + p] = i;
    } else if (i < NT + MS) {
        int j = i - NT;
        int b = sbi[j];
        int p = atomicAdd(&g_mcur[b], 1);
        g_mlist[g_mstart[b] + p] = j;
    }
}

// ---------------- front GEMM via mma.sync bf16x3, cp.async 2-stage pipeline ----------------
// [16384x512] @ [512x1024] -> fx | w.  Tile 128x128, warp 32x64, K-slab 32, SW64.
__global__ void __launch_bounds__(256, 2)
k_gemm_mma(const float* __restrict__ bfx) {
    extern __shared__ char dynsmem[];
    uint32_t sb = smem_to_u32(dynsmem);
    int t = threadIdx.x;
    int lane = t & 31, wid = t >> 5;
    int wm = (wid & 3) * 32, wn = (wid >> 2) * 64;
    int row0 = blockIdx.y * 128, col0 = blockIdx.x * 128;
    float acc[2][8][4] = {};
    int a_row = wm + (lane & 15);
    int a_u = lane >> 4;            // 16B unit within k16
    int b_row = wn + (lane & 7) + ((lane >> 4) << 3);
    int b_u = (lane >> 3) & 1;

    auto load_slab = [&](int kc, int stg) {
        uint32_t sbase = sb + stg * STG_BYTES;
#pragma unroll
        for (int half = 0; half < 2; half++) {
            int idx = half * 256 + t;       // 0..511
            int r = idx >> 2, c = idx & 3;  // 128 rows x 4 16B-chunks
            uint32_t o = SW64_((uint32_t)(r * 64 + c * 16));
            size_t offa = (size_t)(row0 + r) * DM + kc + c * 8;
            size_t offb = (size_t)(col0 + r) * DM + kc + c * 8;
            cp16(sbase + OFFS_AH + o, g_xhi + offa);
            cp16(sbase + OFFS_AL + o, g_xlo + offa);
            cp16(sbase + OFFS_BH + o, g_Bthi + offb);
            cp16(sbase + OFFS_BL + o, g_Btlo + offb);
        }
        CP_COMMIT();
    };

    load_slab(0, 0);
#pragma unroll 1
    for (int ch = 0; ch < DM / KSLAB; ch++) {
        if (ch + 1 < DM / KSLAB) { load_slab((ch + 1) * KSLAB, (ch + 1) & 1); CP_WAIT1(); }
        else { CP_WAIT0(); }
        __syncthreads();
        uint32_t sbase = sb + (ch & 1) * STG_BYTES;
#pragma unroll
        for (int ks = 0; ks < 2; ks++) {
            uint32_t ah[2][4], al[2][4];
#pragma unroll
            for (int mt = 0; mt < 2; mt++) {
                uint32_t off = SW64_((uint32_t)((a_row + mt * 16) * 64 + ks * 32 + a_u * 16));
                ldsm4(ah[mt], sbase + OFFS_AH + off);
                ldsm4(al[mt], sbase + OFFS_AL + off);
            }
#pragma unroll
            for (int np = 0; np < 4; np++) {
                uint32_t bh[4], bl[4];
                uint32_t boff = SW64_((uint32_t)((b_row + np * 16) * 64 + ks * 32 + b_u * 16));
                ldsm4(bh, sbase + OFFS_BH + boff);
                ldsm4(bl, sbase + OFFS_BL + boff);
#pragma unroll
                for (int mt = 0; mt < 2; mt++) {
                    mma16816(acc[mt][np * 2 + 0], ah[mt], bh[0], bh[1]);
                    mma16816(acc[mt][np * 2 + 0], ah[mt], bl[0], bl[1]);
                    mma16816(acc[mt][np * 2 + 0], al[mt], bh[0], bh[1]);
                    mma16816(acc[mt][np * 2 + 1], ah[mt], bh[2], bh[3]);
                    mma16816(acc[mt][np * 2 + 1], ah[mt], bl[2], bl[3]);
                    mma16816(acc[mt][np * 2 + 1], al[mt], bh[2], bh[3]);
                }
            }
        }
        __syncthreads();
    }
    int g = lane >> 2, tig = lane & 3;
    bool isfx = (col0 < DM);
    float* dstb = isfx ? g_fx : g_w;
    int cbase = (isfx ? col0 : col0 - DM);
    const float* bias = isfx ? bfx : g_bcomb;
#pragma unroll
    for (int mt = 0; mt < 2; mt++)
#pragma unroll
        for (int nt = 0; nt < 8; nt++) {
            int r1 = row0 + wm + mt * 16 + g;
            int c = cbase + wn + nt * 8 + tig * 2;
            float b0v = bias[c], b1v = bias[c + 1];
            float2 v0 = make_float2(acc[mt][nt][0] + b0v, acc[mt][nt][1] + b1v);
            float2 v1 = make_float2(acc[mt][nt][2] + b0v, acc[mt][nt][3] + b1v);
            *(float2*)(dstb + (size_t)r1 * DM + c) = v0;
            *(float2*)(dstb + (size_t)(r1 + 8) * DM + c) = v1;
        }
}

// per-(n,h) softmax over 64 slice logits; writes fp32 w and bf16 hi/lo split
__global__ void k_softmax(const float* __restrict__ temp) {
    int n = blockIdx.x;
    int wid = threadIdx.x >> 5, lane = threadIdx.x & 31;
    size_t off = (size_t)n * DM + wid * 64;
    float* p = g_w + off;
    float it = 1.f / temp[wid];
    float v0 = p[lane] * it, v1 = p[lane + 32] * it;
    float m = fmaxf(v0, v1);
#pragma unroll
    for (int o = 16; o; o >>= 1) m = fmaxf(m, __shfl_xor_sync(0xFFFFFFFFu, m, o));
    float e0 = __expf(v0 - m), e1 = __expf(v1 - m);
    float s = e0 + e1;
#pragma unroll
    for (int o = 16; o; o >>= 1) s += __shfl_xor_sync(0xFFFFFFFFu, s, o);
    float inv = 1.f / s;
    float w0 = e0 * inv, w1 = e1 * inv;
    p[lane] = w0;
    p[lane + 32] = w1;
    __nv_bfloat16 h, l;
    bsplit(w0, h, l); g_whi[off + lane] = h; g_wlo[off + lane] = l;
    bsplit(w1, h, l); g_whi[off + lane + 32] = h; g_wlo[off + lane + 32] = l;
}

// tokens[b,h,g,d] = sum_{n in b} w[n,h,g] * fx[n,h,d]; norms[b,h,g] = sum w
__global__ void k_tokens() {
    int bh = blockIdx.x;
    int b = bh >> 3, h = bh & 7;
    int cnt = g_rowcnt[b], start = g_rowstart[b];
    int c0 = (int)(((long long)cnt * blockIdx.y) >> 4);
    int c1 = (int)(((long long)cnt * (blockIdx.y + 1)) >> 4);
    int t = threadIdx.x;
    int tg = (t >> 4) * 4, td = (t & 15) * 4;
    float acc[4][4] = {};
    float nacc[4] = {};
    __shared__ float ws[8][64], fs[8][64];
    __shared__ int rid[8];
    for (int i0 = c0; i0 < c1; i0 += 8) {
        int nr = c1 - i0; if (nr > 8) nr = 8;
        if (t < nr) rid[t] = g_rowlist[start + i0 + t];
        __syncthreads();
        for (int idx = t; idx < nr * 64; idx += 256) {
            int r = idx >> 6, c = idx & 63;
            size_t off = (size_t)rid[r] * DM + h * 64 + c;
            ws[r][c] = g_w[off];
            fs[r][c] = g_fx[off];
        }
        __syncthreads();
        for (int r = 0; r < nr; r++) {
            float wv[4], fv[4];
#pragma unroll
            for (int i = 0; i < 4; i++) { wv[i] = ws[r][tg + i]; fv[i] = fs[r][td + i]; }
#pragma unroll
            for (int i = 0; i < 4; i++) {
                if (td == 0) nacc[i] += wv[i];
#pragma unroll
                for (int j = 0; j < 4; j++) acc[i][j] = fmaf(wv[i], fv[j], acc[i][j]);
            }
        }
        __syncthreads();
    }
    float* tok = g_tokens + (size_t)bh * NG * DH;
#pragma unroll
    for (int i = 0; i < 4; i++) {
#pragma unroll
        for (int j = 0; j < 4; j++) atomicAdd(&tok[(tg + i) * DH + td + j], acc[i][j]);
        if (td == 0) atomicAdd(&g_norms[bh * NG + tg + i], nacc[i]);
    }
}

// q/k/v = normalized tokens @ W + b  (per (b,h), 64x64x64)
__global__ void k_qkv(const float* __restrict__ Wq, const float* __restrict__ bq,
                      const float* __restrict__ Wk, const float* __restrict__ bk,
                      const float* __restrict__ Wv, const float* __restrict__ bv) {
    int bh = blockIdx.x, sel = blockIdx.y;
    const float* W = sel == 0 ? Wq : (sel == 1 ? Wk : Wv);
    const float* bias = sel == 0 ? bq : (sel == 1 ? bk : bv);
    __shared__ float s_a[64][65];
    __shared__ float s_b[64][64];
    int t = threadIdx.x;
    for (int i = t; i < 4096; i += 256) {
        int g = i >> 6, d = i & 63;
        s_a[g][d] = g_tokens[(size_t)bh * 4096 + i] / (g_norms[bh * 64 + g] + 1e-5f);
        s_b[g][d] = W[i];
    }
    __syncthreads();
    int tx = t & 15, ty = t >> 4;
    float acc[4][4] = {};
    for (int k = 0; k < 64; k++) {
        float av[4], bv2[4];
#pragma unroll
        for (int i = 0; i < 4; i++) av[i] = s_a[ty * 4 + i][k];
#pragma unroll
        for (int j = 0; j < 4; j++) bv2[j] = s_b[k][tx * 4 + j];
#pragma unroll
        for (int i = 0; i < 4; i++)
#pragma unroll
            for (int j = 0; j < 4; j++) acc[i][j] = fmaf(av[i], bv2[j], acc[i][j]);
    }
    float* dst = g_qkv + ((size_t)sel * 64 + bh) * 4096;
#pragma unroll
    for (int i = 0; i < 4; i++)
#pragma unroll
        for (int j = 0; j < 4; j++)
            dst[(ty * 4 + i) * 64 + tx * 4 + j] = acc[i][j] + bias[tx * 4 + j];
}

// per-(b,h) 64x64 attention: out_tok = softmax(q k^T * SCL) @ v
__global__ void k_attn() {
    int bh = blockIdx.x;
    __shared__ float s_x[64][64];
    __shared__ float s_k[64][64];
    __shared__ float s_s[64][64];
    int t = threadIdx.x;
    const float* q = g_qkv + (size_t)bh * 4096;
    const float* kk_ = g_qkv + (size_t)(64 + bh) * 4096;
    const float* vv = g_qkv + (size_t)(128 + bh) * 4096;
    for (int i = t; i < 4096; i += 256) { s_x[i >> 6][i & 63] = q[i]; s_k[i >> 6][i & 63] = kk_[i]; }
    __syncthreads();
    int tx = t & 15, ty = t >> 4;
    {
        float acc[4][4] = {};
        for (int d = 0; d < 64; d++) {
            float av[4], bv[4];
#pragma unroll
            for (int i = 0; i < 4; i++) av[i] = s_x[ty * 4 + i][d];
#pragma unroll
            for (int j = 0; j < 4; j++) bv[j] = s_k[tx * 4 + j][d];
#pragma unroll
            for (int i = 0; i < 4; i++)
#pragma unroll
                for (int j = 0; j < 4; j++) acc[i][j] = fmaf(av[i], bv[j], acc[i][j]);
        }
#pragma unroll
        for (int i = 0; i < 4; i++)
#pragma unroll
            for (int j = 0; j < 4; j++) s_s[ty * 4 + i][tx * 4 + j] = acc[i][j] * SCL;
    }
    __syncthreads();
    for (int i = t; i < 4096; i += 256) s_x[i >> 6][i & 63] = vv[i];
    if (t < 64) {
        float m = -1e30f;
        for (int j = 0; j < 64; j++) m = fmaxf(m, s_s[t][j]);
        float s = 0.f;
        for (int j = 0; j < 64; j++) { float e = __expf(s_s[t][j] - m); s_s[t][j] = e; s += e; }
        float inv = 1.f / s;
        for (int j = 0; j < 64; j++) s_s[t][j] *= inv;
    }
    __syncthreads();
    float acc[4][4] = {};
    for (int k2 = 0; k2 < 64; k2++) {
        float av[4], bv[4];
#pragma unroll
        for (int i = 0; i < 4; i++) av[i] = s_s[ty * 4 + i][k2];
#pragma unroll
        for (int j = 0; j < 4; j++) bv[j] = s_x[k2][tx * 4 + j];
#pragma unroll
        for (int i = 0; i < 4; i++)
#pragma unroll
            for (int j = 0; j < 4; j++) acc[i][j] = fmaf(av[i], bv[j], acc[i][j]);
    }
#pragma unroll
    for (int i = 0; i < 4; i++)
#pragma unroll
        for (int j = 0; j < 4; j++)
            g_outtok[(size_t)bh * 4096 + (ty * 4 + i) * 64 + tx * 4 + j] = acc[i][j];
}

// sonata ks/vs projection: [32768x64] @ [64x64] + bias
__global__ void k_skv(const float* __restrict__ son,
                      const float* __restrict__ Wck, const float* __restrict__ bck,
                      const float* __restrict__ Wcv, const float* __restrict__ bcv) {
    int rt = blockIdx.x;
    int sel = blockIdx.y;
    const float* W = sel ? Wcv : Wck;
    const float* bias = sel ? bcv : bck;
    float* dst = sel ? g_vs : g_ks;
    __shared__ float s_at[64][65];
    __shared__ float s_b[64][64];
    int t = threadIdx.x;
    size_t base = (size_t)rt * 64 * 64;
    for (int i = t; i < 4096; i += 256) {
        s_at[i & 63][i >> 6] = son[base + i];
        s_b[i >> 6][i & 63] = W[i];
    }
    __syncthreads();
    int tx = t & 15, ty = t >> 4;
    float acc[4][4] = {};
    for (int k = 0; k < 64; k++) {
        float av[4], bv2[4];
#pragma unroll
        for (int i = 0; i < 4; i++) av[i] = s_at[k][ty * 4 + i];
#pragma unroll
        for (int j = 0; j < 4; j++) bv2[j] = s_b[k][tx * 4 + j];
#pragma unroll
        for (int i = 0; i < 4; i++)
#pragma unroll
            for (int j = 0; j < 4; j++) acc[i][j] = fmaf(av[i], bv2[j], acc[i][j]);
    }
#pragma unroll
    for (int i = 0; i < 4; i++)
#pragma unroll
        for (int j = 0; j < 4; j++)
            dst[base + (size_t)(ty * 4 + i) * 64 + tx * 4 + j] = acc[i][j] + bias[tx * 4 + j];
}

// per-(b,h): masked cross attention over sonata rows of batch b, out_tok += cw @ vs
__global__ void k_cross() {
    int bh = blockIdx.x, b = bh >> 3, h = bh & 7;
    int cnt = g_mcnt[b], start = g_mstart[b];
    if (cnt == 0) return;
    __shared__ float s_q[64][65];
    __shared__ float s_kv[32][64];
    __shared__ float s_cw[64][33];
    __shared__ float red[64][4];
    __shared__ int mid[32];
    int t = threadIdx.x;
    for (int i = t; i < 4096; i += 256) s_q[i >> 6][i & 63] = g_outtok[(size_t)bh * 4096 + i];
    __syncthreads();
    float* sc = g_scores + (size_t)bh * 64 * MS;
    for (int j0 = 0; j0 < cnt; j0 += 32) {
        int nj = cnt - j0; if (nj > 32) nj = 32;
        if (t < nj) mid[t] = g_mlist[start + j0 + t];
        __syncthreads();
        for (int i = t; i < nj * 64; i += 256) {
            int r = i >> 6, c = i & 63;
            s_kv[r][c] = g_ks[(size_t)mid[r] * DM + h * 64 + c];
        }
        __syncthreads();
        int g = t & 63, jp = t >> 6;
        for (int j = jp; j < nj; j += 4) {
            float a = 0.f;
#pragma unroll 16
            for (int d = 0; d < 64; d++) a = fmaf(s_q[g][d], s_kv[j][d], a);
            sc[(size_t)g * MS + j0 + j] = a * SCL;
        }
        __syncthreads();
    }
    {
        int g = t >> 2, part = t & 3;
        float m = -1e30f;
        for (int j = part; j < cnt; j += 4) m = fmaxf(m, sc[(size_t)g * MS + j]);
        red[g][part] = m;
        __syncthreads();
        m = fmaxf(fmaxf(red[g][0], red[g][1]), fmaxf(red[g][2], red[g][3]));
        float s = 0.f;
        for (int j = part; j < cnt; j += 4) s += __expf(sc[(size_t)g * MS + j] - m);
        __syncthreads();
        red[g][part] = s;
        __syncthreads();
        s = red[g][0] + red[g][1] + red[g][2] + red[g][3];
        float inv = 1.f / s;
        for (int j = part; j < cnt; j += 4)
            sc[(size_t)g * MS + j] = __expf(sc[(size_t)g * MS + j] - m) * inv;
    }
    __syncthreads();
    int tx = t & 15, ty = t >> 4;
    float acc[4][4] = {};
    for (int j0 = 0; j0 < cnt; j0 += 32) {
        int nj = cnt - j0; if (nj > 32) nj = 32;
        if (t < nj) mid[t] = g_mlist[start + j0 + t];
        __syncthreads();
        for (int i = t; i < nj * 64; i += 256) {
            int r = i >> 6, c = i & 63;
            s_kv[r][c] = g_vs[(size_t)mid[r] * DM + h * 64 + c];
        }
        for (int i = t; i < 64 * 32; i += 256) {
            int g = i >> 5, j = i & 31;
            s_cw[g][j] = (j < nj) ? sc[(size_t)g * MS + j0 + j] : 0.f;
        }
        __syncthreads();
        for (int j = 0; j < nj; j++) {
            float vvv[4];
#pragma unroll
            for (int jj = 0; jj < 4; jj++) vvv[jj] = s_kv[j][tx * 4 + jj];
#pragma unroll
            for (int i = 0; i < 4; i++) {
                float c = s_cw[ty * 4 + i][j];
#pragma unroll
                for (int jj = 0; jj < 4; jj++) acc[i][jj] = fmaf(c, vvv[jj], acc[i][jj]);
            }
        }
        __syncthreads();
    }
#pragma unroll
    for (int i = 0; i < 4; i++)
#pragma unroll
        for (int jj = 0; jj < 4; jj++) {
            size_t o = (size_t)bh * 4096 + (ty * 4 + i) * 64 + tx * 4 + jj;
            g_outtok[o] += acc[i][jj];
        }
}

// P[b, h*64+g, c] = sum_d out_tok[b,h,g,d] * W_out[h*64+d, c], stored transposed bf16 hi/lo
__global__ void k_P(const float* __restrict__ Wout) {
    int bh = blockIdx.x, b = bh >> 3, h = bh & 7;
    int col0 = blockIdx.y * 64;
    __shared__ float s_a[64][65];
    __shared__ float s_b[64][64];
    int t = threadIdx.x;
    for (int i = t; i < 4096; i += 256) {
        int r = i >> 6, c = i & 63;
        s_a[r][c] = g_outtok[(size_t)bh * 4096 + i];
        s_b[r][c] = Wout[(size_t)(h * 64 + r) * DM + col0 + c];
    }
    __syncthreads();
    int tx = t & 15, ty = t >> 4;
    float acc[4][4] = {};
    for (int d = 0; d < 64; d++) {
        float av[4], bv[4];
#pragma unroll
        for (int i = 0; i < 4; i++) av[i] = s_a[ty * 4 + i][d];
#pragma unroll
        for (int j = 0; j < 4; j++) bv[j] = s_b[d][tx * 4 + j];
#pragma unroll
        for (int i = 0; i < 4; i++)
#pragma unroll
            for (int j = 0; j < 4; j++) acc[i][j] = fmaf(av[i], bv[j], acc[i][j]);
    }
#pragma unroll
    for (int i = 0; i < 4; i++)
#pragma unroll
        for (int j = 0; j < 4; j++) {
            int r = h * 64 + ty * 4 + i;       // k index of P
            int c = col0 + tx * 4 + j;         // output col
            __nv_bfloat16 hh, ll;
            bsplit(acc[i][j], hh, ll);
            g_Pthi[((size_t)b * DM + c) * DM + r] = hh;
            g_Ptlo[((size_t)b * DM + c) * DM + r] = ll;
        }
}

// out[n, :] = w[n, :] @ P[batch(n)] via mma.sync bf16x3, gathered rows, pipelined
__global__ void __launch_bounds__(256, 2)
k_final_mma(float* __restrict__ out) {
    int b = blockIdx.z;
    int cnt = g_rowcnt[b];
    int r0 = blockIdx.y * 128;
    if (r0 >= cnt) return;
    int nr = cnt - r0; if (nr > 128) nr = 128;
    extern __shared__ char dynsmem[];
    uint32_t sb = smem_to_u32(dynsmem);
    __shared__ int rid[128];
    int t = threadIdx.x;
    int lane = t & 31, wid = t >> 5;
    int wm = (wid & 3) * 32, wn = (wid >> 2) * 64;
    int col0 = blockIdx.x * 128;
    int start = g_rowstart[b];
    if (t < 128) rid[t] = g_rowlist[start + r0 + (t < nr ? t : nr - 1)];
    __syncthreads();
    float acc[2][8][4] = {};
    int a_row = wm + (lane & 15);
    int a_u = lane >> 4;
    int b_row = wn + (lane & 7) + ((lane >> 4) << 3);
    int b_u = (lane >> 3) & 1;
    const __nv_bfloat16* Ph = g_Pthi + ((size_t)b * DM + col0) * DM;
    const __nv_bfloat16* Pl = g_Ptlo + ((size_t)b * DM + col0) * DM;

    auto load_slab = [&](int kc, int stg) {
        uint32_t sbase = sb + stg * STG_BYTES;
#pragma unroll
        for (int half = 0; half < 2; half++) {
            int idx = half * 256 + t;
            int r = idx >> 2, c = idx & 3;
            uint32_t o = SW64_((uint32_t)(r * 64 + c * 16));
            size_t offa = (size_t)rid[r] * DM + kc + c * 8;
            size_t offb = (size_t)r * DM + kc + c * 8;
            cp16(sbase + OFFS_AH + o, g_whi + offa);
            cp16(sbase + OFFS_AL + o, g_wlo + offa);
            cp16(sbase + OFFS_BH + o, Ph + offb);
            cp16(sbase + OFFS_BL + o, Pl + offb);
        }
        CP_COMMIT();
    };

    load_slab(0, 0);
#pragma unroll 1
    for (int ch = 0; ch < DM / KSLAB; ch++) {
        if (ch + 1 < DM / KSLAB) { load_slab((ch + 1) * KSLAB, (ch + 1) & 1); CP_WAIT1(); }
        else { CP_WAIT0(); }
        __syncthreads();
        uint32_t sbase = sb + (ch & 1) * STG_BYTES;
#pragma unroll
        for (int ks = 0; ks < 2; ks++) {
            uint32_t ah[2][4], al[2][4];
#pragma unroll
            for (int mt = 0; mt < 2; mt++) {
                uint32_t off = SW64_((uint32_t)((a_row + mt * 16) * 64 + ks * 32 + a_u * 16));
                ldsm4(ah[mt], sbase + OFFS_AH + off);
                ldsm4(al[mt], sbase + OFFS_AL + off);
            }
#pragma unroll
            for (int np = 0; np < 4; np++) {
                uint32_t bh[4], bl[4];
                uint32_t boff = SW64_((uint32_t)((b_row + np * 16) * 64 + ks * 32 + b_u * 16));
                ldsm4(bh, sbase + OFFS_BH + boff);
                ldsm4(bl, sbase + OFFS_BL + boff);
#pragma unroll
                for (int mt = 0; mt < 2; mt++) {
                    mma16816(acc[mt][np * 2 + 0], ah[mt], bh[0], bh[1]);
                    mma16816(acc[mt][np * 2 + 0], ah[mt], bl[0], bl[1]);
                    mma16816(acc[mt][np * 2 + 0], al[mt], bh[0], bh[1]);
                    mma16816(acc[mt][np * 2 + 1], ah[mt], bh[2], bh[3]);
                    mma16816(acc[mt][np * 2 + 1], ah[mt], bl[2], bl[3]);
                    mma16816(acc[mt][np * 2 + 1], al[mt], bh[2], bh[3]);
                }
            }
        }
        __syncthreads();
    }
    int g = lane >> 2, tig = lane & 3;
#pragma unroll
    for (int mt = 0; mt < 2; mt++)
#pragma unroll
        for (int nt = 0; nt < 8; nt++) {
            int ml = wm + mt * 16 + g;
            int c = col0 + wn + nt * 8 + tig * 2;
            if (ml < nr)
                *(float2*)(out + (size_t)rid[ml] * DM + c) =
                    make_float2(acc[mt][nt][0], acc[mt][nt][1]);
            if (ml + 8 < nr)
                *(float2*)(out + (size_t)rid[ml + 8] * DM + c) =
                    make_float2(acc[mt][nt][2], acc[mt][nt][3]);
        }
}

extern "C" void kernel_launch(void* const* d_in, const int* in_sizes, int n_in,
                              void* d_out, int out_size) {
    const float* x    = (const float*)d_in[0];
    const int*   bi   = (const int*)d_in[1];
    const float* son  = (const float*)d_in[2];
    const int*   sbi  = (const int*)d_in[3];
    const float* temp = (const float*)d_in[4];
    const float* Wfx  = (const float*)d_in[5];
    const float* bfx  = (const float*)d_in[6];
    const float* Wx   = (const float*)d_in[7];
    const float* bx   = (const float*)d_in[8];
    const float* Wsl  = (const float*)d_in[9];
    const float* bsl  = (const float*)d_in[10];
    const float* Wq   = (const float*)d_in[11];
    const float* bq   = (const float*)d_in[12];
    const float* Wk   = (const float*)d_in[13];
    const float* bk   = (const float*)d_in[14];
    const float* Wv   = (const float*)d_in[15];
    const float* bv   = (const float*)d_in[16];
    const float* Wck  = (const float*)d_in[17];
    const float* bck  = (const float*)d_in[18];
    const float* Wcv  = (const float*)d_in[19];
    const float* bcv  = (const float*)d_in[20];
    const float* Wout = (const float*)d_in[21];
    float* out = (float*)d_out;

    cudaFuncSetAttribute(k_gemm_mma, cudaFuncAttributeMaxDynamicSharedMemorySize, SMEM_MMA);
    cudaFuncSetAttribute(k_final_mma, cudaFuncAttributeMaxDynamicSharedMemorySize, SMEM_MMA);

    k_bcomb<<<1, 512>>>(bx, Wsl, bsl);
    k_cvt_x<<<8192, 256>>>(x);
    k_wcomb<<<dim3(512, 2), 256>>>(Wx, Wsl, Wfx);
    k_gemm_mma<<<dim3(8, 128), 256, SMEM_MMA>>>(bfx);
    k_zero<<<1024, 256>>>();
    k_count<<<80, 256>>>(bi, sbi);
    k_prefix<<<1, 1>>>();
    k_scatter<<<80, 256>>>(bi, sbi);
    k_softmax<<<NT, 256>>>(temp);
    k_tokens<<<dim3(64, 16), 256>>>();
    k_qkv<<<dim3(64, 3), 256>>>(Wq, bq, Wk, bk, Wv, bv);
    k_attn<<<64, 256>>>();
    k_skv<<<dim3(512, 2), 256>>>(son, Wck, bck, Wcv, bcv);
    k_cross<<<64, 256>>>();
    k_P<<<dim3(64, 8), 256>>>(Wout);
    k_final_mma<<<dim3(4, 128, 8), 256, SMEM_MMA>>>(out);
}

// round 9
// speedup vs baseline: 2.5600x; 1.2284x over previous
#include <cuda_runtime.h>
#include <cuda_bf16.h>
#include <cstdint>

#define NT 16384   // x rows
#define MS 4096    // sonata rows
#define NB 8       // batches
#define NH 8       // heads
#define DH 64      // head dim
#define NG 64      // slice groups
#define DM 512     // model dim
#define SCL 0.125f // D^-0.5

#define SW64_(o) ((o) ^ (((o) >> 3) & 0x30))

__device__ __forceinline__ uint32_t smem_to_u32(const void* p) {
    uint32_t a;
    asm("{ .reg .u64 tmp; cvta.to.shared.u64 tmp, %1; cvt.u32.u64 %0, tmp; }"
        : "=r"(a) : "l"(p));
    return a;
}
__device__ __forceinline__ void ldsm4(uint32_t a[4], uint32_t addr) {
    asm volatile("ldmatrix.sync.aligned.m8n8.x4.shared.b16 {%0,%1,%2,%3}, [%4];"
                 : "=r"(a[0]), "=r"(a[1]), "=r"(a[2]), "=r"(a[3]) : "r"(addr));
}
__device__ __forceinline__ void mma16816(float c[4], const uint32_t a[4],
                                         uint32_t b0, uint32_t b1) {
    asm volatile(
        "mma.sync.aligned.m16n8k16.row.col.f32.bf16.bf16.f32 "
        "{%0,%1,%2,%3}, {%4,%5,%6,%7}, {%8,%9}, {%0,%1,%2,%3};"
        : "+f"(c[0]), "+f"(c[1]), "+f"(c[2]), "+f"(c[3])
        : "r"(a[0]), "r"(a[1]), "r"(a[2]), "r"(a[3]), "r"(b0), "r"(b1));
}
__device__ __forceinline__ void cp16(uint32_t dst, const void* src) {
    asm volatile("cp.async.cg.shared.global [%0], [%1], 16;" :: "r"(dst), "l"(src));
}
#define CP_COMMIT() asm volatile("cp.async.commit_group;" ::: "memory")
#define CP_WAIT2() asm volatile("cp.async.wait_group 2;" ::: "memory")
#define CP_WAIT1() asm volatile("cp.async.wait_group 1;" ::: "memory")
#define CP_WAIT0() asm volatile("cp.async.wait_group 0;" ::: "memory")

__device__ __forceinline__ void bsplit(float v, __nv_bfloat16& h, __nv_bfloat16& l) {
    h = __float2bfloat16(v);
    l = __float2bfloat16(v - __bfloat162float(h));
}

// pipelined MMA smem: 3 stages x (AH 8K | AL 8K | BH 8K | BL 8K) = 96KB
#define STG_BYTES 32768
#define OFFS_AH 0
#define OFFS_AL 8192
#define OFFS_BH 16384
#define OFFS_BL 24576
#define SMEM_MMA (3 * STG_BYTES)
#define KSLAB 32
#define NSLAB (DM / KSLAB)

// fused qkv+attn smem: a[64][65] + q,k,v,s 4x[64][64]  (floats)
#define QKV_SMEM ((64 * 65 + 4 * 4096) * 4)

// ---------------- device scratch ----------------
__device__ float g_bcomb[DM];
__device__ float g_fx[(size_t)NT * DM];
__device__ float g_w[(size_t)NT * DM];
__device__ __nv_bfloat16 g_xhi[(size_t)NT * DM], g_xlo[(size_t)NT * DM];
__device__ __nv_bfloat16 g_Bthi[(size_t)2 * DM * DM], g_Btlo[(size_t)2 * DM * DM]; // [1024][512]
__device__ __nv_bfloat16 g_whi[(size_t)NT * DM], g_wlo[(size_t)NT * DM];
__device__ __nv_bfloat16 g_Pthi[(size_t)NB * DM * DM], g_Ptlo[(size_t)NB * DM * DM]; // [b][c][k]
__device__ float g_tokens[NB * NH * NG * DH];
__device__ float g_norms[NB * NH * NG];
__device__ float g_outtok[NB * NH * NG * DH];
__device__ float g_ks[(size_t)MS * DM];
__device__ float g_vs[(size_t)MS * DM];
__device__ float g_scores[(size_t)NB * NH * NG * MS];
__device__ int g_rowlist[NT], g_rowcnt[NB], g_rowstart[NB + 1], g_rowcur[NB];
__device__ int g_mlist[MS], g_mcnt[NB], g_mstart[NB + 1], g_mcur[NB];

// ---------------- setup kernels ----------------
__global__ void k_zero() {
    int i = blockIdx.x * 256 + threadIdx.x;
    if (i < NB * NH * NG * DH) g_tokens[i] = 0.f;
    if (i < NB * NH * NG) g_norms[i] = 0.f;
    if (i < NB) {
        g_rowcnt[i] = 0; g_mcnt[i] = 0;
        g_rowcur[i] = 0; g_mcur[i] = 0;
    }
}

__global__ void k_bcomb(const float* __restrict__ bx, const float* __restrict__ Wsl,
                        const float* __restrict__ bsl) {
    int o = threadIdx.x;  // 512
    int h = o >> 6, g = o & 63;
    float acc = bsl[g];
    for (int d = 0; d < 64; d++) acc = fmaf(bx[h * 64 + d], Wsl[d * 64 + g], acc);
    g_bcomb[o] = acc;
}

// x fp32 -> bf16 hi/lo split
__global__ void k_cvt_x(const float* __restrict__ x) {
    size_t i = (size_t)blockIdx.x * 256 + threadIdx.x;  // one float4 each
    float4 v = ((const float4*)x)[i];
    __nv_bfloat16 h0, h1, h2, h3, l0, l1, l2, l3;
    bsplit(v.x, h0, l0); bsplit(v.y, h1, l1);
    bsplit(v.z, h2, l2); bsplit(v.w, h3, l3);
    ((__nv_bfloat162*)g_xhi)[i * 2 + 0] = __halves2bfloat162(h0, h1);
    ((__nv_bfloat162*)g_xhi)[i * 2 + 1] = __halves2bfloat162(h2, h3);
    ((__nv_bfloat162*)g_xlo)[i * 2 + 0] = __halves2bfloat162(l0, l1);
    ((__nv_bfloat162*)g_xlo)[i * 2 + 1] = __halves2bfloat162(l2, l3);
}

// y==1: Bt rows 0..511 (transposed Wfx); y==0: Bt rows 512..1023 from Wcomb = Wx·Wsl
__global__ void k_wcomb(const float* __restrict__ Wx, const float* __restrict__ Wsl,
                        const float* __restrict__ Wfx) {
    int c = blockIdx.x;  // 0..511
    int t = threadIdx.x;
    if (blockIdx.y == 1) {
        for (int k = t; k < DM; k += 256) {
            __nv_bfloat16 h, l;
            bsplit(Wfx[(size_t)k * DM + c], h, l);
            g_Bthi[(size_t)c * DM + k] = h;
            g_Btlo[(size_t)c * DM + k] = l;
        }
        return;
    }
    __shared__ float s_sl[4096];
    for (int i = t; i < 4096; i += 256) s_sl[i] = Wsl[i];
    __syncthreads();
    for (int o = t; o < 512; o += 256) {
        int h = o >> 6, g = o & 63;
        const float* wxr = Wx + (size_t)c * DM + h * 64;
        float acc = 0.f;
        for (int d = 0; d < 64; d++) acc = fmaf(wxr[d], s_sl[d * 64 + g], acc);
        __nv_bfloat16 hh, ll;
        bsplit(acc, hh, ll);
        g_Bthi[(size_t)(DM + o) * DM + c] = hh;
        g_Btlo[(size_t)(DM + o) * DM + c] = ll;
    }
}

__global__ void k_count(const int* __restrict__ bi, const int* __restrict__ sbi) {
    int i = blockIdx.x * 256 + threadIdx.x;
    if (i < NT) atomicAdd(&g_rowcnt[bi[i]], 1);
    else if (i < NT + MS) atomicAdd(&g_mcnt[sbi[i - NT]], 1);
}

__global__ void k_prefix() {
    if (threadIdx.x == 0) {
        int s = 0;
        for (int b = 0; b < NB; b++) { g_rowstart[b] = s; s += g_rowcnt[b]; }
        g_rowstart[NB] = s;
        s = 0;
        for (int b = 0; b < NB; b++) { g_mstart[b] = s; s += g_mcnt[b]; }
        g_mstart[NB] = s;
    }
}

__global__ void k_scatter(const int* __restrict__ bi, const int* __restrict__ sbi) {
    int i = blockIdx.x * 256 + threadIdx.x;
    if (i < NT) {
        int b = bi[i];
        int p = atomicAdd(&g_rowcur[b], 1);
        g_rowlist[g_rowstart[b] + p] = i;
    } else if (i < NT + MS) {
        int j = i - NT;
        int b = sbi[j];
        int p = atomicAdd(&g_mcur[b], 1);
        g_mlist[g_mstart[b] + p] = j;
    }
}

// ---------------- front GEMM via mma.sync bf16x3, cp.async 3-stage pipeline ----------------
__global__ void __launch_bounds__(256, 2)
k_gemm_mma(const float* __restrict__ bfx) {
    extern __shared__ char dynsmem[];
    uint32_t sb = smem_to_u32(dynsmem);
    int t = threadIdx.x;
    int lane = t & 31, wid = t >> 5;
    int wm = (wid & 3) * 32, wn = (wid >> 2) * 64;
    int row0 = blockIdx.y * 128, col0 = blockIdx.x * 128;
    float acc[2][8][4] = {};
    int a_row = wm + (lane & 15);
    int a_u = lane >> 4;
    int b_row = wn + (lane & 7) + ((lane >> 4) << 3);
    int b_u = (lane >> 3) & 1;

    auto load_slab = [&](int kc, int stg) {
        uint32_t sbase = sb + stg * STG_BYTES;
#pragma unroll
        for (int half = 0; half < 2; half++) {
            int idx = half * 256 + t;
            int r = idx >> 2, c = idx & 3;
            uint32_t o = SW64_((uint32_t)(r * 64 + c * 16));
            size_t offa = (size_t)(row0 + r) * DM + kc + c * 8;
            size_t offb = (size_t)(col0 + r) * DM + kc + c * 8;
            cp16(sbase + OFFS_AH + o, g_xhi + offa);
            cp16(sbase + OFFS_AL + o, g_xlo + offa);
            cp16(sbase + OFFS_BH + o, g_Bthi + offb);
            cp16(sbase + OFFS_BL + o, g_Btlo + offb);
        }
        CP_COMMIT();
    };

    load_slab(0, 0);
    load_slab(KSLAB, 1);
#pragma unroll 1
    for (int ch = 0; ch < NSLAB; ch++) {
        if (ch + 2 < NSLAB) { load_slab((ch + 2) * KSLAB, (ch + 2) % 3); CP_WAIT2(); }
        else if (ch + 1 < NSLAB) { CP_WAIT1(); }
        else { CP_WAIT0(); }
        __syncthreads();
        uint32_t sbase = sb + (ch % 3) * STG_BYTES;
#pragma unroll
        for (int ks = 0; ks < 2; ks++) {
            uint32_t ah[2][4], al[2][4];
#pragma unroll
            for (int mt = 0; mt < 2; mt++) {
                uint32_t off = SW64_((uint32_t)((a_row + mt * 16) * 64 + ks * 32 + a_u * 16));
                ldsm4(ah[mt], sbase + OFFS_AH + off);
                ldsm4(al[mt], sbase + OFFS_AL + off);
            }
#pragma unroll
            for (int np = 0; np < 4; np++) {
                uint32_t bh[4], bl[4];
                uint32_t boff = SW64_((uint32_t)((b_row + np * 16) * 64 + ks * 32 + b_u * 16));
                ldsm4(bh, sbase + OFFS_BH + boff);
                ldsm4(bl, sbase + OFFS_BL + boff);
#pragma unroll
                for (int mt = 0; mt < 2; mt++) {
                    mma16816(acc[mt][np * 2 + 0], ah[mt], bh[0], bh[1]);
                    mma16816(acc[mt][np * 2 + 0], ah[mt], bl[0], bl[1]);
                    mma16816(acc[mt][np * 2 + 0], al[mt], bh[0], bh[1]);
                    mma16816(acc[mt][np * 2 + 1], ah[mt], bh[2], bh[3]);
                    mma16816(acc[mt][np * 2 + 1], ah[mt], bl[2], bl[3]);
                    mma16816(acc[mt][np * 2 + 1], al[mt], bh[2], bh[3]);
                }
            }
        }
        __syncthreads();
    }
    int g = lane >> 2, tig = lane & 3;
    bool isfx = (col0 < DM);
    float* dstb = isfx ? g_fx : g_w;
    int cbase = (isfx ? col0 : col0 - DM);
    const float* bias = isfx ? bfx : g_bcomb;
#pragma unroll
    for (int mt = 0; mt < 2; mt++)
#pragma unroll
        for (int nt = 0; nt < 8; nt++) {
            int r1 = row0 + wm + mt * 16 + g;
            int c = cbase + wn + nt * 8 + tig * 2;
            float b0v = bias[c], b1v = bias[c + 1];
            float2 v0 = make_float2(acc[mt][nt][0] + b0v, acc[mt][nt][1] + b1v);
            float2 v1 = make_float2(acc[mt][nt][2] + b0v, acc[mt][nt][3] + b1v);
            *(float2*)(dstb + (size_t)r1 * DM + c) = v0;
            *(float2*)(dstb + (size_t)(r1 + 8) * DM + c) = v1;
        }
}

// per-(n,h) softmax over 64 slice logits; writes fp32 w and bf16 hi/lo split
__global__ void k_softmax(const float* __restrict__ temp) {
    int n = blockIdx.x;
    int wid = threadIdx.x >> 5, lane = threadIdx.x & 31;
    size_t off = (size_t)n * DM + wid * 64;
    float* p = g_w + off;
    float it = 1.f / temp[wid];
    float v0 = p[lane] * it, v1 = p[lane + 32] * it;
    float m = fmaxf(v0, v1);
#pragma unroll
    for (int o = 16; o; o >>= 1) m = fmaxf(m, __shfl_xor_sync(0xFFFFFFFFu, m, o));
    float e0 = __expf(v0 - m), e1 = __expf(v1 - m);
    float s = e0 + e1;
#pragma unroll
    for (int o = 16; o; o >>= 1) s += __shfl_xor_sync(0xFFFFFFFFu, s, o);
    float inv = 1.f / s;
    float w0 = e0 * inv, w1 = e1 * inv;
    p[lane] = w0;
    p[lane + 32] = w1;
    __nv_bfloat16 h, l;
    bsplit(w0, h, l); g_whi[off + lane] = h; g_wlo[off + lane] = l;
    bsplit(w1, h, l); g_whi[off + lane + 32] = h; g_wlo[off + lane + 32] = l;
}

// tokens[b,h,g,d] = sum_{n in b} w[n,h,g] * fx[n,h,d]; norms[b,h,g] = sum w
__global__ void k_tokens() {
    int bh = blockIdx.x;
    int b = bh >> 3, h = bh & 7;
    int cnt = g_rowcnt[b], start = g_rowstart[b];
    int c0 = (int)(((long long)cnt * blockIdx.y) >> 4);
    int c1 = (int)(((long long)cnt * (blockIdx.y + 1)) >> 4);
    int t = threadIdx.x;
    int tg = (t >> 4) * 4, td = (t & 15) * 4;
    float acc[4][4] = {};
    float nacc[4] = {};
    __shared__ float ws[8][64], fs[8][64];
    __shared__ int rid[8];
    for (int i0 = c0; i0 < c1; i0 += 8) {
        int nr = c1 - i0; if (nr > 8) nr = 8;
        if (t < nr) rid[t] = g_rowlist[start + i0 + t];
        __syncthreads();
        for (int idx = t; idx < nr * 64; idx += 256) {
            int r = idx >> 6, c = idx & 63;
            size_t off = (size_t)rid[r] * DM + h * 64 + c;
            ws[r][c] = g_w[off];
            fs[r][c] = g_fx[off];
        }
        __syncthreads();
        for (int r = 0; r < nr; r++) {
            float wv[4], fv[4];
#pragma unroll
            for (int i = 0; i < 4; i++) { wv[i] = ws[r][tg + i]; fv[i] = fs[r][td + i]; }
#pragma unroll
            for (int i = 0; i < 4; i++) {
                if (td == 0) nacc[i] += wv[i];
#pragma unroll
                for (int j = 0; j < 4; j++) acc[i][j] = fmaf(wv[i], fv[j], acc[i][j]);
            }
        }
        __syncthreads();
    }
    float* tok = g_tokens + (size_t)bh * NG * DH;
#pragma unroll
    for (int i = 0; i < 4; i++) {
#pragma unroll
        for (int j = 0; j < 4; j++) atomicAdd(&tok[(tg + i) * DH + td + j], acc[i][j]);
        if (td == 0) atomicAdd(&g_norms[bh * NG + tg + i], nacc[i]);
    }
}

// fused q/k/v projection + 64x64 self-attention per (b,h)
__global__ void k_qkvattn(const float* __restrict__ Wq, const float* __restrict__ bq,
                          const float* __restrict__ Wk, const float* __restrict__ bk,
                          const float* __restrict__ Wv, const float* __restrict__ bv) {
    int bh = blockIdx.x;
    extern __shared__ float fsm[];
    float* s_a = fsm;                 // [64][65]
    float* s_q = fsm + 64 * 65;
    float* s_k = s_q + 4096;
    float* s_v = s_k + 4096;
    float* s_s = s_v + 4096;          // W staging, then scores
    int t = threadIdx.x;
    for (int i = t; i < 4096; i += 256) {
        int g = i >> 6, d = i & 63;
        s_a[g * 65 + d] = g_tokens[(size_t)bh * 4096 + i] / (g_norms[bh * 64 + g] + 1e-5f);
    }
    int tx = t & 15, ty = t >> 4;
    const float* Ws[3] = {Wq, Wk, Wv};
    const float* bs[3] = {bq, bk, bv};
    float* outs[3] = {s_q, s_k, s_v};
#pragma unroll 1
    for (int p = 0; p < 3; p++) {
        for (int i = t; i < 4096; i += 256) s_s[i] = Ws[p][i];
        __syncthreads();
        float acc[4][4] = {};
        for (int k = 0; k < 64; k++) {
            float av[4], bv2[4];
#pragma unroll
            for (int i = 0; i < 4; i++) av[i] = s_a[(ty * 4 + i) * 65 + k];
#pragma unroll
            for (int j = 0; j < 4; j++) bv2[j] = s_s[k * 64 + tx * 4 + j];
#pragma unroll
            for (int i = 0; i < 4; i++)
#pragma unroll
                for (int j = 0; j < 4; j++) acc[i][j] = fmaf(av[i], bv2[j], acc[i][j]);
        }
#pragma unroll
        for (int i = 0; i < 4; i++)
#pragma unroll
            for (int j = 0; j < 4; j++)
                outs[p][(ty * 4 + i) * 64 + tx * 4 + j] = acc[i][j] + bs[p][tx * 4 + j];
        __syncthreads();
    }
    // scores = q k^T * SCL into s_s
    {
        float acc[4][4] = {};
        for (int d = 0; d < 64; d++) {
            float av[4], bv2[4];
#pragma unroll
            for (int i = 0; i < 4; i++) av[i] = s_q[(ty * 4 + i) * 64 + d];
#pragma unroll
            for (int j = 0; j < 4; j++) bv2[j] = s_k[(tx * 4 + j) * 64 + d];
#pragma unroll
            for (int i = 0; i < 4; i++)
#pragma unroll
                for (int j = 0; j < 4; j++) acc[i][j] = fmaf(av[i], bv2[j], acc[i][j]);
        }
#pragma unroll
        for (int i = 0; i < 4; i++)
#pragma unroll
            for (int j = 0; j < 4; j++)
                s_s[(ty * 4 + i) * 64 + tx * 4 + j] = acc[i][j] * SCL;
    }
    __syncthreads();
    if (t < 64) {
        float m = -1e30f;
        for (int j = 0; j < 64; j++) m = fmaxf(m, s_s[t * 64 + j]);
        float s = 0.f;
        for (int j = 0; j < 64; j++) { float e = __expf(s_s[t * 64 + j] - m); s_s[t * 64 + j] = e; s += e; }
        float inv = 1.f / s;
        for (int j = 0; j < 64; j++) s_s[t * 64 + j] *= inv;
    }
    __syncthreads();
    float acc[4][4] = {};
    for (int k2 = 0; k2 < 64; k2++) {
        float av[4], bv2[4];
#pragma unroll
        for (int i = 0; i < 4; i++) av[i] = s_s[(ty * 4 + i) * 64 + k2];
#pragma unroll
        for (int j = 0; j < 4; j++) bv2[j] = s_v[k2 * 64 + tx * 4 + j];
#pragma unroll
        for (int i = 0; i < 4; i++)
#pragma unroll
            for (int j = 0; j < 4; j++) acc[i][j] = fmaf(av[i], bv2[j], acc[i][j]);
    }
#pragma unroll
    for (int i = 0; i < 4; i++)
#pragma unroll
        for (int j = 0; j < 4; j++)
            g_outtok[(size_t)bh * 4096 + (ty * 4 + i) * 64 + tx * 4 + j] = acc[i][j];
}

// sonata ks/vs projection: [32768x64] @ [64x64] + bias
__global__ void k_skv(const float* __restrict__ son,
                      const float* __restrict__ Wck, const float* __restrict__ bck,
                      const float* __restrict__ Wcv, const float* __restrict__ bcv) {
    int rt = blockIdx.x;
    int sel = blockIdx.y;
    const float* W = sel ? Wcv : Wck;
    const float* bias = sel ? bcv : bck;
    float* dst = sel ? g_vs : g_ks;
    __shared__ float s_at[64][65];
    __shared__ float s_b[64][64];
    int t = threadIdx.x;
    size_t base = (size_t)rt * 64 * 64;
    for (int i = t; i < 4096; i += 256) {
        s_at[i & 63][i >> 6] = son[base + i];
        s_b[i >> 6][i & 63] = W[i];
    }
    __syncthreads();
    int tx = t & 15, ty = t >> 4;
    float acc[4][4] = {};
    for (int k = 0; k < 64; k++) {
        float av[4], bv2[4];
#pragma unroll
        for (int i = 0; i < 4; i++) av[i] = s_at[k][ty * 4 + i];
#pragma unroll
        for (int j = 0; j < 4; j++) bv2[j] = s_b[k][tx * 4 + j];
#pragma unroll
        for (int i = 0; i < 4; i++)
#pragma unroll
            for (int j = 0; j < 4; j++) acc[i][j] = fmaf(av[i], bv2[j], acc[i][j]);
    }
#pragma unroll
    for (int i = 0; i < 4; i++)
#pragma unroll
        for (int j = 0; j < 4; j++)
            dst[base + (size_t)(ty * 4 + i) * 64 + tx * 4 + j] = acc[i][j] + bias[tx * 4 + j];
}

// cross-attention scores: grid (64 bh, 8 j-slices)
__global__ void k_cross_score() {
    int bh = blockIdx.x, b = bh >> 3, h = bh & 7;
    int cnt = g_mcnt[b], start = g_mstart[b];
    if (cnt == 0) return;
    int sl = blockIdx.y;
    int lo = (int)(((long long)cnt * sl) >> 3);
    int hi = (int)(((long long)cnt * (sl + 1)) >> 3);
    if (lo >= hi) return;
    __shared__ float s_q[64][65];
    __shared__ float s_kv[32][64];
    __shared__ int mid[32];
    int t = threadIdx.x;
    for (int i = t; i < 4096; i += 256) s_q[i >> 6][i & 63] = g_outtok[(size_t)bh * 4096 + i];
    __syncthreads();
    float* sc = g_scores + (size_t)bh * 64 * MS;
    for (int j0 = lo; j0 < hi; j0 += 32) {
        int nj = hi - j0; if (nj > 32) nj = 32;
        if (t < nj) mid[t] = g_mlist[start + j0 + t];
        __syncthreads();
        for (int i = t; i < nj * 64; i += 256) {
            int r = i >> 6, c = i & 63;
            s_kv[r][c] = g_ks[(size_t)mid[r] * DM + h * 64 + c];
        }
        __syncthreads();
        int g = t & 63, jp = t >> 6;
        for (int j = jp; j < nj; j += 4) {
            float a = 0.f;
#pragma unroll 16
            for (int d = 0; d < 64; d++) a = fmaf(s_q[g][d], s_kv[j][d], a);
            sc[(size_t)g * MS + j0 + j] = a * SCL;
        }
        __syncthreads();
    }
}

// cross-attention softmax: grid (64 bh), warp handles 8 rows
__global__ void k_cross_soft() {
    int bh = blockIdx.x, b = bh >> 3;
    int cnt = g_mcnt[b];
    if (cnt == 0) return;
    float* sc = g_scores + (size_t)bh * 64 * MS;
    int warp = threadIdx.x >> 5, lane = threadIdx.x & 31;
    for (int g = warp * 8; g < warp * 8 + 8; g++) {
        float* row = sc + (size_t)g * MS;
        float m = -1e30f;
        for (int j = lane; j < cnt; j += 32) m = fmaxf(m, row[j]);
#pragma unroll
        for (int o = 16; o; o >>= 1) m = fmaxf(m, __shfl_xor_sync(0xFFFFFFFFu, m, o));
        float s = 0.f;
        for (int j = lane; j < cnt; j += 32) s += __expf(row[j] - m);
#pragma unroll
        for (int o = 16; o; o >>= 1) s += __shfl_xor_sync(0xFFFFFFFFu, s, o);
        float inv = 1.f / s;
        for (int j = lane; j < cnt; j += 32) row[j] = __expf(row[j] - m) * inv;
    }
}

// cross-attention output: grid (64 bh, 4 j-slices), atomic accumulate into outtok
__global__ void k_cross_out() {
    int bh = blockIdx.x, b = bh >> 3, h = bh & 7;
    int cnt = g_mcnt[b], start = g_mstart[b];
    if (cnt == 0) return;
    int sl = blockIdx.y;
    int lo = (int)(((long long)cnt * sl) >> 2);
    int hi = (int)(((long long)cnt * (sl + 1)) >> 2);
    if (lo >= hi) return;
    __shared__ float s_kv[32][64];
    __shared__ float s_cw[64][33];
    __shared__ int mid[32];
    int t = threadIdx.x;
    int tx = t & 15, ty = t >> 4;
    const float* sc = g_scores + (size_t)bh * 64 * MS;
    float acc[4][4] = {};
    for (int j0 = lo; j0 < hi; j0 += 32) {
        int nj = hi - j0; if (nj > 32) nj = 32;
        if (t < nj) mid[t] = g_mlist[start + j0 + t];
        __syncthreads();
        for (int i = t; i < nj * 64; i += 256) {
            int r = i >> 6, c = i & 63;
            s_kv[r][c] = g_vs[(size_t)mid[r] * DM + h * 64 + c];
        }
        for (int i = t; i < 64 * 32; i += 256) {
            int g = i >> 5, j = i & 31;
            s_cw[g][j] = (j < nj) ? sc[(size_t)g * MS + j0 + j] : 0.f;
        }
        __syncthreads();
        for (int j = 0; j < nj; j++) {
            float vvv[4];
#pragma unroll
            for (int jj = 0; jj < 4; jj++) vvv[jj] = s_kv[j][tx * 4 + jj];
#pragma unroll
            for (int i = 0; i < 4; i++) {
                float c = s_cw[ty * 4 + i][j];
#pragma unroll
                for (int jj = 0; jj < 4; jj++) acc[i][jj] = fmaf(c, vvv[jj], acc[i][jj]);
            }
        }
        __syncthreads();
    }
#pragma unroll
    for (int i = 0; i < 4; i++)
#pragma unroll
        for (int jj = 0; jj < 4; jj++)
            atomicAdd(&g_outtok[(size_t)bh * 4096 + (ty * 4 + i) * 64 + tx * 4 + jj], acc[i][jj]);
}

// P[b, h*64+g, c] = sum_d out_tok[b,h,g,d] * W_out[h*64+d, c], stored transposed bf16 hi/lo
__global__ void k_P(const float* __restrict__ Wout) {
    int bh = blockIdx.x, b = bh >> 3, h = bh & 7;
    int col0 = blockIdx.y * 64;
    __shared__ float s_a[64][65];
    __shared__ float s_b[64][64];
    int t = threadIdx.x;
    for (int i = t; i < 4096; i += 256) {
        int r = i >> 6, c = i & 63;
        s_a[r][c] = g_outtok[(size_t)bh * 4096 + i];
        s_b[r][c] = Wout[(size_t)(h * 64 + r) * DM + col0 + c];
    }
    __syncthreads();
    int tx = t & 15, ty = t >> 4;
    float acc[4][4] = {};
    for (int d = 0; d < 64; d++) {
        float av[4], bv[4];
#pragma unroll
        for (int i = 0; i < 4; i++) av[i] = s_a[ty * 4 + i][d];
#pragma unroll
        for (int j = 0; j < 4; j++) bv[j] = s_b[d][tx * 4 + j];
#pragma unroll
        for (int i = 0; i < 4; i++)
#pragma unroll
            for (int j = 0; j < 4; j++) acc[i][j] = fmaf(av[i], bv[j], acc[i][j]);
    }
#pragma unroll
    for (int i = 0; i < 4; i++)
#pragma unroll
        for (int j = 0; j < 4; j++) {
            int r = h * 64 + ty * 4 + i;       // k index of P
            int c = col0 + tx * 4 + j;         // output col
            __nv_bfloat16 hh, ll;
            bsplit(acc[i][j], hh, ll);
            g_Pthi[((size_t)b * DM + c) * DM + r] = hh;
            g_Ptlo[((size_t)b * DM + c) * DM + r] = ll;
        }
}

// out[n, :] = w[n, :] @ P[batch(n)] via mma.sync bf16x3, gathered rows, 3-stage pipeline
__global__ void __launch_bounds__(256, 2)
k_final_mma(float* __restrict__ out) {
    int b = blockIdx.z;
    int cnt = g_rowcnt[b];
    int r0 = blockIdx.y * 128;
    if (r0 >= cnt) return;
    int nr = cnt - r0; if (nr > 128) nr = 128;
    extern __shared__ char dynsmem[];
    uint32_t sb = smem_to_u32(dynsmem);
    __shared__ int rid[128];
    int t = threadIdx.x;
    int lane = t & 31, wid = t >> 5;
    int wm = (wid & 3) * 32, wn = (wid >> 2) * 64;
    int col0 = blockIdx.x * 128;
    int start = g_rowstart[b];
    if (t < 128) rid[t] = g_rowlist[start + r0 + (t < nr ? t : nr - 1)];
    __syncthreads();
    float acc[2][8][4] = {};
    int a_row = wm + (lane & 15);
    int a_u = lane >> 4;
    int b_row = wn + (lane & 7) + ((lane >> 4) << 3);
    int b_u = (lane >> 3) & 1;
    const __nv_bfloat16* Ph = g_Pthi + ((size_t)b * DM + col0) * DM;
    const __nv_bfloat16* Pl = g_Ptlo + ((size_t)b * DM + col0) * DM;

    auto load_slab = [&](int kc, int stg) {
        uint32_t sbase = sb + stg * STG_BYTES;
#pragma unroll
        for (int half = 0; half < 2; half++) {
            int idx = half * 256 + t;
            int r = idx >> 2, c = idx & 3;
            uint32_t o = SW64_((uint32_t)(r * 64 + c * 16));
            size_t offa = (size_t)rid[r] * DM + kc + c * 8;
            size_t offb = (size_t)r * DM + kc + c * 8;
            cp16(sbase + OFFS_AH + o, g_whi + offa);
            cp16(sbase + OFFS_AL + o, g_wlo + offa);
            cp16(sbase + OFFS_BH + o, Ph + offb);
            cp16(sbase + OFFS_BL + o, Pl + offb);
        }
        CP_COMMIT();
    };

    load_slab(0, 0);
    load_slab(KSLAB, 1);
#pragma unroll 1
    for (int ch = 0; ch < NSLAB; ch++) {
        if (ch + 2 < NSLAB) { load_slab((ch + 2) * KSLAB, (ch + 2) % 3); CP_WAIT2(); }
        else if (ch + 1 < NSLAB) { CP_WAIT1(); }
        else { CP_WAIT0(); }
        __syncthreads();
        uint32_t sbase = sb + (ch % 3) * STG_BYTES;
#pragma unroll
        for (int ks = 0; ks < 2; ks++) {
            uint32_t ah[2][4], al[2][4];
#pragma unroll
            for (int mt = 0; mt < 2; mt++) {
                uint32_t off = SW64_((uint32_t)((a_row + mt * 16) * 64 + ks * 32 + a_u * 16));
                ldsm4(ah[mt], sbase + OFFS_AH + off);
                ldsm4(al[mt], sbase + OFFS_AL + off);
            }
#pragma unroll
            for (int np = 0; np < 4; np++) {
                uint32_t bh[4], bl[4];
                uint32_t boff = SW64_((uint32_t)((b_row + np * 16) * 64 + ks * 32 + b_u * 16));
                ldsm4(bh, sbase + OFFS_BH + boff);
                ldsm4(bl, sbase + OFFS_BL + boff);
#pragma unroll
                for (int mt = 0; mt < 2; mt++) {
                    mma16816(acc[mt][np * 2 + 0], ah[mt], bh[0], bh[1]);
                    mma16816(acc[mt][np * 2 + 0], ah[mt], bl[0], bl[1]);
                    mma16816(acc[mt][np * 2 + 0], al[mt], bh[0], bh[1]);
                    mma16816(acc[mt][np * 2 + 1], ah[mt], bh[2], bh[3]);
                    mma16816(acc[mt][np * 2 + 1], ah[mt], bl[2], bl[3]);
                    mma16816(acc[mt][np * 2 + 1], al[mt], bh[2], bh[3]);
                }
            }
        }
        __syncthreads();
    }
    int g = lane >> 2, tig = lane & 3;
#pragma unroll
    for (int mt = 0; mt < 2; mt++)
#pragma unroll
        for (int nt = 0; nt < 8; nt++) {
            int ml = wm + mt * 16 + g;
            int c = col0 + wn + nt * 8 + tig * 2;
            if (ml < nr)
                *(float2*)(out + (size_t)rid[ml] * DM + c) =
                    make_float2(acc[mt][nt][0], acc[mt][nt][1]);
            if (ml + 8 < nr)
                *(float2*)(out + (size_t)rid[ml + 8] * DM + c) =
                    make_float2(acc[mt][nt][2], acc[mt][nt][3]);
        }
}

extern "C" void kernel_launch(void* const* d_in, const int* in_sizes, int n_in,
                              void* d_out, int out_size) {
    const float* x    = (const float*)d_in[0];
    const int*   bi   = (const int*)d_in[1];
    const float* son  = (const float*)d_in[2];
    const int*   sbi  = (const int*)d_in[3];
    const float* temp = (const float*)d_in[4];
    const float* Wfx  = (const float*)d_in[5];
    const float* bfx  = (const float*)d_in[6];
    const float* Wx   = (const float*)d_in[7];
    const float* bx   = (const float*)d_in[8];
    const float* Wsl  = (const float*)d_in[9];
    const float* bsl  = (const float*)d_in[10];
    const float* Wq   = (const float*)d_in[11];
    const float* bq   = (const float*)d_in[12];
    const float* Wk   = (const float*)d_in[13];
    const float* bk   = (const float*)d_in[14];
    const float* Wv   = (const float*)d_in[15];
    const float* bv   = (const float*)d_in[16];
    const float* Wck  = (const float*)d_in[17];
    const float* bck  = (const float*)d_in[18];
    const float* Wcv  = (const float*)d_in[19];
    const float* bcv  = (const float*)d_in[20];
    const float* Wout = (const float*)d_in[21];
    float* out = (float*)d_out;

    cudaFuncSetAttribute(k_gemm_mma, cudaFuncAttributeMaxDynamicSharedMemorySize, SMEM_MMA);
    cudaFuncSetAttribute(k_final_mma, cudaFuncAttributeMaxDynamicSharedMemorySize, SMEM_MMA);
    cudaFuncSetAttribute(k_qkvattn, cudaFuncAttributeMaxDynamicSharedMemorySize, QKV_SMEM);

    k_bcomb<<<1, 512>>>(bx, Wsl, bsl);
    k_cvt_x<<<8192, 256>>>(x);
    k_wcomb<<<dim3(512, 2), 256>>>(Wx, Wsl, Wfx);
    k_gemm_mma<<<dim3(8, 128), 256, SMEM_MMA>>>(bfx);
    k_zero<<<1024, 256>>>();
    k_count<<<80, 256>>>(bi, sbi);
    k_prefix<<<1, 1>>>();
    k_scatter<<<80, 256>>>(bi, sbi);
    k_softmax<<<NT, 256>>>(temp);
    k_tokens<<<dim3(64, 16), 256>>>();
    k_qkvattn<<<64, 256, QKV_SMEM>>>(Wq, bq, Wk, bk, Wv, bv);
    k_skv<<<dim3(512, 2), 256>>>(son, Wck, bck, Wcv, bcv);
    k_cross_score<<<dim3(64, 8), 256>>>();
    k_cross_soft<<<64, 256>>>();
    k_cross_out<<<dim3(64, 4), 256>>>();
    k_P<<<dim3(64, 8), 256>>>(Wout);
    k_final_mma<<<dim3(4, 128, 8), 256, SMEM_MMA>>>(out);
}

// round 11
// speedup vs baseline: 2.6481x; 1.0344x over previous
#include <cuda_runtime.h>
#include <cuda_bf16.h>
#include <cstdint>

#define NT 16384   // x rows
#define MS 4096    // sonata rows
#define NB 8       // batches
#define NH 8       // heads
#define DH 64      // head dim
#define NG 64      // slice groups
#define DM 512     // model dim
#define SCL 0.125f // D^-0.5

#define SW64_(o) ((o) ^ (((o) >> 3) & 0x30))

__device__ __forceinline__ uint32_t smem_to_u32(const void* p) {
    uint32_t a;
    asm("{ .reg .u64 tmp; cvta.to.shared.u64 tmp, %1; cvt.u32.u64 %0, tmp; }"
        : "=r"(a) : "l"(p));
    return a;
}
__device__ __forceinline__ void ldsm4(uint32_t a[4], uint32_t addr) {
    asm volatile("ldmatrix.sync.aligned.m8n8.x4.shared.b16 {%0,%1,%2,%3}, [%4];"
                 : "=r"(a[0]), "=r"(a[1]), "=r"(a[2]), "=r"(a[3]) : "r"(addr));
}
__device__ __forceinline__ void mma16816(float c[4], const uint32_t a[4],
                                         uint32_t b0, uint32_t b1) {
    asm volatile(
        "mma.sync.aligned.m16n8k16.row.col.f32.bf16.bf16.f32 "
        "{%0,%1,%2,%3}, {%4,%5,%6,%7}, {%8,%9}, {%0,%1,%2,%3};"
        : "+f"(c[0]), "+f"(c[1]), "+f"(c[2]), "+f"(c[3])
        : "r"(a[0]), "r"(a[1]), "r"(a[2]), "r"(a[3]), "r"(b0), "r"(b1));
}
__device__ __forceinline__ void cp16(uint32_t dst, const void* src) {
    asm volatile("cp.async.cg.shared.global [%0], [%1], 16;" :: "r"(dst), "l"(src));
}
#define CP_COMMIT() asm volatile("cp.async.commit_group;" ::: "memory")
#define CP_WAIT2() asm volatile("cp.async.wait_group 2;" ::: "memory")
#define CP_WAIT1() asm volatile("cp.async.wait_group 1;" ::: "memory")
#define CP_WAIT0() asm volatile("cp.async.wait_group 0;" ::: "memory")

__device__ __forceinline__ void bsplit(float v, __nv_bfloat16& h, __nv_bfloat16& l) {
    h = __float2bfloat16(v);
    l = __float2bfloat16(v - __bfloat162float(h));
}

// pipelined MMA smem: 3 stages x (AH 8K | AL 8K | BH 8K | BL 8K) = 96KB
#define STG_BYTES 32768
#define OFFS_AH 0
#define OFFS_AL 8192
#define OFFS_BH 16384
#define OFFS_BL 24576
#define SMEM_MMA (3 * STG_BYTES)
#define KSLAB 32
#define NSLAB (DM / KSLAB)

// fused qkv+attn smem: a[64][65] + q,k,v,s 4x[64][64]  (floats)
#define QKV_SMEM ((64 * 65 + 4 * 4096) * 4)

// ---------------- device scratch ----------------
__device__ float g_bcomb[DM];
__device__ float g_fx[(size_t)NT * DM];
__device__ float g_w[(size_t)NT * DM];
__device__ __nv_bfloat16 g_xhi[(size_t)NT * DM], g_xlo[(size_t)NT * DM];
__device__ __nv_bfloat16 g_Bthi[(size_t)2 * DM * DM], g_Btlo[(size_t)2 * DM * DM]; // [1024][512]
__device__ __nv_bfloat16 g_whi[(size_t)NT * DM], g_wlo[(size_t)NT * DM];
__device__ __nv_bfloat16 g_Pthi[(size_t)NB * DM * DM], g_Ptlo[(size_t)NB * DM * DM]; // [b][c][k]
__device__ float g_tokens[NB * NH * NG * DH];
__device__ float g_norms[NB * NH * NG];
__device__ float g_outtok[NB * NH * NG * DH];
__device__ float g_ks[(size_t)MS * DM];
__device__ float g_vs[(size_t)MS * DM];
__device__ float g_scores[(size_t)NB * NH * NG * MS];
__device__ int g_rowlist[NT], g_rowcnt[NB], g_rowstart[NB + 1], g_rowcur[NB];
__device__ int g_mlist[MS], g_mcnt[NB], g_mstart[NB + 1], g_mcur[NB];

// ---------------- setup kernels ----------------
__global__ void k_zero() {
    int i = blockIdx.x * 256 + threadIdx.x;
    if (i < NB * NH * NG * DH) g_tokens[i] = 0.f;
    if (i < NB * NH * NG) g_norms[i] = 0.f;
    if (i < NB) {
        g_rowcnt[i] = 0; g_mcnt[i] = 0;
        g_rowcur[i] = 0; g_mcur[i] = 0;
    }
}

__global__ void k_bcomb(const float* __restrict__ bx, const float* __restrict__ Wsl,
                        const float* __restrict__ bsl) {
    int o = threadIdx.x;  // 512
    int h = o >> 6, g = o & 63;
    float acc = bsl[g];
    for (int d = 0; d < 64; d++) acc = fmaf(bx[h * 64 + d], Wsl[d * 64 + g], acc);
    g_bcomb[o] = acc;
}

// x fp32 -> bf16 hi/lo split
__global__ void k_cvt_x(const float* __restrict__ x) {
    size_t i = (size_t)blockIdx.x * 256 + threadIdx.x;  // one float4 each
    float4 v = ((const float4*)x)[i];
    __nv_bfloat16 h0, h1, h2, h3, l0, l1, l2, l3;
    bsplit(v.x, h0, l0); bsplit(v.y, h1, l1);
    bsplit(v.z, h2, l2); bsplit(v.w, h3, l3);
    ((__nv_bfloat162*)g_xhi)[i * 2 + 0] = __halves2bfloat162(h0, h1);
    ((__nv_bfloat162*)g_xhi)[i * 2 + 1] = __halves2bfloat162(h2, h3);
    ((__nv_bfloat162*)g_xlo)[i * 2 + 0] = __halves2bfloat162(l0, l1);
    ((__nv_bfloat162*)g_xlo)[i * 2 + 1] = __halves2bfloat162(l2, l3);
}

// y==1: Bt rows 0..511 (transposed Wfx); y==0: Bt rows 512..1023 from Wcomb = Wx·Wsl
__global__ void k_wcomb(const float* __restrict__ Wx, const float* __restrict__ Wsl,
                        const float* __restrict__ Wfx) {
    int c = blockIdx.x;  // 0..511
    int t = threadIdx.x;
    if (blockIdx.y == 1) {
        for (int k = t; k < DM; k += 256) {
            __nv_bfloat16 h, l;
            bsplit(Wfx[(size_t)k * DM + c], h, l);
            g_Bthi[(size_t)c * DM + k] = h;
            g_Btlo[(size_t)c * DM + k] = l;
        }
        return;
    }
    __shared__ float s_sl[4096];
    for (int i = t; i < 4096; i += 256) s_sl[i] = Wsl[i];
    __syncthreads();
    for (int o = t; o < 512; o += 256) {
        int h = o >> 6, g = o & 63;
        const float* wxr = Wx + (size_t)c * DM + h * 64;
        float acc = 0.f;
        for (int d = 0; d < 64; d++) acc = fmaf(wxr[d], s_sl[d * 64 + g], acc);
        __nv_bfloat16 hh, ll;
        bsplit(acc, hh, ll);
        g_Bthi[(size_t)(DM + o) * DM + c] = hh;
        g_Btlo[(size_t)(DM + o) * DM + c] = ll;
    }
}

__global__ void k_count(const int* __restrict__ bi, const int* __restrict__ sbi) {
    int i = blockIdx.x * 256 + threadIdx.x;
    if (i < NT) atomicAdd(&g_rowcnt[bi[i]], 1);
    else if (i < NT + MS) atomicAdd(&g_mcnt[sbi[i - NT]], 1);
}

__global__ void k_prefix() {
    if (threadIdx.x == 0) {
        int s = 0;
        for (int b = 0; b < NB; b++) { g_rowstart[b] = s; s += g_rowcnt[b]; }
        g_rowstart[NB] = s;
        s = 0;
        for (int b = 0; b < NB; b++) { g_mstart[b] = s; s += g_mcnt[b]; }
        g_mstart[NB] = s;
    }
}

__global__ void k_scatter(const int* __restrict__ bi, const int* __restrict__ sbi) {
    int i = blockIdx.x * 256 + threadIdx.x;
    if (i < NT) {
        int b = bi[i];
        int p = atomicAdd(&g_rowcur[b], 1);
        g_rowlist[g_rowstart[b] + p] = i;
    } else if (i < NT + MS) {
        int j = i - NT;
        int b = sbi[j];
        int p = atomicAdd(&g_mcur[b], 1);
        g_mlist[g_mstart[b] + p] = j;
    }
}

// ---------------- front GEMM via mma.sync bf16x3, 3-stage pipeline, fused slice-softmax ----------------
__global__ void __launch_bounds__(256, 2)
k_gemm_mma(const float* __restrict__ bfx, const float* __restrict__ temp) {
    extern __shared__ char dynsmem[];
    uint32_t sb = smem_to_u32(dynsmem);
    int t = threadIdx.x;
    int lane = t & 31, wid = t >> 5;
    int wm = (wid & 3) * 32, wn = (wid >> 2) * 64;
    int row0 = blockIdx.y * 128, col0 = blockIdx.x * 128;
    float acc[2][8][4] = {};
    int a_row = wm + (lane & 15);
    int a_u = lane >> 4;
    int b_row = wn + (lane & 7) + ((lane >> 4) << 3);
    int b_u = (lane >> 3) & 1;

    auto load_slab = [&](int kc, int stg) {
        uint32_t sbase = sb + stg * STG_BYTES;
#pragma unroll
        for (int half = 0; half < 2; half++) {
            int idx = half * 256 + t;
            int r = idx >> 2, c = idx & 3;
            uint32_t o = SW64_((uint32_t)(r * 64 + c * 16));
            size_t offa = (size_t)(row0 + r) * DM + kc + c * 8;
            size_t offb = (size_t)(col0 + r) * DM + kc + c * 8;
            cp16(sbase + OFFS_AH + o, g_xhi + offa);
            cp16(sbase + OFFS_AL + o, g_xlo + offa);
            cp16(sbase + OFFS_BH + o, g_Bthi + offb);
            cp16(sbase + OFFS_BL + o, g_Btlo + offb);
        }
        CP_COMMIT();
    };

    load_slab(0, 0);
    load_slab(KSLAB, 1);
#pragma unroll 1
    for (int ch = 0; ch < NSLAB; ch++) {
        if (ch + 2 < NSLAB) { load_slab((ch + 2) * KSLAB, (ch + 2) % 3); CP_WAIT2(); }
        else if (ch + 1 < NSLAB) { CP_WAIT1(); }
        else { CP_WAIT0(); }
        __syncthreads();
        uint32_t sbase = sb + (ch % 3) * STG_BYTES;
#pragma unroll
        for (int ks = 0; ks < 2; ks++) {
            uint32_t ah[2][4], al[2][4];
#pragma unroll
            for (int mt = 0; mt < 2; mt++) {
                uint32_t off = SW64_((uint32_t)((a_row + mt * 16) * 64 + ks * 32 + a_u * 16));
                ldsm4(ah[mt], sbase + OFFS_AH + off);
                ldsm4(al[mt], sbase + OFFS_AL + off);
            }
#pragma unroll
            for (int np = 0; np < 4; np++) {
                uint32_t bh[4], bl[4];
                uint32_t boff = SW64_((uint32_t)((b_row + np * 16) * 64 + ks * 32 + b_u * 16));
                ldsm4(bh, sbase + OFFS_BH + boff);
                ldsm4(bl, sbase + OFFS_BL + boff);
#pragma unroll
                for (int mt = 0; mt < 2; mt++) {
                    mma16816(acc[mt][np * 2 + 0], ah[mt], bh[0], bh[1]);
                    mma16816(acc[mt][np * 2 + 0], ah[mt], bl[0], bl[1]);
                    mma16816(acc[mt][np * 2 + 0], al[mt], bh[0], bh[1]);
                    mma16816(acc[mt][np * 2 + 1], ah[mt], bh[2], bh[3]);
                    mma16816(acc[mt][np * 2 + 1], ah[mt], bl[2], bl[3]);
                    mma16816(acc[mt][np * 2 + 1], al[mt], bh[2], bh[3]);
                }
            }
        }
        __syncthreads();
    }
    int g = lane >> 2, tig = lane & 3;
    bool isfx = (col0 < DM);
    if (isfx) {
#pragma unroll
        for (int mt = 0; mt < 2; mt++)
#pragma unroll
            for (int nt = 0; nt < 8; nt++) {
                int r1 = row0 + wm + mt * 16 + g;
                int c = col0 + wn + nt * 8 + tig * 2;
                float b0v = bfx[c], b1v = bfx[c + 1];
                *(float2*)(g_fx + (size_t)r1 * DM + c) =
                    make_float2(acc[mt][nt][0] + b0v, acc[mt][nt][1] + b1v);
                *(float2*)(g_fx + (size_t)(r1 + 8) * DM + c) =
                    make_float2(acc[mt][nt][2] + b0v, acc[mt][nt][3] + b1v);
            }
    } else {
        // fused slice softmax: this warp's 64 cols == one head; each row's 64
        // logits live in the 4 lanes sharing g (tig 0..3), 16 values each.
        int cbase = col0 - DM;
        int h = (cbase + wn) >> 6;
        float it = 1.f / temp[h];
#pragma unroll
        for (int mt = 0; mt < 2; mt++)
#pragma unroll
            for (int half = 0; half < 2; half++) {
                int r1 = row0 + wm + mt * 16 + g + half * 8;
                float v[16];
#pragma unroll
                for (int nt = 0; nt < 8; nt++) {
                    int c = cbase + wn + nt * 8 + tig * 2;
                    v[nt * 2 + 0] = (acc[mt][nt][half * 2 + 0] + g_bcomb[c]) * it;
                    v[nt * 2 + 1] = (acc[mt][nt][half * 2 + 1] + g_bcomb[c + 1]) * it;
                }
                float m = v[0];
#pragma unroll
                for (int i = 1; i < 16; i++) m = fmaxf(m, v[i]);
                m = fmaxf(m, __shfl_xor_sync(0xFFFFFFFFu, m, 1));
                m = fmaxf(m, __shfl_xor_sync(0xFFFFFFFFu, m, 2));
                float s = 0.f;
#pragma unroll
                for (int i = 0; i < 16; i++) { v[i] = __expf(v[i] - m); s += v[i]; }
                s += __shfl_xor_sync(0xFFFFFFFFu, s, 1);
                s += __shfl_xor_sync(0xFFFFFFFFu, s, 2);
                float inv = 1.f / s;
#pragma unroll
                for (int nt = 0; nt < 8; nt++) {
                    int cw = cbase + wn + nt * 8 + tig * 2;
                    float w0 = v[nt * 2 + 0] * inv, w1 = v[nt * 2 + 1] * inv;
                    *(float2*)(g_w + (size_t)r1 * DM + cw) = make_float2(w0, w1);
                    __nv_bfloat16 h0, l0, h1, l1;
                    bsplit(w0, h0, l0); bsplit(w1, h1, l1);
                    *(__nv_bfloat162*)(g_whi + (size_t)r1 * DM + cw) = __halves2bfloat162(h0, h1);
                    *(__nv_bfloat162*)(g_wlo + (size_t)r1 * DM + cw) = __halves2bfloat162(l0, l1);
                }
            }
    }
}

// tokens[b,h,g,d] = sum_{n in b} w[n,h,g] * fx[n,h,d]; norms[b,h,g] = sum w
__global__ void k_tokens() {
    int bh = blockIdx.x;
    int b = bh >> 3, h = bh & 7;
    int cnt = g_rowcnt[b], start = g_rowstart[b];
    int c0 = (int)(((long long)cnt * blockIdx.y) >> 4);
    int c1 = (int)(((long long)cnt * (blockIdx.y + 1)) >> 4);
    int t = threadIdx.x;
    int tg = (t >> 4) * 4, td = (t & 15) * 4;
    float acc[4][4] = {};
    float nacc[4] = {};
    __shared__ float ws[16][64], fs[16][64];
    __shared__ int rid[16];
    for (int i0 = c0; i0 < c1; i0 += 16) {
        int nr = c1 - i0; if (nr > 16) nr = 16;
        if (t < nr) rid[t] = g_rowlist[start + i0 + t];
        __syncthreads();
        for (int idx = t; idx < nr * 64; idx += 256) {
            int r = idx >> 6, c = idx & 63;
            size_t off = (size_t)rid[r] * DM + h * 64 + c;
            ws[r][c] = g_w[off];
            fs[r][c] = g_fx[off];
        }
        __syncthreads();
        for (int r = 0; r < nr; r++) {
            float wv[4], fv[4];
#pragma unroll
            for (int i = 0; i < 4; i++) { wv[i] = ws[r][tg + i]; fv[i] = fs[r][td + i]; }
#pragma unroll
            for (int i = 0; i < 4; i++) {
                if (td == 0) nacc[i] += wv[i];
#pragma unroll
                for (int j = 0; j < 4; j++) acc[i][j] = fmaf(wv[i], fv[j], acc[i][j]);
            }
        }
        __syncthreads();
    }
    float* tok = g_tokens + (size_t)bh * NG * DH;
#pragma unroll
    for (int i = 0; i < 4; i++) {
#pragma unroll
        for (int j = 0; j < 4; j++) atomicAdd(&tok[(tg + i) * DH + td + j], acc[i][j]);
        if (td == 0) atomicAdd(&g_norms[bh * NG + tg + i], nacc[i]);
    }
}

// fused q/k/v projection + 64x64 self-attention per (b,h)
__global__ void k_qkvattn(const float* __restrict__ Wq, const float* __restrict__ bq,
                          const float* __restrict__ Wk, const float* __restrict__ bk,
                          const float* __restrict__ Wv, const float* __restrict__ bv) {
    int bh = blockIdx.x;
    extern __shared__ float fsm[];
    float* s_a = fsm;                 // [64][65]
    float* s_q = fsm + 64 * 65;
    float* s_k = s_q + 4096;
    float* s_v = s_k + 4096;
    float* s_s = s_v + 4096;          // W staging, then scores
    int t = threadIdx.x;
    for (int i = t; i < 4096; i += 256) {
        int g = i >> 6, d = i & 63;
        s_a[g * 65 + d] = g_tokens[(size_t)bh * 4096 + i] / (g_norms[bh * 64 + g] + 1e-5f);
    }
    int tx = t & 15, ty = t >> 4;
    const float* Ws[3] = {Wq, Wk, Wv};
    const float* bs[3] = {bq, bk, bv};
    float* outs[3] = {s_q, s_k, s_v};
#pragma unroll 1
    for (int p = 0; p < 3; p++) {
        for (int i = t; i < 4096; i += 256) s_s[i] = Ws[p][i];
        __syncthreads();
        float acc[4][4] = {};
        for (int k = 0; k < 64; k++) {
            float av[4], bv2[4];
#pragma unroll
            for (int i = 0; i < 4; i++) av[i] = s_a[(ty * 4 + i) * 65 + k];
#pragma unroll
            for (int j = 0; j < 4; j++) bv2[j] = s_s[k * 64 + tx * 4 + j];
#pragma unroll
            for (int i = 0; i < 4; i++)
#pragma unroll
                for (int j = 0; j < 4; j++) acc[i][j] = fmaf(av[i], bv2[j], acc[i][j]);
        }
#pragma unroll
        for (int i = 0; i < 4; i++)
#pragma unroll
            for (int j = 0; j < 4; j++)
                outs[p][(ty * 4 + i) * 64 + tx * 4 + j] = acc[i][j] + bs[p][tx * 4 + j];
        __syncthreads();
    }
    // scores = q k^T * SCL into s_s
    {
        float acc[4][4] = {};
        for (int d = 0; d < 64; d++) {
            float av[4], bv2[4];
#pragma unroll
            for (int i = 0; i < 4; i++) av[i] = s_q[(ty * 4 + i) * 64 + d];
#pragma unroll
            for (int j = 0; j < 4; j++) bv2[j] = s_k[(tx * 4 + j) * 64 + d];
#pragma unroll
            for (int i = 0; i < 4; i++)
#pragma unroll
                for (int j = 0; j < 4; j++) acc[i][j] = fmaf(av[i], bv2[j], acc[i][j]);
        }
#pragma unroll
        for (int i = 0; i < 4; i++)
#pragma unroll
            for (int j = 0; j < 4; j++)
                s_s[(ty * 4 + i) * 64 + tx * 4 + j] = acc[i][j] * SCL;
    }
    __syncthreads();
    if (t < 64) {
        float m = -1e30f;
        for (int j = 0; j < 64; j++) m = fmaxf(m, s_s[t * 64 + j]);
        float s = 0.f;
        for (int j = 0; j < 64; j++) { float e = __expf(s_s[t * 64 + j] - m); s_s[t * 64 + j] = e; s += e; }
        float inv = 1.f / s;
        for (int j = 0; j < 64; j++) s_s[t * 64 + j] *= inv;
    }
    __syncthreads();
    float acc[4][4] = {};
    for (int k2 = 0; k2 < 64; k2++) {
        float av[4], bv2[4];
#pragma unroll
        for (int i = 0; i < 4; i++) av[i] = s_s[(ty * 4 + i) * 64 + k2];
#pragma unroll
        for (int j = 0; j < 4; j++) bv2[j] = s_v[k2 * 64 + tx * 4 + j];
#pragma unroll
        for (int i = 0; i < 4; i++)
#pragma unroll
            for (int j = 0; j < 4; j++) acc[i][j] = fmaf(av[i], bv2[j], acc[i][j]);
    }
#pragma unroll
    for (int i = 0; i < 4; i++)
#pragma unroll
        for (int j = 0; j < 4; j++)
            g_outtok[(size_t)bh * 4096 + (ty * 4 + i) * 64 + tx * 4 + j] = acc[i][j];
}

// sonata ks/vs projection: [32768x64] @ [64x64] + bias
__global__ void k_skv(const float* __restrict__ son,
                      const float* __restrict__ Wck, const float* __restrict__ bck,
                      const float* __restrict__ Wcv, const float* __restrict__ bcv) {
    int rt = blockIdx.x;
    int sel = blockIdx.y;
    const float* W = sel ? Wcv : Wck;
    const float* bias = sel ? bcv : bck;
    float* dst = sel ? g_vs : g_ks;
    __shared__ float s_at[64][65];
    __shared__ float s_b[64][64];
    int t = threadIdx.x;
    size_t base = (size_t)rt * 64 * 64;
    for (int i = t; i < 4096; i += 256) {
        s_at[i & 63][i >> 6] = son[base + i];
        s_b[i >> 6][i & 63] = W[i];
    }
    __syncthreads();
    int tx = t & 15, ty = t >> 4;
    float acc[4][4] = {};
    for (int k = 0; k < 64; k++) {
        float av[4], bv2[4];
#pragma unroll
        for (int i = 0; i < 4; i++) av[i] = s_at[k][ty * 4 + i];
#pragma unroll
        for (int j = 0; j < 4; j++) bv2[j] = s_b[k][tx * 4 + j];
#pragma unroll
        for (int i = 0; i < 4; i++)
#pragma unroll
            for (int j = 0; j < 4; j++) acc[i][j] = fmaf(av[i], bv2[j], acc[i][j]);
    }
#pragma unroll
    for (int i = 0; i < 4; i++)
#pragma unroll
        for (int j = 0; j < 4; j++)
            dst[base + (size_t)(ty * 4 + i) * 64 + tx * 4 + j] = acc[i][j] + bias[tx * 4 + j];
}

// cross-attention scores: grid (64 bh, 8 j-slices)
__global__ void k_cross_score() {
    int bh = blockIdx.x, b = bh >> 3, h = bh & 7;
    int cnt = g_mcnt[b], start = g_mstart[b];
    if (cnt == 0) return;
    int sl = blockIdx.y;
    int lo = (int)(((long long)cnt * sl) >> 3);
    int hi = (int)(((long long)cnt * (sl + 1)) >> 3);
    if (lo >= hi) return;
    __shared__ float s_q[64][65];
    __shared__ float s_kv[32][64];
    __shared__ int mid[32];
    int t = threadIdx.x;
    for (int i = t; i < 4096; i += 256) s_q[i >> 6][i & 63] = g_outtok[(size_t)bh * 4096 + i];
    __syncthreads();
    float* sc = g_scores + (size_t)bh * 64 * MS;
    for (int j0 = lo; j0 < hi; j0 += 32) {
        int nj = hi - j0; if (nj > 32) nj = 32;
        if (t < nj) mid[t] = g_mlist[start + j0 + t];
        __syncthreads();
        for (int i = t; i < nj * 64; i += 256) {
            int r = i >> 6, c = i & 63;
            s_kv[r][c] = g_ks[(size_t)mid[r] * DM + h * 64 + c];
        }
        __syncthreads();
        int g = t & 63, jp = t >> 6;
        for (int j = jp; j < nj; j += 4) {
            float a = 0.f;
#pragma unroll 16
            for (int d = 0; d < 64; d++) a = fmaf(s_q[g][d], s_kv[j][d], a);
            sc[(size_t)g * MS + j0 + j] = a * SCL;
        }
        __syncthreads();
    }
}

// cross-attention softmax: grid (64 bh), warp handles 8 rows
__global__ void k_cross_soft() {
    int bh = blockIdx.x, b = bh >> 3;
    int cnt = g_mcnt[b];
    if (cnt == 0) return;
    float* sc = g_scores + (size_t)bh * 64 * MS;
    int warp = threadIdx.x >> 5, lane = threadIdx.x & 31;
    for (int g = warp * 8; g < warp * 8 + 8; g++) {
        float* row = sc + (size_t)g * MS;
        float m = -1e30f;
        for (int j = lane; j < cnt; j += 32) m = fmaxf(m, row[j]);
#pragma unroll
        for (int o = 16; o; o >>= 1) m = fmaxf(m, __shfl_xor_sync(0xFFFFFFFFu, m, o));
        float s = 0.f;
        for (int j = lane; j < cnt; j += 32) s += __expf(row[j] - m);
#pragma unroll
        for (int o = 16; o; o >>= 1) s += __shfl_xor_sync(0xFFFFFFFFu, s, o);
        float inv = 1.f / s;
        for (int j = lane; j < cnt; j += 32) row[j] = __expf(row[j] - m) * inv;
    }
}

// cross-attention output: grid (64 bh, 4 j-slices), atomic accumulate into outtok
__global__ void k_cross_out() {
    int bh = blockIdx.x, b = bh >> 3, h = bh & 7;
    int cnt = g_mcnt[b], start = g_mstart[b];
    if (cnt == 0) return;
    int sl = blockIdx.y;
    int lo = (int)(((long long)cnt * sl) >> 2);
    int hi = (int)(((long long)cnt * (sl + 1)) >> 2);
    if (lo >= hi) return;
    __shared__ float s_kv[32][64];
    __shared__ float s_cw[64][33];
    __shared__ int mid[32];
    int t = threadIdx.x;
    int tx = t & 15, ty = t >> 4;
    const float* sc = g_scores + (size_t)bh * 64 * MS;
    float acc[4][4] = {};
    for (int j0 = lo; j0 < hi; j0 += 32) {
        int nj = hi - j0; if (nj > 32) nj = 32;
        if (t < nj) mid[t] = g_mlist[start + j0 + t];
        __syncthreads();
        for (int i = t; i < nj * 64; i += 256) {
            int r = i >> 6, c = i & 63;
            s_kv[r][c] = g_vs[(size_t)mid[r] * DM + h * 64 + c];
        }
        for (int i = t; i < 64 * 32; i += 256) {
            int g = i >> 5, j = i & 31;
            s_cw[g][j] = (j < nj) ? sc[(size_t)g * MS + j0 + j] : 0.f;
        }
        __syncthreads();
        for (int j = 0; j < nj; j++) {
            float vvv[4];
#pragma unroll
            for (int jj = 0; jj < 4; jj++) vvv[jj] = s_kv[j][tx * 4 + jj];
#pragma unroll
            for (int i = 0; i < 4; i++) {
                float c = s_cw[ty * 4 + i][j];
#pragma unroll
                for (int jj = 0; jj < 4; jj++) acc[i][jj] = fmaf(c, vvv[jj], acc[i][jj]);
            }
        }
        __syncthreads();
    }
#pragma unroll
    for (int i = 0; i < 4; i++)
#pragma unroll
        for (int jj = 0; jj < 4; jj++)
            atomicAdd(&g_outtok[(size_t)bh * 4096 + (ty * 4 + i) * 64 + tx * 4 + jj], acc[i][jj]);
}

// P[b, h*64+g, c] = sum_d out_tok[b,h,g,d] * W_out[h*64+d, c], stored transposed bf16 hi/lo
__global__ void k_P(const float* __restrict__ Wout) {
    int bh = blockIdx.x, b = bh >> 3, h = bh & 7;
    int col0 = blockIdx.y * 64;
    __shared__ float s_a[64][65];
    __shared__ float s_b[64][64];
    int t = threadIdx.x;
    for (int i = t; i < 4096; i += 256) {
        int r = i >> 6, c = i & 63;
        s_a[r][c] = g_outtok[(size_t)bh * 4096 + i];
        s_b[r][c] = Wout[(size_t)(h * 64 + r) * DM + col0 + c];
    }
    __syncthreads();
    int tx = t & 15, ty = t >> 4;
    float acc[4][4] = {};
    for (int d = 0; d < 64; d++) {
        float av[4], bv[4];
#pragma unroll
        for (int i = 0; i < 4; i++) av[i] = s_a[ty * 4 + i][d];
#pragma unroll
        for (int j = 0; j < 4; j++) bv[j] = s_b[d][tx * 4 + j];
#pragma unroll
        for (int i = 0; i < 4; i++)
#pragma unroll
            for (int j = 0; j < 4; j++) acc[i][j] = fmaf(av[i], bv[j], acc[i][j]);
    }
#pragma unroll
    for (int i = 0; i < 4; i++)
#pragma unroll
        for (int j = 0; j < 4; j++) {
            int r = h * 64 + ty * 4 + i;       // k index of P
            int c = col0 + tx * 4 + j;         // output col
            __nv_bfloat16 hh, ll;
            bsplit(acc[i][j], hh, ll);
            g_Pthi[((size_t)b * DM + c) * DM + r] = hh;
            g_Ptlo[((size_t)b * DM + c) * DM + r] = ll;
        }
}

// out[n, :] = w[n, :] @ P[batch(n)] via mma.sync bf16x3, gathered rows, 3-stage pipeline
__global__ void __launch_bounds__(256, 2)
k_final_mma(float* __restrict__ out) {
    int b = blockIdx.z;
    int cnt = g_rowcnt[b];
    int r0 = blockIdx.y * 128;
    if (r0 >= cnt) return;
    int nr = cnt - r0; if (nr > 128) nr = 128;
    extern __shared__ char dynsmem[];
    uint32_t sb = smem_to_u32(dynsmem);
    __shared__ int rid[128];
    int t = threadIdx.x;
    int lane = t & 31, wid = t >> 5;
    int wm = (wid & 3) * 32, wn = (wid >> 2) * 64;
    int col0 = blockIdx.x * 128;
    int start = g_rowstart[b];
    if (t < 128) rid[t] = g_rowlist[start + r0 + (t < nr ? t : nr - 1)];
    __syncthreads();
    float acc[2][8][4] = {};
    int a_row = wm + (lane & 15);
    int a_u = lane >> 4;
    int b_row = wn + (lane & 7) + ((lane >> 4) << 3);
    int b_u = (lane >> 3) & 1;
    const __nv_bfloat16* Ph = g_Pthi + ((size_t)b * DM + col0) * DM;
    const __nv_bfloat16* Pl = g_Ptlo + ((size_t)b * DM + col0) * DM;

    auto load_slab = [&](int kc, int stg) {
        uint32_t sbase = sb + stg * STG_BYTES;
#pragma unroll
        for (int half = 0; half < 2; half++) {
            int idx = half * 256 + t;
            int r = idx >> 2, c = idx & 3;
            uint32_t o = SW64_((uint32_t)(r * 64 + c * 16));
            size_t offa = (size_t)rid[r] * DM + kc + c * 8;
            size_t offb = (size_t)r * DM + kc + c * 8;
            cp16(sbase + OFFS_AH + o, g_whi + offa);
            cp16(sbase + OFFS_AL + o, g_wlo + offa);
            cp16(sbase + OFFS_BH + o, Ph + offb);
            cp16(sbase + OFFS_BL + o, Pl + offb);
        }
        CP_COMMIT();
    };

    load_slab(0, 0);
    load_slab(KSLAB, 1);
#pragma unroll 1
    for (int ch = 0; ch < NSLAB; ch++) {
        if (ch + 2 < NSLAB) { load_slab((ch + 2) * KSLAB, (ch + 2) % 3); CP_WAIT2(); }
        else if (ch + 1 < NSLAB) { CP_WAIT1(); }
        else { CP_WAIT0(); }
        __syncthreads();
        uint32_t sbase = sb + (ch % 3) * STG_BYTES;
#pragma unroll
        for (int ks = 0; ks < 2; ks++) {
            uint32_t ah[2][4], al[2][4];
#pragma unroll
            for (int mt = 0; mt < 2; mt++) {
                uint32_t off = SW64_((uint32_t)((a_row + mt * 16) * 64 + ks * 32 + a_u * 16));
                ldsm4(ah[mt], sbase + OFFS_AH + off);
                ldsm4(al[mt], sbase + OFFS_AL + off);
            }
#pragma unroll
            for (int np = 0; np < 4; np++) {
                uint32_t bh[4], bl[4];
                uint32_t boff = SW64_((uint32_t)((b_row + np * 16) * 64 + ks * 32 + b_u * 16));
                ldsm4(bh, sbase + OFFS_BH + boff);
                ldsm4(bl, sbase + OFFS_BL + boff);
#pragma unroll
                for (int mt = 0; mt < 2; mt++) {
                    mma16816(acc[mt][np * 2 + 0], ah[mt], bh[0], bh[1]);
                    mma16816(acc[mt][np * 2 + 0], ah[mt], bl[0], bl[1]);
                    mma16816(acc[mt][np * 2 + 0], al[mt], bh[0], bh[1]);
                    mma16816(acc[mt][np * 2 + 1], ah[mt], bh[2], bh[3]);
                    mma16816(acc[mt][np * 2 + 1], ah[mt], bl[2], bl[3]);
                    mma16816(acc[mt][np * 2 + 1], al[mt], bh[2], bh[3]);
                }
            }
        }
        __syncthreads();
    }
    int g = lane >> 2, tig = lane & 3;
#pragma unroll
    for (int mt = 0; mt < 2; mt++)
#pragma unroll
        for (int nt = 0; nt < 8; nt++) {
            int ml = wm + mt * 16 + g;
            int c = col0 + wn + nt * 8 + tig * 2;
            if (ml < nr)
                *(float2*)(out + (size_t)rid[ml] * DM + c) =
                    make_float2(acc[mt][nt][0], acc[mt][nt][1]);
            if (ml + 8 < nr)
                *(float2*)(out + (size_t)rid[ml + 8] * DM + c) =
                    make_float2(acc[mt][nt][2], acc[mt][nt][3]);
        }
}

extern "C" void kernel_launch(void* const* d_in, const int* in_sizes, int n_in,
                              void* d_out, int out_size) {
    const float* x    = (const float*)d_in[0];
    const int*   bi   = (const int*)d_in[1];
    const float* son  = (const float*)d_in[2];
    const int*   sbi  = (const int*)d_in[3];
    const float* temp = (const float*)d_in[4];
    const float* Wfx  = (const float*)d_in[5];
    const float* bfx  = (const float*)d_in[6];
    const float* Wx   = (const float*)d_in[7];
    const float* bx   = (const float*)d_in[8];
    const float* Wsl  = (const float*)d_in[9];
    const float* bsl  = (const float*)d_in[10];
    const float* Wq   = (const float*)d_in[11];
    const float* bq   = (const float*)d_in[12];
    const float* Wk   = (const float*)d_in[13];
    const float* bk   = (const float*)d_in[14];
    const float* Wv   = (const float*)d_in[15];
    const float* bv   = (const float*)d_in[16];
    const float* Wck  = (const float*)d_in[17];
    const float* bck  = (const float*)d_in[18];
    const float* Wcv  = (const float*)d_in[19];
    const float* bcv  = (const float*)d_in[20];
    const float* Wout = (const float*)d_in[21];
    float* out = (float*)d_out;

    cudaFuncSetAttribute(k_gemm_mma, cudaFuncAttributeMaxDynamicSharedMemorySize, SMEM_MMA);
    cudaFuncSetAttribute(k_final_mma, cudaFuncAttributeMaxDynamicSharedMemorySize, SMEM_MMA);
    cudaFuncSetAttribute(k_qkvattn, cudaFuncAttributeMaxDynamicSharedMemorySize, QKV_SMEM);

    k_bcomb<<<1, 512>>>(bx, Wsl, bsl);
    k_cvt_x<<<8192, 256>>>(x);
    k_wcomb<<<dim3(512, 2), 256>>>(Wx, Wsl, Wfx);
    k_gemm_mma<<<dim3(8, 128), 256, SMEM_MMA>>>(bfx, temp);
    k_zero<<<1024, 256>>>();
    k_count<<<80, 256>>>(bi, sbi);
    k_prefix<<<1, 1>>>();
    k_scatter<<<80, 256>>>(bi, sbi);
    k_tokens<<<dim3(64, 16), 256>>>();
    k_qkvattn<<<64, 256, QKV_SMEM>>>(Wq, bq, Wk, bk, Wv, bv);
    k_skv<<<dim3(512, 2), 256>>>(son, Wck, bck, Wcv, bcv);
    k_cross_score<<<dim3(64, 8), 256>>>();
    k_cross_soft<<<64, 256>>>();
    k_cross_out<<<dim3(64, 4), 256>>>();
    k_P<<<dim3(64, 8), 256>>>(Wout);
    k_final_mma<<<dim3(4, 128, 8), 256, SMEM_MMA>>>(out);
}

// round 12
// speedup vs baseline: 2.6775x; 1.0111x over previous
#include <cuda_runtime.h>
#include <cuda_bf16.h>
#include <cstdint>

#define NT 16384   // x rows
#define MS 4096    // sonata rows
#define NB 8       // batches
#define NH 8       // heads
#define DH 64      // head dim
#define NG 64      // slice groups
#define DM 512     // model dim
#define SCL 0.125f // D^-0.5

#define SW64_(o) ((o) ^ (((o) >> 3) & 0x30))

__device__ __forceinline__ uint32_t smem_to_u32(const void* p) {
    uint32_t a;
    asm("{ .reg .u64 tmp; cvta.to.shared.u64 tmp, %1; cvt.u32.u64 %0, tmp; }"
        : "=r"(a) : "l"(p));
    return a;
}
__device__ __forceinline__ void ldsm4(uint32_t a[4], uint32_t addr) {
    asm volatile("ldmatrix.sync.aligned.m8n8.x4.shared.b16 {%0,%1,%2,%3}, [%4];"
                 : "=r"(a[0]), "=r"(a[1]), "=r"(a[2]), "=r"(a[3]) : "r"(addr));
}
__device__ __forceinline__ void mma16816(float c[4], const uint32_t a[4],
                                         uint32_t b0, uint32_t b1) {
    asm volatile(
        "mma.sync.aligned.m16n8k16.row.col.f32.bf16.bf16.f32 "
        "{%0,%1,%2,%3}, {%4,%5,%6,%7}, {%8,%9}, {%0,%1,%2,%3};"
        : "+f"(c[0]), "+f"(c[1]), "+f"(c[2]), "+f"(c[3])
        : "r"(a[0]), "r"(a[1]), "r"(a[2]), "r"(a[3]), "r"(b0), "r"(b1));
}
__device__ __forceinline__ void cp16(uint32_t dst, const void* src) {
    asm volatile("cp.async.cg.shared.global [%0], [%1], 16;" :: "r"(dst), "l"(src));
}
#define CP_COMMIT() asm volatile("cp.async.commit_group;" ::: "memory")
#define CP_WAIT2() asm volatile("cp.async.wait_group 2;" ::: "memory")
#define CP_WAIT1() asm volatile("cp.async.wait_group 1;" ::: "memory")
#define CP_WAIT0() asm volatile("cp.async.wait_group 0;" ::: "memory")

__device__ __forceinline__ void bsplit(float v, __nv_bfloat16& h, __nv_bfloat16& l) {
    h = __float2bfloat16(v);
    l = __float2bfloat16(v - __bfloat162float(h));
}

// pipelined MMA smem: 3 stages x (AH 8K | AL 8K | BH 8K | BL 8K) = 96KB
#define STG_BYTES 32768
#define OFFS_AH 0
#define OFFS_AL 8192
#define OFFS_BH 16384
#define OFFS_BL 24576
#define SMEM_MMA (3 * STG_BYTES)
#define KSLAB 32
#define NSLAB (DM / KSLAB)

// fused qkv+attn smem: a[64][65] + q,k,v,s 4x[64][64]  (floats)
#define QKV_SMEM ((64 * 65 + 4 * 4096) * 4)

// ---------------- device scratch ----------------
__device__ float g_bcomb[DM];
__device__ float g_fx[(size_t)NT * DM];
__device__ float g_w[(size_t)NT * DM];
__device__ __nv_bfloat16 g_xhi[(size_t)NT * DM], g_xlo[(size_t)NT * DM];
__device__ __nv_bfloat16 g_Bthi[(size_t)2 * DM * DM], g_Btlo[(size_t)2 * DM * DM]; // [1024][512]
__device__ __nv_bfloat16 g_whi[(size_t)NT * DM], g_wlo[(size_t)NT * DM];
__device__ __nv_bfloat16 g_Pthi[(size_t)NB * DM * DM], g_Ptlo[(size_t)NB * DM * DM]; // [b][c][k]
__device__ float g_tokens[NB * NH * NG * DH];
__device__ float g_norms[NB * NH * NG];
__device__ float g_outtok[NB * NH * NG * DH];
__device__ float g_ks[(size_t)MS * DM];
__device__ float g_vs[(size_t)MS * DM];
__device__ float g_scores[(size_t)NB * NH * NG * MS];
__device__ int g_rowlist[NT], g_rowcnt[NB], g_rowstart[NB + 1], g_rowcur[NB];
__device__ int g_mlist[MS], g_mcnt[NB], g_mstart[NB + 1], g_mcur[NB];

// ---------------- setup kernels ----------------
__global__ void k_zero() {
    int i = blockIdx.x * 256 + threadIdx.x;
    if (i < NB * NH * NG * DH) g_tokens[i] = 0.f;
    if (i < NB * NH * NG) g_norms[i] = 0.f;
    if (i < NB) {
        g_rowcnt[i] = 0; g_mcnt[i] = 0;
        g_rowcur[i] = 0; g_mcur[i] = 0;
    }
}

__global__ void k_bcomb(const float* __restrict__ bx, const float* __restrict__ Wsl,
                        const float* __restrict__ bsl) {
    int o = threadIdx.x;  // 512
    int h = o >> 6, g = o & 63;
    float acc = bsl[g];
    for (int d = 0; d < 64; d++) acc = fmaf(bx[h * 64 + d], Wsl[d * 64 + g], acc);
    g_bcomb[o] = acc;
}

// x fp32 -> bf16 hi/lo split
__global__ void k_cvt_x(const float* __restrict__ x) {
    size_t i = (size_t)blockIdx.x * 256 + threadIdx.x;  // one float4 each
    float4 v = ((const float4*)x)[i];
    __nv_bfloat16 h0, h1, h2, h3, l0, l1, l2, l3;
    bsplit(v.x, h0, l0); bsplit(v.y, h1, l1);
    bsplit(v.z, h2, l2); bsplit(v.w, h3, l3);
    ((__nv_bfloat162*)g_xhi)[i * 2 + 0] = __halves2bfloat162(h0, h1);
    ((__nv_bfloat162*)g_xhi)[i * 2 + 1] = __halves2bfloat162(h2, h3);
    ((__nv_bfloat162*)g_xlo)[i * 2 + 0] = __halves2bfloat162(l0, l1);
    ((__nv_bfloat162*)g_xlo)[i * 2 + 1] = __halves2bfloat162(l2, l3);
}

// y==1: Bt rows 0..511 (transposed Wfx); y==0: Bt rows 512..1023 from Wcomb = Wx·Wsl
__global__ void k_wcomb(const float* __restrict__ Wx, const float* __restrict__ Wsl,
                        const float* __restrict__ Wfx) {
    int c = blockIdx.x;  // 0..511
    int t = threadIdx.x;
    if (blockIdx.y == 1) {
        for (int k = t; k < DM; k += 256) {
            __nv_bfloat16 h, l;
            bsplit(Wfx[(size_t)k * DM + c], h, l);
            g_Bthi[(size_t)c * DM + k] = h;
            g_Btlo[(size_t)c * DM + k] = l;
        }
        return;
    }
    __shared__ float s_sl[4096];
    for (int i = t; i < 4096; i += 256) s_sl[i] = Wsl[i];
    __syncthreads();
    for (int o = t; o < 512; o += 256) {
        int h = o >> 6, g = o & 63;
        const float* wxr = Wx + (size_t)c * DM + h * 64;
        float acc = 0.f;
        for (int d = 0; d < 64; d++) acc = fmaf(wxr[d], s_sl[d * 64 + g], acc);
        __nv_bfloat16 hh, ll;
        bsplit(acc, hh, ll);
        g_Bthi[(size_t)(DM + o) * DM + c] = hh;
        g_Btlo[(size_t)(DM + o) * DM + c] = ll;
    }
}

__global__ void k_count(const int* __restrict__ bi, const int* __restrict__ sbi) {
    int i = blockIdx.x * 256 + threadIdx.x;
    if (i < NT) atomicAdd(&g_rowcnt[bi[i]], 1);
    else if (i < NT + MS) atomicAdd(&g_mcnt[sbi[i - NT]], 1);
}

__global__ void k_prefix() {
    if (threadIdx.x == 0) {
        int s = 0;
        for (int b = 0; b < NB; b++) { g_rowstart[b] = s; s += g_rowcnt[b]; }
        g_rowstart[NB] = s;
        s = 0;
        for (int b = 0; b < NB; b++) { g_mstart[b] = s; s += g_mcnt[b]; }
        g_mstart[NB] = s;
    }
}

__global__ void k_scatter(const int* __restrict__ bi, const int* __restrict__ sbi) {
    int i = blockIdx.x * 256 + threadIdx.x;
    if (i < NT) {
        int b = bi[i];
        int p = atomicAdd(&g_rowcur[b], 1);
        g_rowlist[g_rowstart[b] + p] = i;
    } else if (i < NT + MS) {
        int j = i - NT;
        int b = sbi[j];
        int p = atomicAdd(&g_mcur[b], 1);
        g_mlist[g_mstart[b] + p] = j;
    }
}

// ---------------- front GEMM via mma.sync bf16x3, 3-stage pipeline, fused slice-softmax ----------------
__global__ void __launch_bounds__(256, 2)
k_gemm_mma(const float* __restrict__ bfx, const float* __restrict__ temp) {
    extern __shared__ char dynsmem[];
    uint32_t sb = smem_to_u32(dynsmem);
    int t = threadIdx.x;
    int lane = t & 31, wid = t >> 5;
    int wm = (wid & 3) * 32, wn = (wid >> 2) * 64;
    int row0 = blockIdx.y * 128, col0 = blockIdx.x * 128;
    float acc[2][8][4] = {};
    int a_row = wm + (lane & 15);
    int a_u = lane >> 4;
    int b_row = wn + (lane & 7) + ((lane >> 4) << 3);
    int b_u = (lane >> 3) & 1;

    auto load_slab = [&](int kc, int stg) {
        uint32_t sbase = sb + stg * STG_BYTES;
#pragma unroll
        for (int half = 0; half < 2; half++) {
            int idx = half * 256 + t;
            int r = idx >> 2, c = idx & 3;
            uint32_t o = SW64_((uint32_t)(r * 64 + c * 16));
            size_t offa = (size_t)(row0 + r) * DM + kc + c * 8;
            size_t offb = (size_t)(col0 + r) * DM + kc + c * 8;
            cp16(sbase + OFFS_AH + o, g_xhi + offa);
            cp16(sbase + OFFS_AL + o, g_xlo + offa);
            cp16(sbase + OFFS_BH + o, g_Bthi + offb);
            cp16(sbase + OFFS_BL + o, g_Btlo + offb);
        }
        CP_COMMIT();
    };

    load_slab(0, 0);
    load_slab(KSLAB, 1);
#pragma unroll 1
    for (int ch = 0; ch < NSLAB; ch++) {
        if (ch + 2 < NSLAB) { load_slab((ch + 2) * KSLAB, (ch + 2) % 3); CP_WAIT2(); }
        else if (ch + 1 < NSLAB) { CP_WAIT1(); }
        else { CP_WAIT0(); }
        __syncthreads();
        uint32_t sbase = sb + (ch % 3) * STG_BYTES;
#pragma unroll
        for (int ks = 0; ks < 2; ks++) {
            uint32_t ah[2][4], al[2][4];
#pragma unroll
            for (int mt = 0; mt < 2; mt++) {
                uint32_t off = SW64_((uint32_t)((a_row + mt * 16) * 64 + ks * 32 + a_u * 16));
                ldsm4(ah[mt], sbase + OFFS_AH + off);
                ldsm4(al[mt], sbase + OFFS_AL + off);
            }
#pragma unroll
            for (int np = 0; np < 4; np++) {
                uint32_t bh[4], bl[4];
                uint32_t boff = SW64_((uint32_t)((b_row + np * 16) * 64 + ks * 32 + b_u * 16));
                ldsm4(bh, sbase + OFFS_BH + boff);
                ldsm4(bl, sbase + OFFS_BL + boff);
#pragma unroll
                for (int mt = 0; mt < 2; mt++) {
                    mma16816(acc[mt][np * 2 + 0], ah[mt], bh[0], bh[1]);
                    mma16816(acc[mt][np * 2 + 0], ah[mt], bl[0], bl[1]);
                    mma16816(acc[mt][np * 2 + 0], al[mt], bh[0], bh[1]);
                    mma16816(acc[mt][np * 2 + 1], ah[mt], bh[2], bh[3]);
                    mma16816(acc[mt][np * 2 + 1], ah[mt], bl[2], bl[3]);
                    mma16816(acc[mt][np * 2 + 1], al[mt], bh[2], bh[3]);
                }
            }
        }
        __syncthreads();
    }
    int g = lane >> 2, tig = lane & 3;
    bool isfx = (col0 < DM);
    if (isfx) {
#pragma unroll
        for (int mt = 0; mt < 2; mt++)
#pragma unroll
            for (int nt = 0; nt < 8; nt++) {
                int r1 = row0 + wm + mt * 16 + g;
                int c = col0 + wn + nt * 8 + tig * 2;
                float b0v = bfx[c], b1v = bfx[c + 1];
                *(float2*)(g_fx + (size_t)r1 * DM + c) =
                    make_float2(acc[mt][nt][0] + b0v, acc[mt][nt][1] + b1v);
                *(float2*)(g_fx + (size_t)(r1 + 8) * DM + c) =
                    make_float2(acc[mt][nt][2] + b0v, acc[mt][nt][3] + b1v);
            }
    } else {
        // fused slice softmax: this warp's 64 cols == one head; each row's 64
        // logits live in the 4 lanes sharing g (tig 0..3), 16 values each.
        int cbase = col0 - DM;
        int h = (cbase + wn) >> 6;
        float it = 1.f / temp[h];
#pragma unroll
        for (int mt = 0; mt < 2; mt++)
#pragma unroll
            for (int half = 0; half < 2; half++) {
                int r1 = row0 + wm + mt * 16 + g + half * 8;
                float v[16];
#pragma unroll
                for (int nt = 0; nt < 8; nt++) {
                    int c = cbase + wn + nt * 8 + tig * 2;
                    v[nt * 2 + 0] = (acc[mt][nt][half * 2 + 0] + g_bcomb[c]) * it;
                    v[nt * 2 + 1] = (acc[mt][nt][half * 2 + 1] + g_bcomb[c + 1]) * it;
                }
                float m = v[0];
#pragma unroll
                for (int i = 1; i < 16; i++) m = fmaxf(m, v[i]);
                m = fmaxf(m, __shfl_xor_sync(0xFFFFFFFFu, m, 1));
                m = fmaxf(m, __shfl_xor_sync(0xFFFFFFFFu, m, 2));
                float s = 0.f;
#pragma unroll
                for (int i = 0; i < 16; i++) { v[i] = __expf(v[i] - m); s += v[i]; }
                s += __shfl_xor_sync(0xFFFFFFFFu, s, 1);
                s += __shfl_xor_sync(0xFFFFFFFFu, s, 2);
                float inv = 1.f / s;
#pragma unroll
                for (int nt = 0; nt < 8; nt++) {
                    int cw = cbase + wn + nt * 8 + tig * 2;
                    float w0 = v[nt * 2 + 0] * inv, w1 = v[nt * 2 + 1] * inv;
                    *(float2*)(g_w + (size_t)r1 * DM + cw) = make_float2(w0, w1);
                    __nv_bfloat16 h0, l0, h1, l1;
                    bsplit(w0, h0, l0); bsplit(w1, h1, l1);
                    *(__nv_bfloat162*)(g_whi + (size_t)r1 * DM + cw) = __halves2bfloat162(h0, h1);
                    *(__nv_bfloat162*)(g_wlo + (size_t)r1 * DM + cw) = __halves2bfloat162(l0, l1);
                }
            }
    }
}

// tokens[b,h,g,d] = sum_{n in b} w[n,h,g] * fx[n,h,d]; norms[b,h,g] = sum w
__global__ void k_tokens() {
    int bh = blockIdx.x;
    int b = bh >> 3, h = bh & 7;
    int cnt = g_rowcnt[b], start = g_rowstart[b];
    int c0 = (int)(((long long)cnt * blockIdx.y) >> 4);
    int c1 = (int)(((long long)cnt * (blockIdx.y + 1)) >> 4);
    int t = threadIdx.x;
    int tg = (t >> 4) * 4, td = (t & 15) * 4;
    float acc[4][4] = {};
    float nacc[4] = {};
    __shared__ float ws[16][64], fs[16][64];
    __shared__ int rid[16];
    for (int i0 = c0; i0 < c1; i0 += 16) {
        int nr = c1 - i0; if (nr > 16) nr = 16;
        if (t < nr) rid[t] = g_rowlist[start + i0 + t];
        __syncthreads();
        for (int idx = t; idx < nr * 64; idx += 256) {
            int r = idx >> 6, c = idx & 63;
            size_t off = (size_t)rid[r] * DM + h * 64 + c;
            ws[r][c] = g_w[off];
            fs[r][c] = g_fx[off];
        }
        __syncthreads();
        for (int r = 0; r < nr; r++) {
            float wv[4], fv[4];
#pragma unroll
            for (int i = 0; i < 4; i++) { wv[i] = ws[r][tg + i]; fv[i] = fs[r][td + i]; }
#pragma unroll
            for (int i = 0; i < 4; i++) {
                if (td == 0) nacc[i] += wv[i];
#pragma unroll
                for (int j = 0; j < 4; j++) acc[i][j] = fmaf(wv[i], fv[j], acc[i][j]);
            }
        }
        __syncthreads();
    }
    float* tok = g_tokens + (size_t)bh * NG * DH;
#pragma unroll
    for (int i = 0; i < 4; i++) {
#pragma unroll
        for (int j = 0; j < 4; j++) atomicAdd(&tok[(tg + i) * DH + td + j], acc[i][j]);
        if (td == 0) atomicAdd(&g_norms[bh * NG + tg + i], nacc[i]);
    }
}

// fused q/k/v projection + 64x64 self-attention per (b,h)
__global__ void k_qkvattn(const float* __restrict__ Wq, const float* __restrict__ bq,
                          const float* __restrict__ Wk, const float* __restrict__ bk,
                          const float* __restrict__ Wv, const float* __restrict__ bv) {
    int bh = blockIdx.x;
    extern __shared__ float fsm[];
    float* s_a = fsm;                 // [64][65]
    float* s_q = fsm + 64 * 65;
    float* s_k = s_q + 4096;
    float* s_v = s_k + 4096;
    float* s_s = s_v + 4096;          // W staging, then scores
    int t = threadIdx.x;
    for (int i = t; i < 4096; i += 256) {
        int g = i >> 6, d = i & 63;
        s_a[g * 65 + d] = g_tokens[(size_t)bh * 4096 + i] / (g_norms[bh * 64 + g] + 1e-5f);
    }
    int tx = t & 15, ty = t >> 4;
    const float* Ws[3] = {Wq, Wk, Wv};
    const float* bs[3] = {bq, bk, bv};
    float* outs[3] = {s_q, s_k, s_v};
#pragma unroll 1
    for (int p = 0; p < 3; p++) {
        for (int i = t; i < 4096; i += 256) s_s[i] = Ws[p][i];
        __syncthreads();
        float acc[4][4] = {};
        for (int k = 0; k < 64; k++) {
            float av[4], bv2[4];
#pragma unroll
            for (int i = 0; i < 4; i++) av[i] = s_a[(ty * 4 + i) * 65 + k];
#pragma unroll
            for (int j = 0; j < 4; j++) bv2[j] = s_s[k * 64 + tx * 4 + j];
#pragma unroll
            for (int i = 0; i < 4; i++)
#pragma unroll
                for (int j = 0; j < 4; j++) acc[i][j] = fmaf(av[i], bv2[j], acc[i][j]);
        }
#pragma unroll
        for (int i = 0; i < 4; i++)
#pragma unroll
            for (int j = 0; j < 4; j++)
                outs[p][(ty * 4 + i) * 64 + tx * 4 + j] = acc[i][j] + bs[p][tx * 4 + j];
        __syncthreads();
    }
    // scores = q k^T * SCL into s_s
    {
        float acc[4][4] = {};
        for (int d = 0; d < 64; d++) {
            float av[4], bv2[4];
#pragma unroll
            for (int i = 0; i < 4; i++) av[i] = s_q[(ty * 4 + i) * 64 + d];
#pragma unroll
            for (int j = 0; j < 4; j++) bv2[j] = s_k[(tx * 4 + j) * 64 + d];
#pragma unroll
            for (int i = 0; i < 4; i++)
#pragma unroll
                for (int j = 0; j < 4; j++) acc[i][j] = fmaf(av[i], bv2[j], acc[i][j]);
        }
#pragma unroll
        for (int i = 0; i < 4; i++)
#pragma unroll
            for (int j = 0; j < 4; j++)
                s_s[(ty * 4 + i) * 64 + tx * 4 + j] = acc[i][j] * SCL;
    }
    __syncthreads();
    if (t < 64) {
        float m = -1e30f;
        for (int j = 0; j < 64; j++) m = fmaxf(m, s_s[t * 64 + j]);
        float s = 0.f;
        for (int j = 0; j < 64; j++) { float e = __expf(s_s[t * 64 + j] - m); s_s[t * 64 + j] = e; s += e; }
        float inv = 1.f / s;
        for (int j = 0; j < 64; j++) s_s[t * 64 + j] *= inv;
    }
    __syncthreads();
    float acc[4][4] = {};
    for (int k2 = 0; k2 < 64; k2++) {
        float av[4], bv2[4];
#pragma unroll
        for (int i = 0; i < 4; i++) av[i] = s_s[(ty * 4 + i) * 64 + k2];
#pragma unroll
        for (int j = 0; j < 4; j++) bv2[j] = s_v[k2 * 64 + tx * 4 + j];
#pragma unroll
        for (int i = 0; i < 4; i++)
#pragma unroll
            for (int j = 0; j < 4; j++) acc[i][j] = fmaf(av[i], bv2[j], acc[i][j]);
    }
#pragma unroll
    for (int i = 0; i < 4; i++)
#pragma unroll
        for (int j = 0; j < 4; j++)
            g_outtok[(size_t)bh * 4096 + (ty * 4 + i) * 64 + tx * 4 + j] = acc[i][j];
}

// sonata ks/vs projection: [32768x64] @ [64x64] + bias
__global__ void k_skv(const float* __restrict__ son,
                      const float* __restrict__ Wck, const float* __restrict__ bck,
                      const float* __restrict__ Wcv, const float* __restrict__ bcv) {
    int rt = blockIdx.x;
    int sel = blockIdx.y;
    const float* W = sel ? Wcv : Wck;
    const float* bias = sel ? bcv : bck;
    float* dst = sel ? g_vs : g_ks;
    __shared__ float s_at[64][65];
    __shared__ float s_b[64][64];
    int t = threadIdx.x;
    size_t base = (size_t)rt * 64 * 64;
    for (int i = t; i < 4096; i += 256) {
        s_at[i & 63][i >> 6] = son[base + i];
        s_b[i >> 6][i & 63] = W[i];
    }
    __syncthreads();
    int tx = t & 15, ty = t >> 4;
    float acc[4][4] = {};
    for (int k = 0; k < 64; k++) {
        float av[4], bv2[4];
#pragma unroll
        for (int i = 0; i < 4; i++) av[i] = s_at[k][ty * 4 + i];
#pragma unroll
        for (int j = 0; j < 4; j++) bv2[j] = s_b[k][tx * 4 + j];
#pragma unroll
        for (int i = 0; i < 4; i++)
#pragma unroll
            for (int j = 0; j < 4; j++) acc[i][j] = fmaf(av[i], bv2[j], acc[i][j]);
    }
#pragma unroll
    for (int i = 0; i < 4; i++)
#pragma unroll
        for (int j = 0; j < 4; j++)
            dst[base + (size_t)(ty * 4 + i) * 64 + tx * 4 + j] = acc[i][j] + bias[tx * 4 + j];
}

// cross-attention scores: grid (64 bh, 8 j-slices)
__global__ void k_cross_score() {
    int bh = blockIdx.x, b = bh >> 3, h = bh & 7;
    int cnt = g_mcnt[b], start = g_mstart[b];
    if (cnt == 0) return;
    int sl = blockIdx.y;
    int lo = (int)(((long long)cnt * sl) >> 3);
    int hi = (int)(((long long)cnt * (sl + 1)) >> 3);
    if (lo >= hi) return;
    __shared__ float s_q[64][65];
    __shared__ float s_kv[32][64];
    __shared__ int mid[32];
    int t = threadIdx.x;
    for (int i = t; i < 4096; i += 256) s_q[i >> 6][i & 63] = g_outtok[(size_t)bh * 4096 + i];
    __syncthreads();
    float* sc = g_scores + (size_t)bh * 64 * MS;
    for (int j0 = lo; j0 < hi; j0 += 32) {
        int nj = hi - j0; if (nj > 32) nj = 32;
        if (t < nj) mid[t] = g_mlist[start + j0 + t];
        __syncthreads();
        for (int i = t; i < nj * 64; i += 256) {
            int r = i >> 6, c = i & 63;
            s_kv[r][c] = g_ks[(size_t)mid[r] * DM + h * 64 + c];
        }
        __syncthreads();
        int g = t & 63, jp = t >> 6;
        for (int j = jp; j < nj; j += 4) {
            float a = 0.f;
#pragma unroll 16
            for (int d = 0; d < 64; d++) a = fmaf(s_q[g][d], s_kv[j][d], a);
            sc[(size_t)g * MS + j0 + j] = a * SCL;
        }
        __syncthreads();
    }
}

// cross-attention softmax: grid (64 bh), warp handles 8 rows
__global__ void k_cross_soft() {
    int bh = blockIdx.x, b = bh >> 3;
    int cnt = g_mcnt[b];
    if (cnt == 0) return;
    float* sc = g_scores + (size_t)bh * 64 * MS;
    int warp = threadIdx.x >> 5, lane = threadIdx.x & 31;
    for (int g = warp * 8; g < warp * 8 + 8; g++) {
        float* row = sc + (size_t)g * MS;
        float m = -1e30f;
        for (int j = lane; j < cnt; j += 32) m = fmaxf(m, row[j]);
#pragma unroll
        for (int o = 16; o; o >>= 1) m = fmaxf(m, __shfl_xor_sync(0xFFFFFFFFu, m, o));
        float s = 0.f;
        for (int j = lane; j < cnt; j += 32) s += __expf(row[j] - m);
#pragma unroll
        for (int o = 16; o; o >>= 1) s += __shfl_xor_sync(0xFFFFFFFFu, s, o);
        float inv = 1.f / s;
        for (int j = lane; j < cnt; j += 32) row[j] = __expf(row[j] - m) * inv;
    }
}

// cross-attention output: grid (64 bh, 4 j-slices), atomic accumulate into outtok
__global__ void k_cross_out() {
    int bh = blockIdx.x, b = bh >> 3, h = bh & 7;
    int cnt = g_mcnt[b], start = g_mstart[b];
    if (cnt == 0) return;
    int sl = blockIdx.y;
    int lo = (int)(((long long)cnt * sl) >> 2);
    int hi = (int)(((long long)cnt * (sl + 1)) >> 2);
    if (lo >= hi) return;
    __shared__ float s_kv[32][64];
    __shared__ float s_cw[64][33];
    __shared__ int mid[32];
    int t = threadIdx.x;
    int tx = t & 15, ty = t >> 4;
    const float* sc = g_scores + (size_t)bh * 64 * MS;
    float acc[4][4] = {};
    for (int j0 = lo; j0 < hi; j0 += 32) {
        int nj = hi - j0; if (nj > 32) nj = 32;
        if (t < nj) mid[t] = g_mlist[start + j0 + t];
        __syncthreads();
        for (int i = t; i < nj * 64; i += 256) {
            int r = i >> 6, c = i & 63;
            s_kv[r][c] = g_vs[(size_t)mid[r] * DM + h * 64 + c];
        }
        for (int i = t; i < 64 * 32; i += 256) {
            int g = i >> 5, j = i & 31;
            s_cw[g][j] = (j < nj) ? sc[(size_t)g * MS + j0 + j] : 0.f;
        }
        __syncthreads();
        for (int j = 0; j < nj; j++) {
            float vvv[4];
#pragma unroll
            for (int jj = 0; jj < 4; jj++) vvv[jj] = s_kv[j][tx * 4 + jj];
#pragma unroll
            for (int i = 0; i < 4; i++) {
                float c = s_cw[ty * 4 + i][j];
#pragma unroll
                for (int jj = 0; jj < 4; jj++) acc[i][jj] = fmaf(c, vvv[jj], acc[i][jj]);
            }
        }
        __syncthreads();
    }
#pragma unroll
    for (int i = 0; i < 4; i++)
#pragma unroll
        for (int jj = 0; jj < 4; jj++)
            atomicAdd(&g_outtok[(size_t)bh * 4096 + (ty * 4 + i) * 64 + tx * 4 + jj], acc[i][jj]);
}

// P[b, h*64+g, c] = sum_d out_tok[b,h,g,d] * W_out[h*64+d, c], stored transposed bf16 hi/lo
__global__ void k_P(const float* __restrict__ Wout) {
    int bh = blockIdx.x, b = bh >> 3, h = bh & 7;
    int col0 = blockIdx.y * 64;
    __shared__ float s_a[64][65];
    __shared__ float s_b[64][64];
    int t = threadIdx.x;
    for (int i = t; i < 4096; i += 256) {
        int r = i >> 6, c = i & 63;
        s_a[r][c] = g_outtok[(size_t)bh * 4096 + i];
        s_b[r][c] = Wout[(size_t)(h * 64 + r) * DM + col0 + c];
    }
    __syncthreads();
    int tx = t & 15, ty = t >> 4;
    float acc[4][4] = {};
    for (int d = 0; d < 64; d++) {
        float av[4], bv[4];
#pragma unroll
        for (int i = 0; i < 4; i++) av[i] = s_a[ty * 4 + i][d];
#pragma unroll
        for (int j = 0; j < 4; j++) bv[j] = s_b[d][tx * 4 + j];
#pragma unroll
        for (int i = 0; i < 4; i++)
#pragma unroll
            for (int j = 0; j < 4; j++) acc[i][j] = fmaf(av[i], bv[j], acc[i][j]);
    }
#pragma unroll
    for (int i = 0; i < 4; i++)
#pragma unroll
        for (int j = 0; j < 4; j++) {
            int r = h * 64 + ty * 4 + i;       // k index of P
            int c = col0 + tx * 4 + j;         // output col
            __nv_bfloat16 hh, ll;
            bsplit(acc[i][j], hh, ll);
            g_Pthi[((size_t)b * DM + c) * DM + r] = hh;
            g_Ptlo[((size_t)b * DM + c) * DM + r] = ll;
        }
}

// out[n, :] = w[n, :] @ P[batch(n)] via mma.sync bf16x3, gathered rows, 3-stage pipeline
__global__ void __launch_bounds__(256, 2)
k_final_mma(float* __restrict__ out) {
    int b = blockIdx.z;
    int cnt = g_rowcnt[b];
    int r0 = blockIdx.y * 128;
    if (r0 >= cnt) return;
    int nr = cnt - r0; if (nr > 128) nr = 128;
    extern __shared__ char dynsmem[];
    uint32_t sb = smem_to_u32(dynsmem);
    __shared__ int rid[128];
    int t = threadIdx.x;
    int lane = t & 31, wid = t >> 5;
    int wm = (wid & 3) * 32, wn = (wid >> 2) * 64;
    int col0 = blockIdx.x * 128;
    int start = g_rowstart[b];
    if (t < 128) rid[t] = g_rowlist[start + r0 + (t < nr ? t : nr - 1)];
    __syncthreads();
    float acc[2][8][4] = {};
    int a_row = wm + (lane & 15);
    int a_u = lane >> 4;
    int b_row = wn + (lane & 7) + ((lane >> 4) << 3);
    int b_u = (lane >> 3) & 1;
    const __nv_bfloat16* Ph = g_Pthi + ((size_t)b * DM + col0) * DM;
    const __nv_bfloat16* Pl = g_Ptlo + ((size_t)b * DM + col0) * DM;

    auto load_slab = [&](int kc, int stg) {
        uint32_t sbase = sb + stg * STG_BYTES;
#pragma unroll
        for (int half = 0; half < 2; half++) {
            int idx = half * 256 + t;
            int r = idx >> 2, c = idx & 3;
            uint32_t o = SW64_((uint32_t)(r * 64 + c * 16));
            size_t offa = (size_t)rid[r] * DM + kc + c * 8;
            size_t offb = (size_t)r * DM + kc + c * 8;
            cp16(sbase + OFFS_AH + o, g_whi + offa);
            cp16(sbase + OFFS_AL + o, g_wlo + offa);
            cp16(sbase + OFFS_BH + o, Ph + offb);
            cp16(sbase + OFFS_BL + o, Pl + offb);
        }
        CP_COMMIT();
    };

    load_slab(0, 0);
    load_slab(KSLAB, 1);
#pragma unroll 1
    for (int ch = 0; ch < NSLAB; ch++) {
        if (ch + 2 < NSLAB) { load_slab((ch + 2) * KSLAB, (ch + 2) % 3); CP_WAIT2(); }
        else if (ch + 1 < NSLAB) { CP_WAIT1(); }
        else { CP_WAIT0(); }
        __syncthreads();
        uint32_t sbase = sb + (ch % 3) * STG_BYTES;
#pragma unroll
        for (int ks = 0; ks < 2; ks++) {
            uint32_t ah[2][4], al[2][4];
#pragma unroll
            for (int mt = 0; mt < 2; mt++) {
                uint32_t off = SW64_((uint32_t)((a_row + mt * 16) * 64 + ks * 32 + a_u * 16));
                ldsm4(ah[mt], sbase + OFFS_AH + off);
                ldsm4(al[mt], sbase + OFFS_AL + off);
            }
#pragma unroll
            for (int np = 0; np < 4; np++) {
                uint32_t bh[4], bl[4];
                uint32_t boff = SW64_((uint32_t)((b_row + np * 16) * 64 + ks * 32 + b_u * 16));
                ldsm4(bh, sbase + OFFS_BH + boff);
                ldsm4(bl, sbase + OFFS_BL + boff);
#pragma unroll
                for (int mt = 0; mt < 2; mt++) {
                    mma16816(acc[mt][np * 2 + 0], ah[mt], bh[0], bh[1]);
                    mma16816(acc[mt][np * 2 + 0], ah[mt], bl[0], bl[1]);
                    mma16816(acc[mt][np * 2 + 0], al[mt], bh[0], bh[1]);
                    mma16816(acc[mt][np * 2 + 1], ah[mt], bh[2], bh[3]);
                    mma16816(acc[mt][np * 2 + 1], ah[mt], bl[2], bl[3]);
                    mma16816(acc[mt][np * 2 + 1], al[mt], bh[2], bh[3]);
                }
            }
        }
        __syncthreads();
    }
    int g = lane >> 2, tig = lane & 3;
#pragma unroll
    for (int mt = 0; mt < 2; mt++)
#pragma unroll
        for (int nt = 0; nt < 8; nt++) {
            int ml = wm + mt * 16 + g;
            int c = col0 + wn + nt * 8 + tig * 2;
            if (ml < nr)
                *(float2*)(out + (size_t)rid[ml] * DM + c) =
                    make_float2(acc[mt][nt][0], acc[mt][nt][1]);
            if (ml + 8 < nr)
                *(float2*)(out + (size_t)rid[ml + 8] * DM + c) =
                    make_float2(acc[mt][nt][2], acc[mt][nt][3]);
        }
}

extern "C" void kernel_launch(void* const* d_in, const int* in_sizes, int n_in,
                              void* d_out, int out_size) {
    const float* x    = (const float*)d_in[0];
    const int*   bi   = (const int*)d_in[1];
    const float* son  = (const float*)d_in[2];
    const int*   sbi  = (const int*)d_in[3];
    const float* temp = (const float*)d_in[4];
    const float* Wfx  = (const float*)d_in[5];
    const float* bfx  = (const float*)d_in[6];
    const float* Wx   = (const float*)d_in[7];
    const float* bx   = (const float*)d_in[8];
    const float* Wsl  = (const float*)d_in[9];
    const float* bsl  = (const float*)d_in[10];
    const float* Wq   = (const float*)d_in[11];
    const float* bq   = (const float*)d_in[12];
    const float* Wk   = (const float*)d_in[13];
    const float* bk   = (const float*)d_in[14];
    const float* Wv   = (const float*)d_in[15];
    const float* bv   = (const float*)d_in[16];
    const float* Wck  = (const float*)d_in[17];
    const float* bck  = (const float*)d_in[18];
    const float* Wcv  = (const float*)d_in[19];
    const float* bcv  = (const float*)d_in[20];
    const float* Wout = (const float*)d_in[21];
    float* out = (float*)d_out;

    // Persistent side streams/events (created once, on the uncaptured
    // correctness call; only record/wait — both capturable — happen later).
    static cudaStream_t s1 = nullptr, s2 = nullptr;
    static cudaEvent_t eF = nullptr, e1 = nullptr, e2a = nullptr, e2b = nullptr;
    if (s1 == nullptr) {
        cudaStreamCreateWithFlags(&s1, cudaStreamNonBlocking);
        cudaStreamCreateWithFlags(&s2, cudaStreamNonBlocking);
        cudaEventCreateWithFlags(&eF, cudaEventDisableTiming);
        cudaEventCreateWithFlags(&e1, cudaEventDisableTiming);
        cudaEventCreateWithFlags(&e2a, cudaEventDisableTiming);
        cudaEventCreateWithFlags(&e2b, cudaEventDisableTiming);
        cudaFuncSetAttribute(k_gemm_mma, cudaFuncAttributeMaxDynamicSharedMemorySize, SMEM_MMA);
        cudaFuncSetAttribute(k_final_mma, cudaFuncAttributeMaxDynamicSharedMemorySize, SMEM_MMA);
        cudaFuncSetAttribute(k_qkvattn, cudaFuncAttributeMaxDynamicSharedMemorySize, QKV_SMEM);
    }

    // fork
    cudaEventRecord(eF, 0);
    cudaStreamWaitEvent(s1, eF, 0);
    cudaStreamWaitEvent(s2, eF, 0);

    // stream s1: batch bucketing chain (independent of x path)
    k_zero<<<1024, 256, 0, s1>>>();
    k_count<<<80, 256, 0, s1>>>(bi, sbi);
    k_prefix<<<1, 1, 0, s1>>>();
    k_scatter<<<80, 256, 0, s1>>>(bi, sbi);
    cudaEventRecord(e1, s1);

    // stream s2: weight transpose (feeds gemm), then sonata K/V projection
    k_wcomb<<<dim3(512, 2), 256, 0, s2>>>(Wx, Wsl, Wfx);
    cudaEventRecord(e2a, s2);
    k_skv<<<dim3(512, 2), 256, 0, s2>>>(son, Wck, bck, Wcv, bcv);
    cudaEventRecord(e2b, s2);

    // main stream
    k_bcomb<<<1, 512>>>(bx, Wsl, bsl);
    k_cvt_x<<<8192, 256>>>(x);
    cudaStreamWaitEvent(0, e2a, 0);
    k_gemm_mma<<<dim3(8, 128), 256, SMEM_MMA>>>(bfx, temp);
    cudaStreamWaitEvent(0, e1, 0);
    k_tokens<<<dim3(64, 16), 256>>>();
    k_qkvattn<<<64, 256, QKV_SMEM>>>(Wq, bq, Wk, bk, Wv, bv);
    cudaStreamWaitEvent(0, e2b, 0);
    k_cross_score<<<dim3(64, 8), 256>>>();
    k_cross_soft<<<64, 256>>>();
    k_cross_out<<<dim3(64, 4), 256>>>();
    k_P<<<dim3(64, 8), 256>>>(Wout);
    k_final_mma<<<dim3(4, 128, 8), 256, SMEM_MMA>>>(out);
}

// round 13
// speedup vs baseline: 2.7510x; 1.0275x over previous
#include <cuda_runtime.h>
#include <cuda_bf16.h>
#include <cstdint>

#define NT 16384   // x rows
#define MS 4096    // sonata rows
#define NB 8       // batches
#define NH 8       // heads
#define DH 64      // head dim
#define NG 64      // slice groups
#define DM 512     // model dim
#define SCL 0.125f // D^-0.5

#define SW64_(o) ((o) ^ (((o) >> 3) & 0x30))

__device__ __forceinline__ uint32_t smem_to_u32(const void* p) {
    uint32_t a;
    asm("{ .reg .u64 tmp; cvta.to.shared.u64 tmp, %1; cvt.u32.u64 %0, tmp; }"
        : "=r"(a) : "l"(p));
    return a;
}
__device__ __forceinline__ void ldsm4(uint32_t a[4], uint32_t addr) {
    asm volatile("ldmatrix.sync.aligned.m8n8.x4.shared.b16 {%0,%1,%2,%3}, [%4];"
                 : "=r"(a[0]), "=r"(a[1]), "=r"(a[2]), "=r"(a[3]) : "r"(addr));
}
__device__ __forceinline__ void mma16816(float c[4], const uint32_t a[4],
                                         uint32_t b0, uint32_t b1) {
    asm volatile(
        "mma.sync.aligned.m16n8k16.row.col.f32.bf16.bf16.f32 "
        "{%0,%1,%2,%3}, {%4,%5,%6,%7}, {%8,%9}, {%0,%1,%2,%3};"
        : "+f"(c[0]), "+f"(c[1]), "+f"(c[2]), "+f"(c[3])
        : "r"(a[0]), "r"(a[1]), "r"(a[2]), "r"(a[3]), "r"(b0), "r"(b1));
}
__device__ __forceinline__ void cp16(uint32_t dst, const void* src) {
    asm volatile("cp.async.cg.shared.global [%0], [%1], 16;" :: "r"(dst), "l"(src));
}
#define CP_COMMIT() asm volatile("cp.async.commit_group;" ::: "memory")
#define CP_WAIT2() asm volatile("cp.async.wait_group 2;" ::: "memory")
#define CP_WAIT1() asm volatile("cp.async.wait_group 1;" ::: "memory")
#define CP_WAIT0() asm volatile("cp.async.wait_group 0;" ::: "memory")

__device__ __forceinline__ void bsplit(float v, __nv_bfloat16& h, __nv_bfloat16& l) {
    h = __float2bfloat16(v);
    l = __float2bfloat16(v - __bfloat162float(h));
}

// pipelined MMA smem: 3 stages x (AH 8K | AL 8K | BH 8K | BL 8K) = 96KB
#define STG_BYTES 32768
#define OFFS_AH 0
#define OFFS_AL 8192
#define OFFS_BH 16384
#define OFFS_BL 24576
#define SMEM_MMA (3 * STG_BYTES)
#define KSLAB 32
#define NSLAB (DM / KSLAB)

// fused qkv+attn smem: a[64][65] + q,k,v,s 4x[64][64]  (floats)
#define QKV_SMEM ((64 * 65 + 4 * 4096) * 4)

// ---------------- device scratch ----------------
__device__ float g_bcomb[DM];
__device__ float g_fx[(size_t)NT * DM];
__device__ float g_w[(size_t)NT * DM];
__device__ __nv_bfloat16 g_xhi[(size_t)NT * DM], g_xlo[(size_t)NT * DM];
__device__ __nv_bfloat16 g_Bthi[(size_t)2 * DM * DM], g_Btlo[(size_t)2 * DM * DM]; // [1024][512]
__device__ __nv_bfloat16 g_whi[(size_t)NT * DM], g_wlo[(size_t)NT * DM];
__device__ __nv_bfloat16 g_Pthi[(size_t)NB * DM * DM], g_Ptlo[(size_t)NB * DM * DM]; // [b][c][k]
__device__ float g_tokens[NB * NH * NG * DH];
__device__ float g_norms[NB * NH * NG];
__device__ float g_outtok[NB * NH * NG * DH];
__device__ float g_ks[(size_t)MS * DM];
__device__ float g_vs[(size_t)MS * DM];
__device__ float g_scores[(size_t)NB * NH * NG * MS];
__device__ float2 g_cstats[NB * NH * NG];   // per-(bh,g) softmax (m, inv)
__device__ int g_rowlist[NT], g_rowcnt[NB], g_rowstart[NB + 1], g_rowcur[NB];
__device__ int g_mlist[MS], g_mcnt[NB], g_mstart[NB + 1], g_mcur[NB];

// ---------------- setup kernels ----------------
__global__ void k_zero() {
    int i = blockIdx.x * 256 + threadIdx.x;
    if (i < NB * NH * NG * DH) g_tokens[i] = 0.f;
    if (i < NB * NH * NG) g_norms[i] = 0.f;
    if (i < NB) {
        g_rowcnt[i] = 0; g_mcnt[i] = 0;
        g_rowcur[i] = 0; g_mcur[i] = 0;
    }
}

__global__ void k_bcomb(const float* __restrict__ bx, const float* __restrict__ Wsl,
                        const float* __restrict__ bsl) {
    int o = threadIdx.x;  // 512
    int h = o >> 6, g = o & 63;
    float acc = bsl[g];
    for (int d = 0; d < 64; d++) acc = fmaf(bx[h * 64 + d], Wsl[d * 64 + g], acc);
    g_bcomb[o] = acc;
}

// x fp32 -> bf16 hi/lo split
__global__ void k_cvt_x(const float* __restrict__ x) {
    size_t i = (size_t)blockIdx.x * 256 + threadIdx.x;  // one float4 each
    float4 v = ((const float4*)x)[i];
    __nv_bfloat16 h0, h1, h2, h3, l0, l1, l2, l3;
    bsplit(v.x, h0, l0); bsplit(v.y, h1, l1);
    bsplit(v.z, h2, l2); bsplit(v.w, h3, l3);
    ((__nv_bfloat162*)g_xhi)[i * 2 + 0] = __halves2bfloat162(h0, h1);
    ((__nv_bfloat162*)g_xhi)[i * 2 + 1] = __halves2bfloat162(h2, h3);
    ((__nv_bfloat162*)g_xlo)[i * 2 + 0] = __halves2bfloat162(l0, l1);
    ((__nv_bfloat162*)g_xlo)[i * 2 + 1] = __halves2bfloat162(l2, l3);
}

// y==1: Bt rows 0..511 (transposed Wfx); y==0: Bt rows 512..1023 from Wcomb = Wx·Wsl
__global__ void k_wcomb(const float* __restrict__ Wx, const float* __restrict__ Wsl,
                        const float* __restrict__ Wfx) {
    int c = blockIdx.x;  // 0..511
    int t = threadIdx.x;
    if (blockIdx.y == 1) {
        for (int k = t; k < DM; k += 256) {
            __nv_bfloat16 h, l;
            bsplit(Wfx[(size_t)k * DM + c], h, l);
            g_Bthi[(size_t)c * DM + k] = h;
            g_Btlo[(size_t)c * DM + k] = l;
        }
        return;
    }
    __shared__ float s_sl[4096];
    for (int i = t; i < 4096; i += 256) s_sl[i] = Wsl[i];
    __syncthreads();
    for (int o = t; o < 512; o += 256) {
        int h = o >> 6, g = o & 63;
        const float* wxr = Wx + (size_t)c * DM + h * 64;
        float acc = 0.f;
        for (int d = 0; d < 64; d++) acc = fmaf(wxr[d], s_sl[d * 64 + g], acc);
        __nv_bfloat16 hh, ll;
        bsplit(acc, hh, ll);
        g_Bthi[(size_t)(DM + o) * DM + c] = hh;
        g_Btlo[(size_t)(DM + o) * DM + c] = ll;
    }
}

__global__ void k_count(const int* __restrict__ bi, const int* __restrict__ sbi) {
    int i = blockIdx.x * 256 + threadIdx.x;
    if (i < NT) atomicAdd(&g_rowcnt[bi[i]], 1);
    else if (i < NT + MS) atomicAdd(&g_mcnt[sbi[i - NT]], 1);
}

__global__ void k_prefix() {
    if (threadIdx.x == 0) {
        int s = 0;
        for (int b = 0; b < NB; b++) { g_rowstart[b] = s; s += g_rowcnt[b]; }
        g_rowstart[NB] = s;
        s = 0;
        for (int b = 0; b < NB; b++) { g_mstart[b] = s; s += g_mcnt[b]; }
        g_mstart[NB] = s;
    }
}

__global__ void k_scatter(const int* __restrict__ bi, const int* __restrict__ sbi) {
    int i = blockIdx.x * 256 + threadIdx.x;
    if (i < NT) {
        int b = bi[i];
        int p = atomicAdd(&g_rowcur[b], 1);
        g_rowlist[g_rowstart[b] + p] = i;
    } else if (i < NT + MS) {
        int j = i - NT;
        int b = sbi[j];
        int p = atomicAdd(&g_mcur[b], 1);
        g_mlist[g_mstart[b] + p] = j;
    }
}

// ---------------- front GEMM via mma.sync bf16x3, 3-stage pipeline, fused slice-softmax ----------------
__global__ void __launch_bounds__(256, 2)
k_gemm_mma(const float* __restrict__ bfx, const float* __restrict__ temp) {
    extern __shared__ char dynsmem[];
    uint32_t sb = smem_to_u32(dynsmem);
    int t = threadIdx.x;
    int lane = t & 31, wid = t >> 5;
    int wm = (wid & 3) * 32, wn = (wid >> 2) * 64;
    int row0 = blockIdx.y * 128, col0 = blockIdx.x * 128;
    float acc[2][8][4] = {};
    int a_row = wm + (lane & 15);
    int a_u = lane >> 4;
    int b_row = wn + (lane & 7) + ((lane >> 4) << 3);
    int b_u = (lane >> 3) & 1;

    auto load_slab = [&](int kc, int stg) {
        uint32_t sbase = sb + stg * STG_BYTES;
#pragma unroll
        for (int half = 0; half < 2; half++) {
            int idx = half * 256 + t;
            int r = idx >> 2, c = idx & 3;
            uint32_t o = SW64_((uint32_t)(r * 64 + c * 16));
            size_t offa = (size_t)(row0 + r) * DM + kc + c * 8;
            size_t offb = (size_t)(col0 + r) * DM + kc + c * 8;
            cp16(sbase + OFFS_AH + o, g_xhi + offa);
            cp16(sbase + OFFS_AL + o, g_xlo + offa);
            cp16(sbase + OFFS_BH + o, g_Bthi + offb);
            cp16(sbase + OFFS_BL + o, g_Btlo + offb);
        }
        CP_COMMIT();
    };

    load_slab(0, 0);
    load_slab(KSLAB, 1);
#pragma unroll 1
    for (int ch = 0; ch < NSLAB; ch++) {
        if (ch + 2 < NSLAB) { load_slab((ch + 2) * KSLAB, (ch + 2) % 3); CP_WAIT2(); }
        else if (ch + 1 < NSLAB) { CP_WAIT1(); }
        else { CP_WAIT0(); }
        __syncthreads();
        uint32_t sbase = sb + (ch % 3) * STG_BYTES;
#pragma unroll
        for (int ks = 0; ks < 2; ks++) {
            uint32_t ah[2][4], al[2][4];
#pragma unroll
            for (int mt = 0; mt < 2; mt++) {
                uint32_t off = SW64_((uint32_t)((a_row + mt * 16) * 64 + ks * 32 + a_u * 16));
                ldsm4(ah[mt], sbase + OFFS_AH + off);
                ldsm4(al[mt], sbase + OFFS_AL + off);
            }
#pragma unroll
            for (int np = 0; np < 4; np++) {
                uint32_t bh[4], bl[4];
                uint32_t boff = SW64_((uint32_t)((b_row + np * 16) * 64 + ks * 32 + b_u * 16));
                ldsm4(bh, sbase + OFFS_BH + boff);
                ldsm4(bl, sbase + OFFS_BL + boff);
#pragma unroll
                for (int mt = 0; mt < 2; mt++) {
                    mma16816(acc[mt][np * 2 + 0], ah[mt], bh[0], bh[1]);
                    mma16816(acc[mt][np * 2 + 0], ah[mt], bl[0], bl[1]);
                    mma16816(acc[mt][np * 2 + 0], al[mt], bh[0], bh[1]);
                    mma16816(acc[mt][np * 2 + 1], ah[mt], bh[2], bh[3]);
                    mma16816(acc[mt][np * 2 + 1], ah[mt], bl[2], bl[3]);
                    mma16816(acc[mt][np * 2 + 1], al[mt], bh[2], bh[3]);
                }
            }
        }
        __syncthreads();
    }
    int g = lane >> 2, tig = lane & 3;
    bool isfx = (col0 < DM);
    if (isfx) {
#pragma unroll
        for (int mt = 0; mt < 2; mt++)
#pragma unroll
            for (int nt = 0; nt < 8; nt++) {
                int r1 = row0 + wm + mt * 16 + g;
                int c = col0 + wn + nt * 8 + tig * 2;
                float b0v = bfx[c], b1v = bfx[c + 1];
                *(float2*)(g_fx + (size_t)r1 * DM + c) =
                    make_float2(acc[mt][nt][0] + b0v, acc[mt][nt][1] + b1v);
                *(float2*)(g_fx + (size_t)(r1 + 8) * DM + c) =
                    make_float2(acc[mt][nt][2] + b0v, acc[mt][nt][3] + b1v);
            }
    } else {
        // fused slice softmax: this warp's 64 cols == one head; each row's 64
        // logits live in the 4 lanes sharing g (tig 0..3), 16 values each.
        int cbase = col0 - DM;
        int h = (cbase + wn) >> 6;
        float it = 1.f / temp[h];
#pragma unroll
        for (int mt = 0; mt < 2; mt++)
#pragma unroll
            for (int half = 0; half < 2; half++) {
                int r1 = row0 + wm + mt * 16 + g + half * 8;
                float v[16];
#pragma unroll
                for (int nt = 0; nt < 8; nt++) {
                    int c = cbase + wn + nt * 8 + tig * 2;
                    v[nt * 2 + 0] = (acc[mt][nt][half * 2 + 0] + g_bcomb[c]) * it;
                    v[nt * 2 + 1] = (acc[mt][nt][half * 2 + 1] + g_bcomb[c + 1]) * it;
                }
                float m = v[0];
#pragma unroll
                for (int i = 1; i < 16; i++) m = fmaxf(m, v[i]);
                m = fmaxf(m, __shfl_xor_sync(0xFFFFFFFFu, m, 1));
                m = fmaxf(m, __shfl_xor_sync(0xFFFFFFFFu, m, 2));
                float s = 0.f;
#pragma unroll
                for (int i = 0; i < 16; i++) { v[i] = __expf(v[i] - m); s += v[i]; }
                s += __shfl_xor_sync(0xFFFFFFFFu, s, 1);
                s += __shfl_xor_sync(0xFFFFFFFFu, s, 2);
                float inv = 1.f / s;
#pragma unroll
                for (int nt = 0; nt < 8; nt++) {
                    int cw = cbase + wn + nt * 8 + tig * 2;
                    float w0 = v[nt * 2 + 0] * inv, w1 = v[nt * 2 + 1] * inv;
                    *(float2*)(g_w + (size_t)r1 * DM + cw) = make_float2(w0, w1);
                    __nv_bfloat16 h0, l0, h1, l1;
                    bsplit(w0, h0, l0); bsplit(w1, h1, l1);
                    *(__nv_bfloat162*)(g_whi + (size_t)r1 * DM + cw) = __halves2bfloat162(h0, h1);
                    *(__nv_bfloat162*)(g_wlo + (size_t)r1 * DM + cw) = __halves2bfloat162(l0, l1);
                }
            }
    }
}

// tokens[b,h,g,d] = sum_{n in b} w[n,h,g] * fx[n,h,d]; norms[b,h,g] = sum w
// grid (64 bh, 32 row-slices)
__global__ void k_tokens() {
    int bh = blockIdx.x;
    int b = bh >> 3, h = bh & 7;
    int cnt = g_rowcnt[b], start = g_rowstart[b];
    int c0 = (int)(((long long)cnt * blockIdx.y) >> 5);
    int c1 = (int)(((long long)cnt * (blockIdx.y + 1)) >> 5);
    int t = threadIdx.x;
    int tg = (t >> 4) * 4, td = (t & 15) * 4;
    float acc[4][4] = {};
    float nacc[4] = {};
    __shared__ float ws[16][64], fs[16][64];
    __shared__ int rid[16];
    for (int i0 = c0; i0 < c1; i0 += 16) {
        int nr = c1 - i0; if (nr > 16) nr = 16;
        if (t < nr) rid[t] = g_rowlist[start + i0 + t];
        __syncthreads();
        for (int idx = t; idx < nr * 64; idx += 256) {
            int r = idx >> 6, c = idx & 63;
            size_t off = (size_t)rid[r] * DM + h * 64 + c;
            ws[r][c] = g_w[off];
            fs[r][c] = g_fx[off];
        }
        __syncthreads();
        for (int r = 0; r < nr; r++) {
            float wv[4], fv[4];
#pragma unroll
            for (int i = 0; i < 4; i++) { wv[i] = ws[r][tg + i]; fv[i] = fs[r][td + i]; }
#pragma unroll
            for (int i = 0; i < 4; i++) {
                if (td == 0) nacc[i] += wv[i];
#pragma unroll
                for (int j = 0; j < 4; j++) acc[i][j] = fmaf(wv[i], fv[j], acc[i][j]);
            }
        }
        __syncthreads();
    }
    float* tok = g_tokens + (size_t)bh * NG * DH;
#pragma unroll
    for (int i = 0; i < 4; i++) {
#pragma unroll
        for (int j = 0; j < 4; j++) atomicAdd(&tok[(tg + i) * DH + td + j], acc[i][j]);
        if (td == 0) atomicAdd(&g_norms[bh * NG + tg + i], nacc[i]);
    }
}

// fused q/k/v projection + 64x64 self-attention per (b,h)
__global__ void k_qkvattn(const float* __restrict__ Wq, const float* __restrict__ bq,
                          const float* __restrict__ Wk, const float* __restrict__ bk,
                          const float* __restrict__ Wv, const float* __restrict__ bv) {
    int bh = blockIdx.x;
    extern __shared__ float fsm[];
    float* s_a = fsm;                 // [64][65]
    float* s_q = fsm + 64 * 65;
    float* s_k = s_q + 4096;
    float* s_v = s_k + 4096;
    float* s_s = s_v + 4096;          // W staging, then scores
    int t = threadIdx.x;
    for (int i = t; i < 4096; i += 256) {
        int g = i >> 6, d = i & 63;
        s_a[g * 65 + d] = g_tokens[(size_t)bh * 4096 + i] / (g_norms[bh * 64 + g] + 1e-5f);
    }
    int tx = t & 15, ty = t >> 4;
    const float* Ws[3] = {Wq, Wk, Wv};
    const float* bs[3] = {bq, bk, bv};
    float* outs[3] = {s_q, s_k, s_v};
#pragma unroll 1
    for (int p = 0; p < 3; p++) {
        for (int i = t; i < 4096; i += 256) s_s[i] = Ws[p][i];
        __syncthreads();
        float acc[4][4] = {};
        for (int k = 0; k < 64; k++) {
            float av[4], bv2[4];
#pragma unroll
            for (int i = 0; i < 4; i++) av[i] = s_a[(ty * 4 + i) * 65 + k];
#pragma unroll
            for (int j = 0; j < 4; j++) bv2[j] = s_s[k * 64 + tx * 4 + j];
#pragma unroll
            for (int i = 0; i < 4; i++)
#pragma unroll
                for (int j = 0; j < 4; j++) acc[i][j] = fmaf(av[i], bv2[j], acc[i][j]);
        }
#pragma unroll
        for (int i = 0; i < 4; i++)
#pragma unroll
            for (int j = 0; j < 4; j++)
                outs[p][(ty * 4 + i) * 64 + tx * 4 + j] = acc[i][j] + bs[p][tx * 4 + j];
        __syncthreads();
    }
    // scores = q k^T * SCL into s_s
    {
        float acc[4][4] = {};
        for (int d = 0; d < 64; d++) {
            float av[4], bv2[4];
#pragma unroll
            for (int i = 0; i < 4; i++) av[i] = s_q[(ty * 4 + i) * 64 + d];
#pragma unroll
            for (int j = 0; j < 4; j++) bv2[j] = s_k[(tx * 4 + j) * 64 + d];
#pragma unroll
            for (int i = 0; i < 4; i++)
#pragma unroll
                for (int j = 0; j < 4; j++) acc[i][j] = fmaf(av[i], bv2[j], acc[i][j]);
        }
#pragma unroll
        for (int i = 0; i < 4; i++)
#pragma unroll
            for (int j = 0; j < 4; j++)
                s_s[(ty * 4 + i) * 64 + tx * 4 + j] = acc[i][j] * SCL;
    }
    __syncthreads();
    if (t < 64) {
        float m = -1e30f;
        for (int j = 0; j < 64; j++) m = fmaxf(m, s_s[t * 64 + j]);
        float s = 0.f;
        for (int j = 0; j < 64; j++) { float e = __expf(s_s[t * 64 + j] - m); s_s[t * 64 + j] = e; s += e; }
        float inv = 1.f / s;
        for (int j = 0; j < 64; j++) s_s[t * 64 + j] *= inv;
    }
    __syncthreads();
    float acc[4][4] = {};
    for (int k2 = 0; k2 < 64; k2++) {
        float av[4], bv2[4];
#pragma unroll
        for (int i = 0; i < 4; i++) av[i] = s_s[(ty * 4 + i) * 64 + k2];
#pragma unroll
        for (int j = 0; j < 4; j++) bv2[j] = s_v[k2 * 64 + tx * 4 + j];
#pragma unroll
        for (int i = 0; i < 4; i++)
#pragma unroll
            for (int j = 0; j < 4; j++) acc[i][j] = fmaf(av[i], bv2[j], acc[i][j]);
    }
#pragma unroll
    for (int i = 0; i < 4; i++)
#pragma unroll
        for (int j = 0; j < 4; j++)
            g_outtok[(size_t)bh * 4096 + (ty * 4 + i) * 64 + tx * 4 + j] = acc[i][j];
}

// sonata ks/vs projection: [32768x64] @ [64x64] + bias
__global__ void k_skv(const float* __restrict__ son,
                      const float* __restrict__ Wck, const float* __restrict__ bck,
                      const float* __restrict__ Wcv, const float* __restrict__ bcv) {
    int rt = blockIdx.x;
    int sel = blockIdx.y;
    const float* W = sel ? Wcv : Wck;
    const float* bias = sel ? bcv : bck;
    float* dst = sel ? g_vs : g_ks;
    __shared__ float s_at[64][65];
    __shared__ float s_b[64][64];
    int t = threadIdx.x;
    size_t base = (size_t)rt * 64 * 64;
    for (int i = t; i < 4096; i += 256) {
        s_at[i & 63][i >> 6] = son[base + i];
        s_b[i >> 6][i & 63] = W[i];
    }
    __syncthreads();
    int tx = t & 15, ty = t >> 4;
    float acc[4][4] = {};
    for (int k = 0; k < 64; k++) {
        float av[4], bv2[4];
#pragma unroll
        for (int i = 0; i < 4; i++) av[i] = s_at[k][ty * 4 + i];
#pragma unroll
        for (int j = 0; j < 4; j++) bv2[j] = s_b[k][tx * 4 + j];
#pragma unroll
        for (int i = 0; i < 4; i++)
#pragma unroll
            for (int j = 0; j < 4; j++) acc[i][j] = fmaf(av[i], bv2[j], acc[i][j]);
    }
#pragma unroll
    for (int i = 0; i < 4; i++)
#pragma unroll
        for (int j = 0; j < 4; j++)
            dst[base + (size_t)(ty * 4 + i) * 64 + tx * 4 + j] = acc[i][j] + bias[tx * 4 + j];
}

// cross-attention scores: grid (64 bh, 8 j-slices)
__global__ void k_cross_score() {
    int bh = blockIdx.x, b = bh >> 3, h = bh & 7;
    int cnt = g_mcnt[b], start = g_mstart[b];
    if (cnt == 0) return;
    int sl = blockIdx.y;
    int lo = (int)(((long long)cnt * sl) >> 3);
    int hi = (int)(((long long)cnt * (sl + 1)) >> 3);
    if (lo >= hi) return;
    __shared__ float s_q[64][65];
    __shared__ float s_kv[32][64];
    __shared__ int mid[32];
    int t = threadIdx.x;
    for (int i = t; i < 4096; i += 256) s_q[i >> 6][i & 63] = g_outtok[(size_t)bh * 4096 + i];
    __syncthreads();
    float* sc = g_scores + (size_t)bh * 64 * MS;
    for (int j0 = lo; j0 < hi; j0 += 32) {
        int nj = hi - j0; if (nj > 32) nj = 32;
        if (t < nj) mid[t] = g_mlist[start + j0 + t];
        __syncthreads();
        for (int i = t; i < nj * 64; i += 256) {
            int r = i >> 6, c = i & 63;
            s_kv[r][c] = g_ks[(size_t)mid[r] * DM + h * 64 + c];
        }
        __syncthreads();
        int g = t & 63, jp = t >> 6;
        for (int j = jp; j < nj; j += 4) {
            float a = 0.f;
#pragma unroll 16
            for (int d = 0; d < 64; d++) a = fmaf(s_q[g][d], s_kv[j][d], a);
            sc[(size_t)g * MS + j0 + j] = a * SCL;
        }
        __syncthreads();
    }
}

// cross-attention softmax stats only: grid (64 bh); writes (m, inv) per row
__global__ void k_cross_stat() {
    int bh = blockIdx.x, b = bh >> 3;
    int cnt = g_mcnt[b];
    if (cnt == 0) return;
    float* sc = g_scores + (size_t)bh * 64 * MS;
    int warp = threadIdx.x >> 5, lane = threadIdx.x & 31;
    for (int g = warp * 8; g < warp * 8 + 8; g++) {
        float* row = sc + (size_t)g * MS;
        float m = -1e30f;
        for (int j = lane; j < cnt; j += 32) m = fmaxf(m, row[j]);
#pragma unroll
        for (int o = 16; o; o >>= 1) m = fmaxf(m, __shfl_xor_sync(0xFFFFFFFFu, m, o));
        float s = 0.f;
        for (int j = lane; j < cnt; j += 32) s += __expf(row[j] - m);
#pragma unroll
        for (int o = 16; o; o >>= 1) s += __shfl_xor_sync(0xFFFFFFFFu, s, o);
        if (lane == 0) g_cstats[bh * 64 + g] = make_float2(m, 1.f / s);
    }
}

// cross-attention output: grid (64 bh, 8 j-slices); applies exp inline, atomic accumulate
__global__ void k_cross_out() {
    int bh = blockIdx.x, b = bh >> 3, h = bh & 7;
    int cnt = g_mcnt[b], start = g_mstart[b];
    if (cnt == 0) return;
    int sl = blockIdx.y;
    int lo = (int)(((long long)cnt * sl) >> 3);
    int hi = (int)(((long long)cnt * (sl + 1)) >> 3);
    if (lo >= hi) return;
    __shared__ float s_kv[32][64];
    __shared__ float s_cw[64][33];
    __shared__ float2 s_st[64];
    __shared__ int mid[32];
    int t = threadIdx.x;
    int tx = t & 15, ty = t >> 4;
    if (t < 64) s_st[t] = g_cstats[bh * 64 + t];
    const float* sc = g_scores + (size_t)bh * 64 * MS;
    float acc[4][4] = {};
    for (int j0 = lo; j0 < hi; j0 += 32) {
        int nj = hi - j0; if (nj > 32) nj = 32;
        if (t < nj) mid[t] = g_mlist[start + j0 + t];
        __syncthreads();
        for (int i = t; i < nj * 64; i += 256) {
            int r = i >> 6, c = i & 63;
            s_kv[r][c] = g_vs[(size_t)mid[r] * DM + h * 64 + c];
        }
        for (int i = t; i < 64 * 32; i += 256) {
            int g = i >> 5, j = i & 31;
            float2 st = s_st[g];
            s_cw[g][j] = (j < nj) ? __expf(sc[(size_t)g * MS + j0 + j] - st.x) * st.y : 0.f;
        }
        __syncthreads();
        for (int j = 0; j < nj; j++) {
            float vvv[4];
#pragma unroll
            for (int jj = 0; jj < 4; jj++) vvv[jj] = s_kv[j][tx * 4 + jj];
#pragma unroll
            for (int i = 0; i < 4; i++) {
                float c = s_cw[ty * 4 + i][j];
#pragma unroll
                for (int jj = 0; jj < 4; jj++) acc[i][jj] = fmaf(c, vvv[jj], acc[i][jj]);
            }
        }
        __syncthreads();
    }
#pragma unroll
    for (int i = 0; i < 4; i++)
#pragma unroll
        for (int jj = 0; jj < 4; jj++)
            atomicAdd(&g_outtok[(size_t)bh * 4096 + (ty * 4 + i) * 64 + tx * 4 + jj], acc[i][jj]);
}

// P[b, h*64+g, c] = sum_d out_tok[b,h,g,d] * W_out[h*64+d, c], stored transposed bf16 hi/lo
__global__ void k_P(const float* __restrict__ Wout) {
    int bh = blockIdx.x, b = bh >> 3, h = bh & 7;
    int col0 = blockIdx.y * 64;
    __shared__ float s_a[64][65];
    __shared__ float s_b[64][64];
    int t = threadIdx.x;
    for (int i = t; i < 4096; i += 256) {
        int r = i >> 6, c = i & 63;
        s_a[r][c] = g_outtok[(size_t)bh * 4096 + i];
        s_b[r][c] = Wout[(size_t)(h * 64 + r) * DM + col0 + c];
    }
    __syncthreads();
    int tx = t & 15, ty = t >> 4;
    float acc[4][4] = {};
    for (int d = 0; d < 64; d++) {
        float av[4], bv[4];
#pragma unroll
        for (int i = 0; i < 4; i++) av[i] = s_a[ty * 4 + i][d];
#pragma unroll
        for (int j = 0; j < 4; j++) bv[j] = s_b[d][tx * 4 + j];
#pragma unroll
        for (int i = 0; i < 4; i++)
#pragma unroll
            for (int j = 0; j < 4; j++) acc[i][j] = fmaf(av[i], bv[j], acc[i][j]);
    }
#pragma unroll
    for (int i = 0; i < 4; i++)
#pragma unroll
        for (int j = 0; j < 4; j++) {
            int r = h * 64 + ty * 4 + i;       // k index of P
            int c = col0 + tx * 4 + j;         // output col
            __nv_bfloat16 hh, ll;
            bsplit(acc[i][j], hh, ll);
            g_Pthi[((size_t)b * DM + c) * DM + r] = hh;
            g_Ptlo[((size_t)b * DM + c) * DM + r] = ll;
        }
}

// out[n, :] = w[n, :] @ P[batch(n)] via mma.sync bf16x3, gathered rows, 3-stage pipeline
__global__ void __launch_bounds__(256, 2)
k_final_mma(float* __restrict__ out) {
    int b = blockIdx.z;
    int cnt = g_rowcnt[b];
    int r0 = blockIdx.y * 128;
    if (r0 >= cnt) return;
    int nr = cnt - r0; if (nr > 128) nr = 128;
    extern __shared__ char dynsmem[];
    uint32_t sb = smem_to_u32(dynsmem);
    __shared__ int rid[128];
    int t = threadIdx.x;
    int lane = t & 31, wid = t >> 5;
    int wm = (wid & 3) * 32, wn = (wid >> 2) * 64;
    int col0 = blockIdx.x * 128;
    int start = g_rowstart[b];
    if (t < 128) rid[t] = g_rowlist[start + r0 + (t < nr ? t : nr - 1)];
    __syncthreads();
    float acc[2][8][4] = {};
    int a_row = wm + (lane & 15);
    int a_u = lane >> 4;
    int b_row = wn + (lane & 7) + ((lane >> 4) << 3);
    int b_u = (lane >> 3) & 1;
    const __nv_bfloat16* Ph = g_Pthi + ((size_t)b * DM + col0) * DM;
    const __nv_bfloat16* Pl = g_Ptlo + ((size_t)b * DM + col0) * DM;

    auto load_slab = [&](int kc, int stg) {
        uint32_t sbase = sb + stg * STG_BYTES;
#pragma unroll
        for (int half = 0; half < 2; half++) {
            int idx = half * 256 + t;
            int r = idx >> 2, c = idx & 3;
            uint32_t o = SW64_((uint32_t)(r * 64 + c * 16));
            size_t offa = (size_t)rid[r] * DM + kc + c * 8;
            size_t offb = (size_t)r * DM + kc + c * 8;
            cp16(sbase + OFFS_AH + o, g_whi + offa);
            cp16(sbase + OFFS_AL + o, g_wlo + offa);
            cp16(sbase + OFFS_BH + o, Ph + offb);
            cp16(sbase + OFFS_BL + o, Pl + offb);
        }
        CP_COMMIT();
    };

    load_slab(0, 0);
    load_slab(KSLAB, 1);
#pragma unroll 1
    for (int ch = 0; ch < NSLAB; ch++) {
        if (ch + 2 < NSLAB) { load_slab((ch + 2) * KSLAB, (ch + 2) % 3); CP_WAIT2(); }
        else if (ch + 1 < NSLAB) { CP_WAIT1(); }
        else { CP_WAIT0(); }
        __syncthreads();
        uint32_t sbase = sb + (ch % 3) * STG_BYTES;
#pragma unroll
        for (int ks = 0; ks < 2; ks++) {
            uint32_t ah[2][4], al[2][4];
#pragma unroll
            for (int mt = 0; mt < 2; mt++) {
                uint32_t off = SW64_((uint32_t)((a_row + mt * 16) * 64 + ks * 32 + a_u * 16));
                ldsm4(ah[mt], sbase + OFFS_AH + off);
                ldsm4(al[mt], sbase + OFFS_AL + off);
            }
#pragma unroll
            for (int np = 0; np < 4; np++) {
                uint32_t bh[4], bl[4];
                uint32_t boff = SW64_((uint32_t)((b_row + np * 16) * 64 + ks * 32 + b_u * 16));
                ldsm4(bh, sbase + OFFS_BH + boff);
                ldsm4(bl, sbase + OFFS_BL + boff);
#pragma unroll
                for (int mt = 0; mt < 2; mt++) {
                    mma16816(acc[mt][np * 2 + 0], ah[mt], bh[0], bh[1]);
                    mma16816(acc[mt][np * 2 + 0], ah[mt], bl[0], bl[1]);
                    mma16816(acc[mt][np * 2 + 0], al[mt], bh[0], bh[1]);
                    mma16816(acc[mt][np * 2 + 1], ah[mt], bh[2], bh[3]);
                    mma16816(acc[mt][np * 2 + 1], ah[mt], bl[2], bl[3]);
                    mma16816(acc[mt][np * 2 + 1], al[mt], bh[2], bh[3]);
                }
            }
        }
        __syncthreads();
    }
    int g = lane >> 2, tig = lane & 3;
#pragma unroll
    for (int mt = 0; mt < 2; mt++)
#pragma unroll
        for (int nt = 0; nt < 8; nt++) {
            int ml = wm + mt * 16 + g;
            int c = col0 + wn + nt * 8 + tig * 2;
            if (ml < nr)
                *(float2*)(out + (size_t)rid[ml] * DM + c) =
                    make_float2(acc[mt][nt][0], acc[mt][nt][1]);
            if (ml + 8 < nr)
                *(float2*)(out + (size_t)rid[ml + 8] * DM + c) =
                    make_float2(acc[mt][nt][2], acc[mt][nt][3]);
        }
}

extern "C" void kernel_launch(void* const* d_in, const int* in_sizes, int n_in,
                              void* d_out, int out_size) {
    const float* x    = (const float*)d_in[0];
    const int*   bi   = (const int*)d_in[1];
    const float* son  = (const float*)d_in[2];
    const int*   sbi  = (const int*)d_in[3];
    const float* temp = (const float*)d_in[4];
    const float* Wfx  = (const float*)d_in[5];
    const float* bfx  = (const float*)d_in[6];
    const float* Wx   = (const float*)d_in[7];
    const float* bx   = (const float*)d_in[8];
    const float* Wsl  = (const float*)d_in[9];
    const float* bsl  = (const float*)d_in[10];
    const float* Wq   = (const float*)d_in[11];
    const float* bq   = (const float*)d_in[12];
    const float* Wk   = (const float*)d_in[13];
    const float* bk   = (const float*)d_in[14];
    const float* Wv   = (const float*)d_in[15];
    const float* bv   = (const float*)d_in[16];
    const float* Wck  = (const float*)d_in[17];
    const float* bck  = (const float*)d_in[18];
    const float* Wcv  = (const float*)d_in[19];
    const float* bcv  = (const float*)d_in[20];
    const float* Wout = (const float*)d_in[21];
    float* out = (float*)d_out;

    static cudaStream_t s1 = nullptr, s2 = nullptr;
    static cudaEvent_t eF = nullptr, e1 = nullptr, e2a = nullptr, e2b = nullptr;
    if (s1 == nullptr) {
        cudaStreamCreateWithFlags(&s1, cudaStreamNonBlocking);
        cudaStreamCreateWithFlags(&s2, cudaStreamNonBlocking);
        cudaEventCreateWithFlags(&eF, cudaEventDisableTiming);
        cudaEventCreateWithFlags(&e1, cudaEventDisableTiming);
        cudaEventCreateWithFlags(&e2a, cudaEventDisableTiming);
        cudaEventCreateWithFlags(&e2b, cudaEventDisableTiming);
        cudaFuncSetAttribute(k_gemm_mma, cudaFuncAttributeMaxDynamicSharedMemorySize, SMEM_MMA);
        cudaFuncSetAttribute(k_final_mma, cudaFuncAttributeMaxDynamicSharedMemorySize, SMEM_MMA);
        cudaFuncSetAttribute(k_qkvattn, cudaFuncAttributeMaxDynamicSharedMemorySize, QKV_SMEM);
    }

    // fork
    cudaEventRecord(eF, 0);
    cudaStreamWaitEvent(s1, eF, 0);
    cudaStreamWaitEvent(s2, eF, 0);

    // stream s1: batch bucketing chain (independent of x path)
    k_zero<<<1024, 256, 0, s1>>>();
    k_count<<<80, 256, 0, s1>>>(bi, sbi);
    k_prefix<<<1, 1, 0, s1>>>();
    k_scatter<<<80, 256, 0, s1>>>(bi, sbi);
    cudaEventRecord(e1, s1);

    // stream s2: weight transpose (feeds gemm), then sonata K/V projection
    k_wcomb<<<dim3(512, 2), 256, 0, s2>>>(Wx, Wsl, Wfx);
    cudaEventRecord(e2a, s2);
    k_skv<<<dim3(512, 2), 256, 0, s2>>>(son, Wck, bck, Wcv, bcv);
    cudaEventRecord(e2b, s2);

    // main stream
    k_bcomb<<<1, 512>>>(bx, Wsl, bsl);
    k_cvt_x<<<8192, 256>>>(x);
    cudaStreamWaitEvent(0, e2a, 0);
    k_gemm_mma<<<dim3(8, 128), 256, SMEM_MMA>>>(bfx, temp);
    cudaStreamWaitEvent(0, e1, 0);
    k_tokens<<<dim3(64, 32), 256>>>();
    k_qkvattn<<<64, 256, QKV_SMEM>>>(Wq, bq, Wk, bk, Wv, bv);
    cudaStreamWaitEvent(0, e2b, 0);
    k_cross_score<<<dim3(64, 8), 256>>>();
    k_cross_stat<<<64, 256>>>();
    k_cross_out<<<dim3(64, 8), 256>>>();
    k_P<<<dim3(64, 8), 256>>>(Wout);
    k_final_mma<<<dim3(4, 128, 8), 256, SMEM_MMA>>>(out);
}

// round 14
// speedup vs baseline: 2.8963x; 1.0528x over previous
#include <cuda_runtime.h>
#include <cuda_bf16.h>
#include <cstdint>

#define NT 16384   // x rows
#define MS 4096    // sonata rows
#define NB 8       // batches
#define NH 8       // heads
#define DH 64      // head dim
#define NG 64      // slice groups
#define DM 512     // model dim
#define SCL 0.125f // D^-0.5

#define SW64_(o) ((o) ^ (((o) >> 3) & 0x30))

__device__ __forceinline__ uint32_t smem_to_u32(const void* p) {
    uint32_t a;
    asm("{ .reg .u64 tmp; cvta.to.shared.u64 tmp, %1; cvt.u32.u64 %0, tmp; }"
        : "=r"(a) : "l"(p));
    return a;
}
__device__ __forceinline__ void ldsm4(uint32_t a[4], uint32_t addr) {
    asm volatile("ldmatrix.sync.aligned.m8n8.x4.shared.b16 {%0,%1,%2,%3}, [%4];"
                 : "=r"(a[0]), "=r"(a[1]), "=r"(a[2]), "=r"(a[3]) : "r"(addr));
}
__device__ __forceinline__ void mma16816(float c[4], const uint32_t a[4],
                                         uint32_t b0, uint32_t b1) {
    asm volatile(
        "mma.sync.aligned.m16n8k16.row.col.f32.bf16.bf16.f32 "
        "{%0,%1,%2,%3}, {%4,%5,%6,%7}, {%8,%9}, {%0,%1,%2,%3};"
        : "+f"(c[0]), "+f"(c[1]), "+f"(c[2]), "+f"(c[3])
        : "r"(a[0]), "r"(a[1]), "r"(a[2]), "r"(a[3]), "r"(b0), "r"(b1));
}
__device__ __forceinline__ void cp16(uint32_t dst, const void* src) {
    asm volatile("cp.async.cg.shared.global [%0], [%1], 16;" :: "r"(dst), "l"(src));
}
#define CP_COMMIT() asm volatile("cp.async.commit_group;" ::: "memory")
#define CP_WAIT2() asm volatile("cp.async.wait_group 2;" ::: "memory")
#define CP_WAIT1() asm volatile("cp.async.wait_group 1;" ::: "memory")
#define CP_WAIT0() asm volatile("cp.async.wait_group 0;" ::: "memory")

__device__ __forceinline__ void bsplit(float v, __nv_bfloat16& h, __nv_bfloat16& l) {
    h = __float2bfloat16(v);
    l = __float2bfloat16(v - __bfloat162float(h));
}

// pipelined MMA smem: 3 stages x (AH 8K | AL 8K | BH 8K | BL 8K) = 96KB
#define STG_BYTES 32768
#define OFFS_AH 0
#define OFFS_AL 8192
#define OFFS_BH 16384
#define OFFS_BL 24576
#define SMEM_MMA (3 * STG_BYTES)
#define KSLAB 32
#define NSLAB (DM / KSLAB)

// fused qkv+attn smem: a[64][65] + 3x W[64][64] + q,k,v[64][64] + s[64][64]
#define QKV_SMEM ((64 * 65 + 3 * 4096 + 3 * 4096 + 4096) * 4)

// ---------------- device scratch ----------------
__device__ float g_bcomb[DM];
__device__ float g_fx[(size_t)NT * DM];
__device__ float g_w[(size_t)NT * DM];
__device__ __nv_bfloat16 g_xhi[(size_t)NT * DM], g_xlo[(size_t)NT * DM];
__device__ __nv_bfloat16 g_Bthi[(size_t)2 * DM * DM], g_Btlo[(size_t)2 * DM * DM]; // [1024][512]
__device__ __nv_bfloat16 g_whi[(size_t)NT * DM], g_wlo[(size_t)NT * DM];
__device__ __nv_bfloat16 g_Pthi[(size_t)NB * DM * DM], g_Ptlo[(size_t)NB * DM * DM]; // [b][c][k]
__device__ float g_tokens[NB * NH * NG * DH];
__device__ float g_norms[NB * NH * NG];
__device__ float g_outtok[NB * NH * NG * DH];
__device__ float g_ks[(size_t)MS * DM];
__device__ float g_vs[(size_t)MS * DM];
__device__ float g_scores[(size_t)NB * NH * NG * MS];
__device__ float2 g_cstats[NB * NH * NG];   // per-(bh,g) softmax (m, inv)
__device__ int g_rowlist[NT], g_rowcnt[NB], g_rowstart[NB + 1], g_rowcur[NB];
__device__ int g_mlist[MS], g_mcnt[NB], g_mstart[NB + 1], g_mcur[NB];

// ---------------- setup kernels ----------------
__global__ void k_zero() {
    int i = blockIdx.x * 256 + threadIdx.x;
    if (i < NB * NH * NG * DH) g_tokens[i] = 0.f;
    if (i < NB * NH * NG) g_norms[i] = 0.f;
    if (i < NB) {
        g_rowcnt[i] = 0; g_mcnt[i] = 0;
        g_rowcur[i] = 0; g_mcur[i] = 0;
    }
}

__global__ void k_bcomb(const float* __restrict__ bx, const float* __restrict__ Wsl,
                        const float* __restrict__ bsl) {
    int o = threadIdx.x;  // 512
    int h = o >> 6, g = o & 63;
    float acc = bsl[g];
    for (int d = 0; d < 64; d++) acc = fmaf(bx[h * 64 + d], Wsl[d * 64 + g], acc);
    g_bcomb[o] = acc;
}

// x fp32 -> bf16 hi/lo split
__global__ void k_cvt_x(const float* __restrict__ x) {
    size_t i = (size_t)blockIdx.x * 256 + threadIdx.x;  // one float4 each
    float4 v = ((const float4*)x)[i];
    __nv_bfloat16 h0, h1, h2, h3, l0, l1, l2, l3;
    bsplit(v.x, h0, l0); bsplit(v.y, h1, l1);
    bsplit(v.z, h2, l2); bsplit(v.w, h3, l3);
    ((__nv_bfloat162*)g_xhi)[i * 2 + 0] = __halves2bfloat162(h0, h1);
    ((__nv_bfloat162*)g_xhi)[i * 2 + 1] = __halves2bfloat162(h2, h3);
    ((__nv_bfloat162*)g_xlo)[i * 2 + 0] = __halves2bfloat162(l0, l1);
    ((__nv_bfloat162*)g_xlo)[i * 2 + 1] = __halves2bfloat162(l2, l3);
}

// y==1: Bt rows 0..511 (transposed Wfx); y==0: Bt rows 512..1023 from Wcomb = Wx·Wsl
__global__ void k_wcomb(const float* __restrict__ Wx, const float* __restrict__ Wsl,
                        const float* __restrict__ Wfx) {
    int c = blockIdx.x;  // 0..511
    int t = threadIdx.x;
    if (blockIdx.y == 1) {
        for (int k = t; k < DM; k += 256) {
            __nv_bfloat16 h, l;
            bsplit(Wfx[(size_t)k * DM + c], h, l);
            g_Bthi[(size_t)c * DM + k] = h;
            g_Btlo[(size_t)c * DM + k] = l;
        }
        return;
    }
    __shared__ float s_sl[4096];
    for (int i = t; i < 4096; i += 256) s_sl[i] = Wsl[i];
    __syncthreads();
    for (int o = t; o < 512; o += 256) {
        int h = o >> 6, g = o & 63;
        const float* wxr = Wx + (size_t)c * DM + h * 64;
        float acc = 0.f;
        for (int d = 0; d < 64; d++) acc = fmaf(wxr[d], s_sl[d * 64 + g], acc);
        __nv_bfloat16 hh, ll;
        bsplit(acc, hh, ll);
        g_Bthi[(size_t)(DM + o) * DM + c] = hh;
        g_Btlo[(size_t)(DM + o) * DM + c] = ll;
    }
}

__global__ void k_count(const int* __restrict__ bi, const int* __restrict__ sbi) {
    int i = blockIdx.x * 256 + threadIdx.x;
    if (i < NT) atomicAdd(&g_rowcnt[bi[i]], 1);
    else if (i < NT + MS) atomicAdd(&g_mcnt[sbi[i - NT]], 1);
}

__global__ void k_prefix() {
    if (threadIdx.x == 0) {
        int s = 0;
        for (int b = 0; b < NB; b++) { g_rowstart[b] = s; s += g_rowcnt[b]; }
        g_rowstart[NB] = s;
        s = 0;
        for (int b = 0; b < NB; b++) { g_mstart[b] = s; s += g_mcnt[b]; }
        g_mstart[NB] = s;
    }
}

__global__ void k_scatter(const int* __restrict__ bi, const int* __restrict__ sbi) {
    int i = blockIdx.x * 256 + threadIdx.x;
    if (i < NT) {
        int b = bi[i];
        int p = atomicAdd(&g_rowcur[b], 1);
        g_rowlist[g_rowstart[b] + p] = i;
    } else if (i < NT + MS) {
        int j = i - NT;
        int b = sbi[j];
        int p = atomicAdd(&g_mcur[b], 1);
        g_mlist[g_mstart[b] + p] = j;
    }
}

// ---------------- front GEMM via mma.sync bf16x3, 3-stage pipeline, fused slice-softmax ----------------
__global__ void __launch_bounds__(256, 2)
k_gemm_mma(const float* __restrict__ bfx, const float* __restrict__ temp) {
    extern __shared__ char dynsmem[];
    uint32_t sb = smem_to_u32(dynsmem);
    int t = threadIdx.x;
    int lane = t & 31, wid = t >> 5;
    int wm = (wid & 3) * 32, wn = (wid >> 2) * 64;
    int row0 = blockIdx.y * 128, col0 = blockIdx.x * 128;
    float acc[2][8][4] = {};
    int a_row = wm + (lane & 15);
    int a_u = lane >> 4;
    int b_row = wn + (lane & 7) + ((lane >> 4) << 3);
    int b_u = (lane >> 3) & 1;

    auto load_slab = [&](int kc, int stg) {
        uint32_t sbase = sb + stg * STG_BYTES;
#pragma unroll
        for (int half = 0; half < 2; half++) {
            int idx = half * 256 + t;
            int r = idx >> 2, c = idx & 3;
            uint32_t o = SW64_((uint32_t)(r * 64 + c * 16));
            size_t offa = (size_t)(row0 + r) * DM + kc + c * 8;
            size_t offb = (size_t)(col0 + r) * DM + kc + c * 8;
            cp16(sbase + OFFS_AH + o, g_xhi + offa);
            cp16(sbase + OFFS_AL + o, g_xlo + offa);
            cp16(sbase + OFFS_BH + o, g_Bthi + offb);
            cp16(sbase + OFFS_BL + o, g_Btlo + offb);
        }
        CP_COMMIT();
    };

    load_slab(0, 0);
    load_slab(KSLAB, 1);
#pragma unroll 1
    for (int ch = 0; ch < NSLAB; ch++) {
        if (ch + 2 < NSLAB) { load_slab((ch + 2) * KSLAB, (ch + 2) % 3); CP_WAIT2(); }
        else if (ch + 1 < NSLAB) { CP_WAIT1(); }
        else { CP_WAIT0(); }
        __syncthreads();
        uint32_t sbase = sb + (ch % 3) * STG_BYTES;
#pragma unroll
        for (int ks = 0; ks < 2; ks++) {
            uint32_t ah[2][4], al[2][4];
#pragma unroll
            for (int mt = 0; mt < 2; mt++) {
                uint32_t off = SW64_((uint32_t)((a_row + mt * 16) * 64 + ks * 32 + a_u * 16));
                ldsm4(ah[mt], sbase + OFFS_AH + off);
                ldsm4(al[mt], sbase + OFFS_AL + off);
            }
#pragma unroll
            for (int np = 0; np < 4; np++) {
                uint32_t bh[4], bl[4];
                uint32_t boff = SW64_((uint32_t)((b_row + np * 16) * 64 + ks * 32 + b_u * 16));
                ldsm4(bh, sbase + OFFS_BH + boff);
                ldsm4(bl, sbase + OFFS_BL + boff);
#pragma unroll
                for (int mt = 0; mt < 2; mt++) {
                    mma16816(acc[mt][np * 2 + 0], ah[mt], bh[0], bh[1]);
                    mma16816(acc[mt][np * 2 + 0], ah[mt], bl[0], bl[1]);
                    mma16816(acc[mt][np * 2 + 0], al[mt], bh[0], bh[1]);
                    mma16816(acc[mt][np * 2 + 1], ah[mt], bh[2], bh[3]);
                    mma16816(acc[mt][np * 2 + 1], ah[mt], bl[2], bl[3]);
                    mma16816(acc[mt][np * 2 + 1], al[mt], bh[2], bh[3]);
                }
            }
        }
        __syncthreads();
    }
    int g = lane >> 2, tig = lane & 3;
    bool isfx = (col0 < DM);
    if (isfx) {
#pragma unroll
        for (int mt = 0; mt < 2; mt++)
#pragma unroll
            for (int nt = 0; nt < 8; nt++) {
                int r1 = row0 + wm + mt * 16 + g;
                int c = col0 + wn + nt * 8 + tig * 2;
                float b0v = bfx[c], b1v = bfx[c + 1];
                *(float2*)(g_fx + (size_t)r1 * DM + c) =
                    make_float2(acc[mt][nt][0] + b0v, acc[mt][nt][1] + b1v);
                *(float2*)(g_fx + (size_t)(r1 + 8) * DM + c) =
                    make_float2(acc[mt][nt][2] + b0v, acc[mt][nt][3] + b1v);
            }
    } else {
        // fused slice softmax: this warp's 64 cols == one head; each row's 64
        // logits live in the 4 lanes sharing g (tig 0..3), 16 values each.
        int cbase = col0 - DM;
        int h = (cbase + wn) >> 6;
        float it = 1.f / temp[h];
#pragma unroll
        for (int mt = 0; mt < 2; mt++)
#pragma unroll
            for (int half = 0; half < 2; half++) {
                int r1 = row0 + wm + mt * 16 + g + half * 8;
                float v[16];
#pragma unroll
                for (int nt = 0; nt < 8; nt++) {
                    int c = cbase + wn + nt * 8 + tig * 2;
                    v[nt * 2 + 0] = (acc[mt][nt][half * 2 + 0] + g_bcomb[c]) * it;
                    v[nt * 2 + 1] = (acc[mt][nt][half * 2 + 1] + g_bcomb[c + 1]) * it;
                }
                float m = v[0];
#pragma unroll
                for (int i = 1; i < 16; i++) m = fmaxf(m, v[i]);
                m = fmaxf(m, __shfl_xor_sync(0xFFFFFFFFu, m, 1));
                m = fmaxf(m, __shfl_xor_sync(0xFFFFFFFFu, m, 2));
                float s = 0.f;
#pragma unroll
                for (int i = 0; i < 16; i++) { v[i] = __expf(v[i] - m); s += v[i]; }
                s += __shfl_xor_sync(0xFFFFFFFFu, s, 1);
                s += __shfl_xor_sync(0xFFFFFFFFu, s, 2);
                float inv = 1.f / s;
#pragma unroll
                for (int nt = 0; nt < 8; nt++) {
                    int cw = cbase + wn + nt * 8 + tig * 2;
                    float w0 = v[nt * 2 + 0] * inv, w1 = v[nt * 2 + 1] * inv;
                    *(float2*)(g_w + (size_t)r1 * DM + cw) = make_float2(w0, w1);
                    __nv_bfloat16 h0, l0, h1, l1;
                    bsplit(w0, h0, l0); bsplit(w1, h1, l1);
                    *(__nv_bfloat162*)(g_whi + (size_t)r1 * DM + cw) = __halves2bfloat162(h0, h1);
                    *(__nv_bfloat162*)(g_wlo + (size_t)r1 * DM + cw) = __halves2bfloat162(l0, l1);
                }
            }
    }
}

// tokens[b,h,g,d] = sum_{n in b} w[n,h,g] * fx[n,h,d]; norms[b,h,g] = sum w
// grid (64 bh, 32 row-slices)
__global__ void k_tokens() {
    int bh = blockIdx.x;
    int b = bh >> 3, h = bh & 7;
    int cnt = g_rowcnt[b], start = g_rowstart[b];
    int c0 = (int)(((long long)cnt * blockIdx.y) >> 5);
    int c1 = (int)(((long long)cnt * (blockIdx.y + 1)) >> 5);
    int t = threadIdx.x;
    int tg = (t >> 4) * 4, td = (t & 15) * 4;
    float acc[4][4] = {};
    float nacc[4] = {};
    __shared__ float ws[16][64], fs[16][64];
    __shared__ int rid[16];
    for (int i0 = c0; i0 < c1; i0 += 16) {
        int nr = c1 - i0; if (nr > 16) nr = 16;
        if (t < nr) rid[t] = g_rowlist[start + i0 + t];
        __syncthreads();
        for (int idx = t; idx < nr * 64; idx += 256) {
            int r = idx >> 6, c = idx & 63;
            size_t off = (size_t)rid[r] * DM + h * 64 + c;
            ws[r][c] = g_w[off];
            fs[r][c] = g_fx[off];
        }
        __syncthreads();
        for (int r = 0; r < nr; r++) {
            float wv[4], fv[4];
#pragma unroll
            for (int i = 0; i < 4; i++) { wv[i] = ws[r][tg + i]; fv[i] = fs[r][td + i]; }
#pragma unroll
            for (int i = 0; i < 4; i++) {
                if (td == 0) nacc[i] += wv[i];
#pragma unroll
                for (int j = 0; j < 4; j++) acc[i][j] = fmaf(wv[i], fv[j], acc[i][j]);
            }
        }
        __syncthreads();
    }
    float* tok = g_tokens + (size_t)bh * NG * DH;
#pragma unroll
    for (int i = 0; i < 4; i++) {
#pragma unroll
        for (int j = 0; j < 4; j++) atomicAdd(&tok[(tg + i) * DH + td + j], acc[i][j]);
        if (td == 0) atomicAdd(&g_norms[bh * NG + tg + i], nacc[i]);
    }
}

// fused q/k/v projection + 64x64 self-attention per (b,h); W prefetched via cp.async
__global__ void k_qkvattn(const float* __restrict__ Wq, const float* __restrict__ bq,
                          const float* __restrict__ Wk, const float* __restrict__ bk,
                          const float* __restrict__ Wv, const float* __restrict__ bv) {
    int bh = blockIdx.x;
    extern __shared__ float fsm[];
    float* s_a = fsm;                 // [64][65]
    float* s_w = fsm + 64 * 65;       // 3 x [64][64]
    float* s_q = s_w + 3 * 4096;
    float* s_k = s_q + 4096;
    float* s_v = s_k + 4096;
    float* s_s = s_v + 4096;          // scores
    uint32_t sb = smem_to_u32(fsm);
    int t = threadIdx.x;
    // prefetch Wq, Wk, Wv (one commit group each)
    const float* Ws[3] = {Wq, Wk, Wv};
    const float* bs[3] = {bq, bk, bv};
#pragma unroll
    for (int p = 0; p < 3; p++) {
        uint32_t dst = sb + (uint32_t)(64 * 65 + p * 4096) * 4;
        for (int i = t; i < 1024; i += 256)
            cp16(dst + i * 16, (const char*)Ws[p] + i * 16);
        CP_COMMIT();
    }
    for (int i = t; i < 4096; i += 256) {
        int g = i >> 6, d = i & 63;
        s_a[g * 65 + d] = g_tokens[(size_t)bh * 4096 + i] / (g_norms[bh * 64 + g] + 1e-5f);
    }
    int tx = t & 15, ty = t >> 4;
    float* outs[3] = {s_q, s_k, s_v};
#pragma unroll 1
    for (int p = 0; p < 3; p++) {
        if (p == 0) CP_WAIT2();
        else if (p == 1) CP_WAIT1();
        else CP_WAIT0();
        __syncthreads();
        const float* wp = s_w + p * 4096;
        float acc[4][4] = {};
        for (int k = 0; k < 64; k++) {
            float av[4], bv2[4];
#pragma unroll
            for (int i = 0; i < 4; i++) av[i] = s_a[(ty * 4 + i) * 65 + k];
#pragma unroll
            for (int j = 0; j < 4; j++) bv2[j] = wp[k * 64 + tx * 4 + j];
#pragma unroll
            for (int i = 0; i < 4; i++)
#pragma unroll
                for (int j = 0; j < 4; j++) acc[i][j] = fmaf(av[i], bv2[j], acc[i][j]);
        }
#pragma unroll
        for (int i = 0; i < 4; i++)
#pragma unroll
            for (int j = 0; j < 4; j++)
                outs[p][(ty * 4 + i) * 64 + tx * 4 + j] = acc[i][j] + bs[p][tx * 4 + j];
    }
    __syncthreads();
    // scores = q k^T * SCL into s_s
    {
        float acc[4][4] = {};
        for (int d = 0; d < 64; d++) {
            float av[4], bv2[4];
#pragma unroll
            for (int i = 0; i < 4; i++) av[i] = s_q[(ty * 4 + i) * 64 + d];
#pragma unroll
            for (int j = 0; j < 4; j++) bv2[j] = s_k[(tx * 4 + j) * 64 + d];
#pragma unroll
            for (int i = 0; i < 4; i++)
#pragma unroll
                for (int j = 0; j < 4; j++) acc[i][j] = fmaf(av[i], bv2[j], acc[i][j]);
        }
#pragma unroll
        for (int i = 0; i < 4; i++)
#pragma unroll
            for (int j = 0; j < 4; j++)
                s_s[(ty * 4 + i) * 64 + tx * 4 + j] = acc[i][j] * SCL;
    }
    __syncthreads();
    if (t < 64) {
        float m = -1e30f;
        for (int j = 0; j < 64; j++) m = fmaxf(m, s_s[t * 64 + j]);
        float s = 0.f;
        for (int j = 0; j < 64; j++) { float e = __expf(s_s[t * 64 + j] - m); s_s[t * 64 + j] = e; s += e; }
        float inv = 1.f / s;
        for (int j = 0; j < 64; j++) s_s[t * 64 + j] *= inv;
    }
    __syncthreads();
    float acc[4][4] = {};
    for (int k2 = 0; k2 < 64; k2++) {
        float av[4], bv2[4];
#pragma unroll
        for (int i = 0; i < 4; i++) av[i] = s_s[(ty * 4 + i) * 64 + k2];
#pragma unroll
        for (int j = 0; j < 4; j++) bv2[j] = s_v[k2 * 64 + tx * 4 + j];
#pragma unroll
        for (int i = 0; i < 4; i++)
#pragma unroll
            for (int j = 0; j < 4; j++) acc[i][j] = fmaf(av[i], bv2[j], acc[i][j]);
    }
#pragma unroll
    for (int i = 0; i < 4; i++)
#pragma unroll
        for (int j = 0; j < 4; j++)
            g_outtok[(size_t)bh * 4096 + (ty * 4 + i) * 64 + tx * 4 + j] = acc[i][j];
}

// sonata ks/vs projection: [32768x64] @ [64x64] + bias
__global__ void k_skv(const float* __restrict__ son,
                      const float* __restrict__ Wck, const float* __restrict__ bck,
                      const float* __restrict__ Wcv, const float* __restrict__ bcv) {
    int rt = blockIdx.x;
    int sel = blockIdx.y;
    const float* W = sel ? Wcv : Wck;
    const float* bias = sel ? bcv : bck;
    float* dst = sel ? g_vs : g_ks;
    __shared__ float s_at[64][65];
    __shared__ float s_b[64][64];
    int t = threadIdx.x;
    size_t base = (size_t)rt * 64 * 64;
    for (int i = t; i < 4096; i += 256) {
        s_at[i & 63][i >> 6] = son[base + i];
        s_b[i >> 6][i & 63] = W[i];
    }
    __syncthreads();
    int tx = t & 15, ty = t >> 4;
    float acc[4][4] = {};
    for (int k = 0; k < 64; k++) {
        float av[4], bv2[4];
#pragma unroll
        for (int i = 0; i < 4; i++) av[i] = s_at[k][ty * 4 + i];
#pragma unroll
        for (int j = 0; j < 4; j++) bv2[j] = s_b[k][tx * 4 + j];
#pragma unroll
        for (int i = 0; i < 4; i++)
#pragma unroll
            for (int j = 0; j < 4; j++) acc[i][j] = fmaf(av[i], bv2[j], acc[i][j]);
    }
#pragma unroll
    for (int i = 0; i < 4; i++)
#pragma unroll
        for (int j = 0; j < 4; j++)
            dst[base + (size_t)(ty * 4 + i) * 64 + tx * 4 + j] = acc[i][j] + bias[tx * 4 + j];
}

// cross-attention scores: grid (64 bh, 8 j-slices); microtiled + coalesced stores
__global__ void k_cross_score() {
    int bh = blockIdx.x, b = bh >> 3, h = bh & 7;
    int cnt = g_mcnt[b], start = g_mstart[b];
    if (cnt == 0) return;
    int sl = blockIdx.y;
    int lo = (int)(((long long)cnt * sl) >> 3);
    int hi = (int)(((long long)cnt * (sl + 1)) >> 3);
    if (lo >= hi) return;
    __shared__ float s_q[64][65];
    __shared__ float s_kv[32][68];
    __shared__ float s_sc[64][33];
    __shared__ int mid[32];
    int t = threadIdx.x;
    int tx = t & 15, ty = t >> 4;
    for (int i = t; i < 4096; i += 256) s_q[i >> 6][i & 63] = g_outtok[(size_t)bh * 4096 + i];
    __syncthreads();
    float* sc = g_scores + (size_t)bh * 64 * MS;
    for (int j0 = lo; j0 < hi; j0 += 32) {
        int nj = hi - j0; if (nj > 32) nj = 32;
        if (t < nj) mid[t] = g_mlist[start + j0 + t];
        __syncthreads();
        for (int i = t; i < nj * 64; i += 256) {
            int r = i >> 6, c = i & 63;
            s_kv[r][c] = g_ks[(size_t)mid[r] * DM + h * 64 + c];
        }
        __syncthreads();
        // 4g x 2j microtile per thread; arithmetic per output identical to before
        float acc[4][2] = {};
        int j1 = tx * 2;
        for (int d = 0; d < 64; d++) {
            float bv0 = s_kv[j1][d], bv1 = s_kv[j1 + 1][d];
#pragma unroll
            for (int i = 0; i < 4; i++) {
                float q = s_q[ty * 4 + i][d];
                acc[i][0] = fmaf(q, bv0, acc[i][0]);
                acc[i][1] = fmaf(q, bv1, acc[i][1]);
            }
        }
#pragma unroll
        for (int i = 0; i < 4; i++) {
            s_sc[ty * 4 + i][j1] = acc[i][0] * SCL;
            s_sc[ty * 4 + i][j1 + 1] = acc[i][1] * SCL;
        }
        __syncthreads();
        for (int i = t; i < 64 * 32; i += 256) {
            int g = i >> 5, j = i & 31;
            if (j < nj) sc[(size_t)g * MS + j0 + j] = s_sc[g][j];
        }
        __syncthreads();
    }
}

// cross-attention softmax stats only: grid (64 bh); writes (m, inv) per row
__global__ void k_cross_stat() {
    int bh = blockIdx.x, b = bh >> 3;
    int cnt = g_mcnt[b];
    if (cnt == 0) return;
    float* sc = g_scores + (size_t)bh * 64 * MS;
    int warp = threadIdx.x >> 5, lane = threadIdx.x & 31;
    for (int g = warp * 8; g < warp * 8 + 8; g++) {
        float* row = sc + (size_t)g * MS;
        float m = -1e30f;
        for (int j = lane; j < cnt; j += 32) m = fmaxf(m, row[j]);
#pragma unroll
        for (int o = 16; o; o >>= 1) m = fmaxf(m, __shfl_xor_sync(0xFFFFFFFFu, m, o));
        float s = 0.f;
        for (int j = lane; j < cnt; j += 32) s += __expf(row[j] - m);
#pragma unroll
        for (int o = 16; o; o >>= 1) s += __shfl_xor_sync(0xFFFFFFFFu, s, o);
        if (lane == 0) g_cstats[bh * 64 + g] = make_float2(m, 1.f / s);
    }
}

// cross-attention output: grid (64 bh, 8 j-slices); applies exp inline, atomic accumulate
__global__ void k_cross_out() {
    int bh = blockIdx.x, b = bh >> 3, h = bh & 7;
    int cnt = g_mcnt[b], start = g_mstart[b];
    if (cnt == 0) return;
    int sl = blockIdx.y;
    int lo = (int)(((long long)cnt * sl) >> 3);
    int hi = (int)(((long long)cnt * (sl + 1)) >> 3);
    if (lo >= hi) return;
    __shared__ float s_kv[32][64];
    __shared__ float s_cw[64][33];
    __shared__ float2 s_st[64];
    __shared__ int mid[32];
    int t = threadIdx.x;
    int tx = t & 15, ty = t >> 4;
    if (t < 64) s_st[t] = g_cstats[bh * 64 + t];
    const float* sc = g_scores + (size_t)bh * 64 * MS;
    float acc[4][4] = {};
    for (int j0 = lo; j0 < hi; j0 += 32) {
        int nj = hi - j0; if (nj > 32) nj = 32;
        if (t < nj) mid[t] = g_mlist[start + j0 + t];
        __syncthreads();
        for (int i = t; i < nj * 64; i += 256) {
            int r = i >> 6, c = i & 63;
            s_kv[r][c] = g_vs[(size_t)mid[r] * DM + h * 64 + c];
        }
        for (int i = t; i < 64 * 32; i += 256) {
            int g = i >> 5, j = i & 31;
            float2 st = s_st[g];
            s_cw[g][j] = (j < nj) ? __expf(sc[(size_t)g * MS + j0 + j] - st.x) * st.y : 0.f;
        }
        __syncthreads();
        for (int j = 0; j < nj; j++) {
            float vvv[4];
#pragma unroll
            for (int jj = 0; jj < 4; jj++) vvv[jj] = s_kv[j][tx * 4 + jj];
#pragma unroll
            for (int i = 0; i < 4; i++) {
                float c = s_cw[ty * 4 + i][j];
#pragma unroll
                for (int jj = 0; jj < 4; jj++) acc[i][jj] = fmaf(c, vvv[jj], acc[i][jj]);
            }
        }
        __syncthreads();
    }
#pragma unroll
    for (int i = 0; i < 4; i++)
#pragma unroll
        for (int jj = 0; jj < 4; jj++)
            atomicAdd(&g_outtok[(size_t)bh * 4096 + (ty * 4 + i) * 64 + tx * 4 + jj], acc[i][jj]);
}

// P[b, h*64+g, c] = sum_d out_tok[b,h,g,d] * W_out[h*64+d, c], stored transposed bf16 hi/lo
__global__ void k_P(const float* __restrict__ Wout) {
    int bh = blockIdx.x, b = bh >> 3, h = bh & 7;
    int col0 = blockIdx.y * 64;
    __shared__ float s_a[64][65];
    __shared__ float s_b[64][64];
    int t = threadIdx.x;
    for (int i = t; i < 4096; i += 256) {
        int r = i >> 6, c = i & 63;
        s_a[r][c] = g_outtok[(size_t)bh * 4096 + i];
        s_b[r][c] = Wout[(size_t)(h * 64 + r) * DM + col0 + c];
    }
    __syncthreads();
    int tx = t & 15, ty = t >> 4;
    float acc[4][4] = {};
    for (int d = 0; d < 64; d++) {
        float av[4], bv[4];
#pragma unroll
        for (int i = 0; i < 4; i++) av[i] = s_a[ty * 4 + i][d];
#pragma unroll
        for (int j = 0; j < 4; j++) bv[j] = s_b[d][tx * 4 + j];
#pragma unroll
        for (int i = 0; i < 4; i++)
#pragma unroll
            for (int j = 0; j < 4; j++) acc[i][j] = fmaf(av[i], bv[j], acc[i][j]);
    }
#pragma unroll
    for (int i = 0; i < 4; i++)
#pragma unroll
        for (int j = 0; j < 4; j++) {
            int r = h * 64 + ty * 4 + i;       // k index of P
            int c = col0 + tx * 4 + j;         // output col
            __nv_bfloat16 hh, ll;
            bsplit(acc[i][j], hh, ll);
            g_Pthi[((size_t)b * DM + c) * DM + r] = hh;
            g_Ptlo[((size_t)b * DM + c) * DM + r] = ll;
        }
}

// out[n, :] = w[n, :] @ P[batch(n)] via mma.sync bf16x3, gathered rows, 3-stage pipeline
__global__ void __launch_bounds__(256, 2)
k_final_mma(float* __restrict__ out) {
    int b = blockIdx.z;
    int cnt = g_rowcnt[b];
    int r0 = blockIdx.y * 128;
    if (r0 >= cnt) return;
    int nr = cnt - r0; if (nr > 128) nr = 128;
    extern __shared__ char dynsmem[];
    uint32_t sb = smem_to_u32(dynsmem);
    __shared__ int rid[128];
    int t = threadIdx.x;
    int lane = t & 31, wid = t >> 5;
    int wm = (wid & 3) * 32, wn = (wid >> 2) * 64;
    int col0 = blockIdx.x * 128;
    int start = g_rowstart[b];
    if (t < 128) rid[t] = g_rowlist[start + r0 + (t < nr ? t : nr - 1)];
    __syncthreads();
    float acc[2][8][4] = {};
    int a_row = wm + (lane & 15);
    int a_u = lane >> 4;
    int b_row = wn + (lane & 7) + ((lane >> 4) << 3);
    int b_u = (lane >> 3) & 1;
    const __nv_bfloat16* Ph = g_Pthi + ((size_t)b * DM + col0) * DM;
    const __nv_bfloat16* Pl = g_Ptlo + ((size_t)b * DM + col0) * DM;

    auto load_slab = [&](int kc, int stg) {
        uint32_t sbase = sb + stg * STG_BYTES;
#pragma unroll
        for (int half = 0; half < 2; half++) {
            int idx = half * 256 + t;
            int r = idx >> 2, c = idx & 3;
            uint32_t o = SW64_((uint32_t)(r * 64 + c * 16));
            size_t offa = (size_t)rid[r] * DM + kc + c * 8;
            size_t offb = (size_t)r * DM + kc + c * 8;
            cp16(sbase + OFFS_AH + o, g_whi + offa);
            cp16(sbase + OFFS_AL + o, g_wlo + offa);
            cp16(sbase + OFFS_BH + o, Ph + offb);
            cp16(sbase + OFFS_BL + o, Pl + offb);
        }
        CP_COMMIT();
    };

    load_slab(0, 0);
    load_slab(KSLAB, 1);
#pragma unroll 1
    for (int ch = 0; ch < NSLAB; ch++) {
        if (ch + 2 < NSLAB) { load_slab((ch + 2) * KSLAB, (ch + 2) % 3); CP_WAIT2(); }
        else if (ch + 1 < NSLAB) { CP_WAIT1(); }
        else { CP_WAIT0(); }
        __syncthreads();
        uint32_t sbase = sb + (ch % 3) * STG_BYTES;
#pragma unroll
        for (int ks = 0; ks < 2; ks++) {
            uint32_t ah[2][4], al[2][4];
#pragma unroll
            for (int mt = 0; mt < 2; mt++) {
                uint32_t off = SW64_((uint32_t)((a_row + mt * 16) * 64 + ks * 32 + a_u * 16));
                ldsm4(ah[mt], sbase + OFFS_AH + off);
                ldsm4(al[mt], sbase + OFFS_AL + off);
            }
#pragma unroll
            for (int np = 0; np < 4; np++) {
                uint32_t bh[4], bl[4];
                uint32_t boff = SW64_((uint32_t)((b_row + np * 16) * 64 + ks * 32 + b_u * 16));
                ldsm4(bh, sbase + OFFS_BH + boff);
                ldsm4(bl, sbase + OFFS_BL + boff);
#pragma unroll
                for (int mt = 0; mt < 2; mt++) {
                    mma16816(acc[mt][np * 2 + 0], ah[mt], bh[0], bh[1]);
                    mma16816(acc[mt][np * 2 + 0], ah[mt], bl[0], bl[1]);
                    mma16816(acc[mt][np * 2 + 0], al[mt], bh[0], bh[1]);
                    mma16816(acc[mt][np * 2 + 1], ah[mt], bh[2], bh[3]);
                    mma16816(acc[mt][np * 2 + 1], ah[mt], bl[2], bl[3]);
                    mma16816(acc[mt][np * 2 + 1], al[mt], bh[2], bh[3]);
                }
            }
        }
        __syncthreads();
    }
    int g = lane >> 2, tig = lane & 3;
#pragma unroll
    for (int mt = 0; mt < 2; mt++)
#pragma unroll
        for (int nt = 0; nt < 8; nt++) {
            int ml = wm + mt * 16 + g;
            int c = col0 + wn + nt * 8 + tig * 2;
            if (ml < nr)
                *(float2*)(out + (size_t)rid[ml] * DM + c) =
                    make_float2(acc[mt][nt][0], acc[mt][nt][1]);
            if (ml + 8 < nr)
                *(float2*)(out + (size_t)rid[ml + 8] * DM + c) =
                    make_float2(acc[mt][nt][2], acc[mt][nt][3]);
        }
}

extern "C" void kernel_launch(void* const* d_in, const int* in_sizes, int n_in,
                              void* d_out, int out_size) {
    const float* x    = (const float*)d_in[0];
    const int*   bi   = (const int*)d_in[1];
    const float* son  = (const float*)d_in[2];
    const int*   sbi  = (const int*)d_in[3];
    const float* temp = (const float*)d_in[4];
    const float* Wfx  = (const float*)d_in[5];
    const float* bfx  = (const float*)d_in[6];
    const float* Wx   = (const float*)d_in[7];
    const float* bx   = (const float*)d_in[8];
    const float* Wsl  = (const float*)d_in[9];
    const float* bsl  = (const float*)d_in[10];
    const float* Wq   = (const float*)d_in[11];
    const float* bq   = (const float*)d_in[12];
    const float* Wk   = (const float*)d_in[13];
    const float* bk   = (const float*)d_in[14];
    const float* Wv   = (const float*)d_in[15];
    const float* bv   = (const float*)d_in[16];
    const float* Wck  = (const float*)d_in[17];
    const float* bck  = (const float*)d_in[18];
    const float* Wcv  = (const float*)d_in[19];
    const float* bcv  = (const float*)d_in[20];
    const float* Wout = (const float*)d_in[21];
    float* out = (float*)d_out;

    static cudaStream_t s1 = nullptr, s2 = nullptr;
    static cudaEvent_t eF = nullptr, e1 = nullptr, e2a = nullptr, e2b = nullptr;
    if (s1 == nullptr) {
        cudaStreamCreateWithFlags(&s1, cudaStreamNonBlocking);
        cudaStreamCreateWithFlags(&s2, cudaStreamNonBlocking);
        cudaEventCreateWithFlags(&eF, cudaEventDisableTiming);
        cudaEventCreateWithFlags(&e1, cudaEventDisableTiming);
        cudaEventCreateWithFlags(&e2a, cudaEventDisableTiming);
        cudaEventCreateWithFlags(&e2b, cudaEventDisableTiming);
        cudaFuncSetAttribute(k_gemm_mma, cudaFuncAttributeMaxDynamicSharedMemorySize, SMEM_MMA);
        cudaFuncSetAttribute(k_final_mma, cudaFuncAttributeMaxDynamicSharedMemorySize, SMEM_MMA);
        cudaFuncSetAttribute(k_qkvattn, cudaFuncAttributeMaxDynamicSharedMemorySize, QKV_SMEM);
    }

    // fork
    cudaEventRecord(eF, 0);
    cudaStreamWaitEvent(s1, eF, 0);
    cudaStreamWaitEvent(s2, eF, 0);

    // stream s1: batch bucketing chain (independent of x path)
    k_zero<<<1024, 256, 0, s1>>>();
    k_count<<<80, 256, 0, s1>>>(bi, sbi);
    k_prefix<<<1, 1, 0, s1>>>();
    k_scatter<<<80, 256, 0, s1>>>(bi, sbi);
    cudaEventRecord(e1, s1);

    // stream s2: weight transpose (feeds gemm), then sonata K/V projection
    k_wcomb<<<dim3(512, 2), 256, 0, s2>>>(Wx, Wsl, Wfx);
    cudaEventRecord(e2a, s2);
    k_skv<<<dim3(512, 2), 256, 0, s2>>>(son, Wck, bck, Wcv, bcv);
    cudaEventRecord(e2b, s2);

    // main stream
    k_bcomb<<<1, 512>>>(bx, Wsl, bsl);
    k_cvt_x<<<8192, 256>>>(x);
    cudaStreamWaitEvent(0, e2a, 0);
    k_gemm_mma<<<dim3(8, 128), 256, SMEM_MMA>>>(bfx, temp);
    cudaStreamWaitEvent(0, e1, 0);
    k_tokens<<<dim3(64, 32), 256>>>();
    k_qkvattn<<<64, 256, QKV_SMEM>>>(Wq, bq, Wk, bk, Wv, bv);
    cudaStreamWaitEvent(0, e2b, 0);
    k_cross_score<<<dim3(64, 8), 256>>>();
    k_cross_stat<<<64, 256>>>();
    k_cross_out<<<dim3(64, 8), 256>>>();
    k_P<<<dim3(64, 8), 256>>>(Wout);
    k_final_mma<<<dim3(4, 128, 8), 256, SMEM_MMA>>>(out);
}

// round 15
// speedup vs baseline: 3.0909x; 1.0672x over previous
#include <cuda_runtime.h>
#include <cuda_bf16.h>
#include <cstdint>

#define NT 16384   // x rows
#define MS 4096    // sonata rows
#define NB 8       // batches
#define NH 8       // heads
#define DH 64      // head dim
#define NG 64      // slice groups
#define DM 512     // model dim
#define SCL 0.125f // D^-0.5

#define SW64_(o) ((o) ^ (((o) >> 3) & 0x30))

__device__ __forceinline__ uint32_t smem_to_u32(const void* p) {
    uint32_t a;
    asm("{ .reg .u64 tmp; cvta.to.shared.u64 tmp, %1; cvt.u32.u64 %0, tmp; }"
        : "=r"(a) : "l"(p));
    return a;
}
__device__ __forceinline__ void ldsm4(uint32_t a[4], uint32_t addr) {
    asm volatile("ldmatrix.sync.aligned.m8n8.x4.shared.b16 {%0,%1,%2,%3}, [%4];"
                 : "=r"(a[0]), "=r"(a[1]), "=r"(a[2]), "=r"(a[3]) : "r"(addr));
}
__device__ __forceinline__ void mma16816(float c[4], const uint32_t a[4],
                                         uint32_t b0, uint32_t b1) {
    asm volatile(
        "mma.sync.aligned.m16n8k16.row.col.f32.bf16.bf16.f32 "
        "{%0,%1,%2,%3}, {%4,%5,%6,%7}, {%8,%9}, {%0,%1,%2,%3};"
        : "+f"(c[0]), "+f"(c[1]), "+f"(c[2]), "+f"(c[3])
        : "r"(a[0]), "r"(a[1]), "r"(a[2]), "r"(a[3]), "r"(b0), "r"(b1));
}
__device__ __forceinline__ void cp16(uint32_t dst, const void* src) {
    asm volatile("cp.async.cg.shared.global [%0], [%1], 16;" :: "r"(dst), "l"(src));
}
#define CP_COMMIT() asm volatile("cp.async.commit_group;" ::: "memory")
#define CP_WAIT2() asm volatile("cp.async.wait_group 2;" ::: "memory")
#define CP_WAIT1() asm volatile("cp.async.wait_group 1;" ::: "memory")
#define CP_WAIT0() asm volatile("cp.async.wait_group 0;" ::: "memory")

__device__ __forceinline__ void bsplit(float v, __nv_bfloat16& h, __nv_bfloat16& l) {
    h = __float2bfloat16(v);
    l = __float2bfloat16(v - __bfloat162float(h));
}

// pipelined MMA smem: 3 stages x (AH 8K | AL 8K | BH 8K | BL 8K) = 96KB
#define STG_BYTES 32768
#define OFFS_AH 0
#define OFFS_AL 8192
#define OFFS_BH 16384
#define OFFS_BL 24576
#define SMEM_MMA (3 * STG_BYTES)
#define KSLAB 32
#define NSLAB (DM / KSLAB)

// fused qkv+attn smem: a[64][65] + 3x W[64][64] + q,k,v[64][64] + s[64][64]
#define QKV_SMEM ((64 * 65 + 3 * 4096 + 3 * 4096 + 4096) * 4)

// ---------------- device scratch ----------------
__device__ float g_bcomb[DM];
__device__ float g_fx[(size_t)NT * DM];
__device__ __nv_bfloat16 g_xhi[(size_t)NT * DM], g_xlo[(size_t)NT * DM];
__device__ __nv_bfloat16 g_Bthi[(size_t)2 * DM * DM], g_Btlo[(size_t)2 * DM * DM]; // [1024][512]
__device__ __nv_bfloat16 g_whi[(size_t)NT * DM], g_wlo[(size_t)NT * DM];
__device__ __nv_bfloat16 g_Pthi[(size_t)NB * DM * DM], g_Ptlo[(size_t)NB * DM * DM]; // [b][c][k]
__device__ float g_tokens[NB * NH * NG * DH];
__device__ float g_norms[NB * NH * NG];
__device__ float g_outtok[NB * NH * NG * DH];
__device__ float g_ks[(size_t)MS * DM];
__device__ float g_vs[(size_t)MS * DM];
__device__ float g_scores[(size_t)NB * NH * NG * MS];
__device__ float2 g_cstats[NB * NH * NG];       // per-(bh,g) final softmax (m, inv)
__device__ float2 g_pstat[NB * NH * 8 * NG];    // per-(bh,slice,g) partial (m, s)
__device__ int g_rowlist[NT], g_rowcnt[NB], g_rowstart[NB + 1], g_rowcur[NB];
__device__ int g_mlist[MS], g_mcnt[NB], g_mstart[NB + 1], g_mcur[NB];

// ---------------- setup kernels ----------------
__global__ void k_zero() {
    int i = blockIdx.x * 256 + threadIdx.x;
    if (i < NB * NH * NG * DH) g_tokens[i] = 0.f;
    if (i < NB * NH * NG) g_norms[i] = 0.f;
    if (i < NB) {
        g_rowcnt[i] = 0; g_mcnt[i] = 0;
        g_rowcur[i] = 0; g_mcur[i] = 0;
    }
}

__global__ void k_bcomb(const float* __restrict__ bx, const float* __restrict__ Wsl,
                        const float* __restrict__ bsl) {
    int o = threadIdx.x;  // 512
    int h = o >> 6, g = o & 63;
    float acc = bsl[g];
    for (int d = 0; d < 64; d++) acc = fmaf(bx[h * 64 + d], Wsl[d * 64 + g], acc);
    g_bcomb[o] = acc;
}

// x fp32 -> bf16 hi/lo split
__global__ void k_cvt_x(const float* __restrict__ x) {
    size_t i = (size_t)blockIdx.x * 256 + threadIdx.x;  // one float4 each
    float4 v = ((const float4*)x)[i];
    __nv_bfloat16 h0, h1, h2, h3, l0, l1, l2, l3;
    bsplit(v.x, h0, l0); bsplit(v.y, h1, l1);
    bsplit(v.z, h2, l2); bsplit(v.w, h3, l3);
    ((__nv_bfloat162*)g_xhi)[i * 2 + 0] = __halves2bfloat162(h0, h1);
    ((__nv_bfloat162*)g_xhi)[i * 2 + 1] = __halves2bfloat162(h2, h3);
    ((__nv_bfloat162*)g_xlo)[i * 2 + 0] = __halves2bfloat162(l0, l1);
    ((__nv_bfloat162*)g_xlo)[i * 2 + 1] = __halves2bfloat162(l2, l3);
}

// y==1: Bt rows 0..511 (transposed Wfx); y==0: Bt rows 512..1023 from Wcomb = Wx·Wsl
__global__ void k_wcomb(const float* __restrict__ Wx, const float* __restrict__ Wsl,
                        const float* __restrict__ Wfx) {
    int c = blockIdx.x;  // 0..511
    int t = threadIdx.x;
    if (blockIdx.y == 1) {
        for (int k = t; k < DM; k += 256) {
            __nv_bfloat16 h, l;
            bsplit(Wfx[(size_t)k * DM + c], h, l);
            g_Bthi[(size_t)c * DM + k] = h;
            g_Btlo[(size_t)c * DM + k] = l;
        }
        return;
    }
    __shared__ float s_sl[4096];
    for (int i = t; i < 4096; i += 256) s_sl[i] = Wsl[i];
    __syncthreads();
    for (int o = t; o < 512; o += 256) {
        int h = o >> 6, g = o & 63;
        const float* wxr = Wx + (size_t)c * DM + h * 64;
        float acc = 0.f;
        for (int d = 0; d < 64; d++) acc = fmaf(wxr[d], s_sl[d * 64 + g], acc);
        __nv_bfloat16 hh, ll;
        bsplit(acc, hh, ll);
        g_Bthi[(size_t)(DM + o) * DM + c] = hh;
        g_Btlo[(size_t)(DM + o) * DM + c] = ll;
    }
}

__global__ void k_count(const int* __restrict__ bi, const int* __restrict__ sbi) {
    int i = blockIdx.x * 256 + threadIdx.x;
    if (i < NT) atomicAdd(&g_rowcnt[bi[i]], 1);
    else if (i < NT + MS) atomicAdd(&g_mcnt[sbi[i - NT]], 1);
}

__global__ void k_prefix() {
    if (threadIdx.x == 0) {
        int s = 0;
        for (int b = 0; b < NB; b++) { g_rowstart[b] = s; s += g_rowcnt[b]; }
        g_rowstart[NB] = s;
        s = 0;
        for (int b = 0; b < NB; b++) { g_mstart[b] = s; s += g_mcnt[b]; }
        g_mstart[NB] = s;
    }
}

__global__ void k_scatter(const int* __restrict__ bi, const int* __restrict__ sbi) {
    int i = blockIdx.x * 256 + threadIdx.x;
    if (i < NT) {
        int b = bi[i];
        int p = atomicAdd(&g_rowcur[b], 1);
        g_rowlist[g_rowstart[b] + p] = i;
    } else if (i < NT + MS) {
        int j = i - NT;
        int b = sbi[j];
        int p = atomicAdd(&g_mcur[b], 1);
        g_mlist[g_mstart[b] + p] = j;
    }
}

// ---------------- front GEMM via mma.sync bf16x3, 3-stage pipeline, fused slice-softmax ----------------
__global__ void __launch_bounds__(256, 2)
k_gemm_mma(const float* __restrict__ bfx, const float* __restrict__ temp) {
    extern __shared__ char dynsmem[];
    uint32_t sb = smem_to_u32(dynsmem);
    int t = threadIdx.x;
    int lane = t & 31, wid = t >> 5;
    int wm = (wid & 3) * 32, wn = (wid >> 2) * 64;
    int row0 = blockIdx.y * 128, col0 = blockIdx.x * 128;
    float acc[2][8][4] = {};
    int a_row = wm + (lane & 15);
    int a_u = lane >> 4;
    int b_row = wn + (lane & 7) + ((lane >> 4) << 3);
    int b_u = (lane >> 3) & 1;

    auto load_slab = [&](int kc, int stg) {
        uint32_t sbase = sb + stg * STG_BYTES;
#pragma unroll
        for (int half = 0; half < 2; half++) {
            int idx = half * 256 + t;
            int r = idx >> 2, c = idx & 3;
            uint32_t o = SW64_((uint32_t)(r * 64 + c * 16));
            size_t offa = (size_t)(row0 + r) * DM + kc + c * 8;
            size_t offb = (size_t)(col0 + r) * DM + kc + c * 8;
            cp16(sbase + OFFS_AH + o, g_xhi + offa);
            cp16(sbase + OFFS_AL + o, g_xlo + offa);
            cp16(sbase + OFFS_BH + o, g_Bthi + offb);
            cp16(sbase + OFFS_BL + o, g_Btlo + offb);
        }
        CP_COMMIT();
    };

    load_slab(0, 0);
    load_slab(KSLAB, 1);
#pragma unroll 1
    for (int ch = 0; ch < NSLAB; ch++) {
        if (ch + 2 < NSLAB) { load_slab((ch + 2) * KSLAB, (ch + 2) % 3); CP_WAIT2(); }
        else if (ch + 1 < NSLAB) { CP_WAIT1(); }
        else { CP_WAIT0(); }
        __syncthreads();
        uint32_t sbase = sb + (ch % 3) * STG_BYTES;
#pragma unroll
        for (int ks = 0; ks < 2; ks++) {
            uint32_t ah[2][4], al[2][4];
#pragma unroll
            for (int mt = 0; mt < 2; mt++) {
                uint32_t off = SW64_((uint32_t)((a_row + mt * 16) * 64 + ks * 32 + a_u * 16));
                ldsm4(ah[mt], sbase + OFFS_AH + off);
                ldsm4(al[mt], sbase + OFFS_AL + off);
            }
#pragma unroll
            for (int np = 0; np < 4; np++) {
                uint32_t bh[4], bl[4];
                uint32_t boff = SW64_((uint32_t)((b_row + np * 16) * 64 + ks * 32 + b_u * 16));
                ldsm4(bh, sbase + OFFS_BH + boff);
                ldsm4(bl, sbase + OFFS_BL + boff);
#pragma unroll
                for (int mt = 0; mt < 2; mt++) {
                    mma16816(acc[mt][np * 2 + 0], ah[mt], bh[0], bh[1]);
                    mma16816(acc[mt][np * 2 + 0], ah[mt], bl[0], bl[1]);
                    mma16816(acc[mt][np * 2 + 0], al[mt], bh[0], bh[1]);
                    mma16816(acc[mt][np * 2 + 1], ah[mt], bh[2], bh[3]);
                    mma16816(acc[mt][np * 2 + 1], ah[mt], bl[2], bl[3]);
                    mma16816(acc[mt][np * 2 + 1], al[mt], bh[2], bh[3]);
                }
            }
        }
        __syncthreads();
    }
    int g = lane >> 2, tig = lane & 3;
    bool isfx = (col0 < DM);
    if (isfx) {
#pragma unroll
        for (int mt = 0; mt < 2; mt++)
#pragma unroll
            for (int nt = 0; nt < 8; nt++) {
                int r1 = row0 + wm + mt * 16 + g;
                int c = col0 + wn + nt * 8 + tig * 2;
                float b0v = bfx[c], b1v = bfx[c + 1];
                *(float2*)(g_fx + (size_t)r1 * DM + c) =
                    make_float2(acc[mt][nt][0] + b0v, acc[mt][nt][1] + b1v);
                *(float2*)(g_fx + (size_t)(r1 + 8) * DM + c) =
                    make_float2(acc[mt][nt][2] + b0v, acc[mt][nt][3] + b1v);
            }
    } else {
        // fused slice softmax; w stored only as bf16 hi/lo split
        int cbase = col0 - DM;
        int h = (cbase + wn) >> 6;
        float it = 1.f / temp[h];
#pragma unroll
        for (int mt = 0; mt < 2; mt++)
#pragma unroll
            for (int half = 0; half < 2; half++) {
                int r1 = row0 + wm + mt * 16 + g + half * 8;
                float v[16];
#pragma unroll
                for (int nt = 0; nt < 8; nt++) {
                    int c = cbase + wn + nt * 8 + tig * 2;
                    v[nt * 2 + 0] = (acc[mt][nt][half * 2 + 0] + g_bcomb[c]) * it;
                    v[nt * 2 + 1] = (acc[mt][nt][half * 2 + 1] + g_bcomb[c + 1]) * it;
                }
                float m = v[0];
#pragma unroll
                for (int i = 1; i < 16; i++) m = fmaxf(m, v[i]);
                m = fmaxf(m, __shfl_xor_sync(0xFFFFFFFFu, m, 1));
                m = fmaxf(m, __shfl_xor_sync(0xFFFFFFFFu, m, 2));
                float s = 0.f;
#pragma unroll
                for (int i = 0; i < 16; i++) { v[i] = __expf(v[i] - m); s += v[i]; }
                s += __shfl_xor_sync(0xFFFFFFFFu, s, 1);
                s += __shfl_xor_sync(0xFFFFFFFFu, s, 2);
                float inv = 1.f / s;
#pragma unroll
                for (int nt = 0; nt < 8; nt++) {
                    int cw = cbase + wn + nt * 8 + tig * 2;
                    float w0 = v[nt * 2 + 0] * inv, w1 = v[nt * 2 + 1] * inv;
                    __nv_bfloat16 h0, l0, h1, l1;
                    bsplit(w0, h0, l0); bsplit(w1, h1, l1);
                    *(__nv_bfloat162*)(g_whi + (size_t)r1 * DM + cw) = __halves2bfloat162(h0, h1);
                    *(__nv_bfloat162*)(g_wlo + (size_t)r1 * DM + cw) = __halves2bfloat162(l0, l1);
                }
            }
    }
}

// tokens[b,h,g,d] = sum_{n in b} w[n,h,g] * fx[n,h,d]; norms[b,h,g] = sum w
// grid (64 bh, 32 row-slices); w reconstructed from bf16 hi+lo
__global__ void k_tokens() {
    int bh = blockIdx.x;
    int b = bh >> 3, h = bh & 7;
    int cnt = g_rowcnt[b], start = g_rowstart[b];
    int c0 = (int)(((long long)cnt * blockIdx.y) >> 5);
    int c1 = (int)(((long long)cnt * (blockIdx.y + 1)) >> 5);
    int t = threadIdx.x;
    int tg = (t >> 4) * 4, td = (t & 15) * 4;
    float acc[4][4] = {};
    float nacc[4] = {};
    __shared__ float ws[16][64], fs[16][64];
    __shared__ int rid[16];
    for (int i0 = c0; i0 < c1; i0 += 16) {
        int nr = c1 - i0; if (nr > 16) nr = 16;
        if (t < nr) rid[t] = g_rowlist[start + i0 + t];
        __syncthreads();
        for (int idx = t; idx < nr * 64; idx += 256) {
            int r = idx >> 6, c = idx & 63;
            size_t off = (size_t)rid[r] * DM + h * 64 + c;
            ws[r][c] = __bfloat162float(g_whi[off]) + __bfloat162float(g_wlo[off]);
            fs[r][c] = g_fx[off];
        }
        __syncthreads();
        for (int r = 0; r < nr; r++) {
            float wv[4], fv[4];
#pragma unroll
            for (int i = 0; i < 4; i++) { wv[i] = ws[r][tg + i]; fv[i] = fs[r][td + i]; }
#pragma unroll
            for (int i = 0; i < 4; i++) {
                if (td == 0) nacc[i] += wv[i];
#pragma unroll
                for (int j = 0; j < 4; j++) acc[i][j] = fmaf(wv[i], fv[j], acc[i][j]);
            }
        }
        __syncthreads();
    }
    float* tok = g_tokens + (size_t)bh * NG * DH;
#pragma unroll
    for (int i = 0; i < 4; i++) {
#pragma unroll
        for (int j = 0; j < 4; j++) atomicAdd(&tok[(tg + i) * DH + td + j], acc[i][j]);
        if (td == 0) atomicAdd(&g_norms[bh * NG + tg + i], nacc[i]);
    }
}

// fused q/k/v projection + 64x64 self-attention per (b,h); W prefetched via cp.async
__global__ void k_qkvattn(const float* __restrict__ Wq, const float* __restrict__ bq,
                          const float* __restrict__ Wk, const float* __restrict__ bk,
                          const float* __restrict__ Wv, const float* __restrict__ bv) {
    int bh = blockIdx.x;
    extern __shared__ float fsm[];
    float* s_a = fsm;                 // [64][65]
    float* s_w = fsm + 64 * 65;       // 3 x [64][64]
    float* s_q = s_w + 3 * 4096;
    float* s_k = s_q + 4096;
    float* s_v = s_k + 4096;
    float* s_s = s_v + 4096;          // scores
    uint32_t sb = smem_to_u32(fsm);
    int t = threadIdx.x;
    const float* Ws[3] = {Wq, Wk, Wv};
    const float* bs[3] = {bq, bk, bv};
#pragma unroll
    for (int p = 0; p < 3; p++) {
        uint32_t dst = sb + (uint32_t)(64 * 65 + p * 4096) * 4;
        for (int i = t; i < 1024; i += 256)
            cp16(dst + i * 16, (const char*)Ws[p] + i * 16);
        CP_COMMIT();
    }
    for (int i = t; i < 4096; i += 256) {
        int g = i >> 6, d = i & 63;
        s_a[g * 65 + d] = g_tokens[(size_t)bh * 4096 + i] / (g_norms[bh * 64 + g] + 1e-5f);
    }
    int tx = t & 15, ty = t >> 4;
    float* outs[3] = {s_q, s_k, s_v};
#pragma unroll 1
    for (int p = 0; p < 3; p++) {
        if (p == 0) CP_WAIT2();
        else if (p == 1) CP_WAIT1();
        else CP_WAIT0();
        __syncthreads();
        const float* wp = s_w + p * 4096;
        float acc[4][4] = {};
        for (int k = 0; k < 64; k++) {
            float av[4], bv2[4];
#pragma unroll
            for (int i = 0; i < 4; i++) av[i] = s_a[(ty * 4 + i) * 65 + k];
#pragma unroll
            for (int j = 0; j < 4; j++) bv2[j] = wp[k * 64 + tx * 4 + j];
#pragma unroll
            for (int i = 0; i < 4; i++)
#pragma unroll
                for (int j = 0; j < 4; j++) acc[i][j] = fmaf(av[i], bv2[j], acc[i][j]);
        }
#pragma unroll
        for (int i = 0; i < 4; i++)
#pragma unroll
            for (int j = 0; j < 4; j++)
                outs[p][(ty * 4 + i) * 64 + tx * 4 + j] = acc[i][j] + bs[p][tx * 4 + j];
    }
    __syncthreads();
    {
        float acc[4][4] = {};
        for (int d = 0; d < 64; d++) {
            float av[4], bv2[4];
#pragma unroll
            for (int i = 0; i < 4; i++) av[i] = s_q[(ty * 4 + i) * 64 + d];
#pragma unroll
            for (int j = 0; j < 4; j++) bv2[j] = s_k[(tx * 4 + j) * 64 + d];
#pragma unroll
            for (int i = 0; i < 4; i++)
#pragma unroll
                for (int j = 0; j < 4; j++) acc[i][j] = fmaf(av[i], bv2[j], acc[i][j]);
        }
#pragma unroll
        for (int i = 0; i < 4; i++)
#pragma unroll
            for (int j = 0; j < 4; j++)
                s_s[(ty * 4 + i) * 64 + tx * 4 + j] = acc[i][j] * SCL;
    }
    __syncthreads();
    if (t < 64) {
        float m = -1e30f;
        for (int j = 0; j < 64; j++) m = fmaxf(m, s_s[t * 64 + j]);
        float s = 0.f;
        for (int j = 0; j < 64; j++) { float e = __expf(s_s[t * 64 + j] - m); s_s[t * 64 + j] = e; s += e; }
        float inv = 1.f / s;
        for (int j = 0; j < 64; j++) s_s[t * 64 + j] *= inv;
    }
    __syncthreads();
    float acc[4][4] = {};
    for (int k2 = 0; k2 < 64; k2++) {
        float av[4], bv2[4];
#pragma unroll
        for (int i = 0; i < 4; i++) av[i] = s_s[(ty * 4 + i) * 64 + k2];
#pragma unroll
        for (int j = 0; j < 4; j++) bv2[j] = s_v[k2 * 64 + tx * 4 + j];
#pragma unroll
        for (int i = 0; i < 4; i++)
#pragma unroll
            for (int j = 0; j < 4; j++) acc[i][j] = fmaf(av[i], bv2[j], acc[i][j]);
    }
#pragma unroll
    for (int i = 0; i < 4; i++)
#pragma unroll
        for (int j = 0; j < 4; j++)
            g_outtok[(size_t)bh * 4096 + (ty * 4 + i) * 64 + tx * 4 + j] = acc[i][j];
}

// sonata ks/vs projection: [32768x64] @ [64x64] + bias
__global__ void k_skv(const float* __restrict__ son,
                      const float* __restrict__ Wck, const float* __restrict__ bck,
                      const float* __restrict__ Wcv, const float* __restrict__ bcv) {
    int rt = blockIdx.x;
    int sel = blockIdx.y;
    const float* W = sel ? Wcv : Wck;
    const float* bias = sel ? bcv : bck;
    float* dst = sel ? g_vs : g_ks;
    __shared__ float s_at[64][65];
    __shared__ float s_b[64][64];
    int t = threadIdx.x;
    size_t base = (size_t)rt * 64 * 64;
    for (int i = t; i < 4096; i += 256) {
        s_at[i & 63][i >> 6] = son[base + i];
        s_b[i >> 6][i & 63] = W[i];
    }
    __syncthreads();
    int tx = t & 15, ty = t >> 4;
    float acc[4][4] = {};
    for (int k = 0; k < 64; k++) {
        float av[4], bv2[4];
#pragma unroll
        for (int i = 0; i < 4; i++) av[i] = s_at[k][ty * 4 + i];
#pragma unroll
        for (int j = 0; j < 4; j++) bv2[j] = s_b[k][tx * 4 + j];
#pragma unroll
        for (int i = 0; i < 4; i++)
#pragma unroll
            for (int j = 0; j < 4; j++) acc[i][j] = fmaf(av[i], bv2[j], acc[i][j]);
    }
#pragma unroll
    for (int i = 0; i < 4; i++)
#pragma unroll
        for (int j = 0; j < 4; j++)
            dst[base + (size_t)(ty * 4 + i) * 64 + tx * 4 + j] = acc[i][j] + bias[tx * 4 + j];
}

// cross-attention scores + per-slice online softmax partials: grid (64 bh, 8 slices)
__global__ void k_cross_score() {
    int bh = blockIdx.x, b = bh >> 3, h = bh & 7;
    int cnt = g_mcnt[b], start = g_mstart[b];
    if (cnt == 0) return;
    int sl = blockIdx.y;
    int lo = (int)(((long long)cnt * sl) >> 3);
    int hi = (int)(((long long)cnt * (sl + 1)) >> 3);
    int t = threadIdx.x;
    if (lo >= hi) {
        if (t < 64) g_pstat[((size_t)bh * 8 + sl) * 64 + t] = make_float2(-1e30f, 0.f);
        return;
    }
    __shared__ float s_q[64][65];
    __shared__ float s_kv[32][68];
    __shared__ float s_sc[64][33];
    __shared__ float row_m[64], row_s[64];
    __shared__ int mid[32];
    int tx = t & 15, ty = t >> 4;
    if (t < 64) { row_m[t] = -1e30f; row_s[t] = 0.f; }
    for (int i = t; i < 4096; i += 256) s_q[i >> 6][i & 63] = g_outtok[(size_t)bh * 4096 + i];
    __syncthreads();
    float* sc = g_scores + (size_t)bh * 64 * MS;
    for (int j0 = lo; j0 < hi; j0 += 32) {
        int nj = hi - j0; if (nj > 32) nj = 32;
        if (t < nj) mid[t] = g_mlist[start + j0 + t];
        __syncthreads();
        for (int i = t; i < nj * 64; i += 256) {
            int r = i >> 6, c = i & 63;
            s_kv[r][c] = g_ks[(size_t)mid[r] * DM + h * 64 + c];
        }
        __syncthreads();
        float acc[4][2] = {};
        int j1 = tx * 2;
        for (int d = 0; d < 64; d++) {
            float bv0 = s_kv[j1][d], bv1 = s_kv[j1 + 1][d];
#pragma unroll
            for (int i = 0; i < 4; i++) {
                float q = s_q[ty * 4 + i][d];
                acc[i][0] = fmaf(q, bv0, acc[i][0]);
                acc[i][1] = fmaf(q, bv1, acc[i][1]);
            }
        }
#pragma unroll
        for (int i = 0; i < 4; i++) {
            s_sc[ty * 4 + i][j1] = acc[i][0] * SCL;
            s_sc[ty * 4 + i][j1 + 1] = acc[i][1] * SCL;
        }
        __syncthreads();
        if (t < 64) {
            float cm = -1e30f;
            for (int j = 0; j < nj; j++) cm = fmaxf(cm, s_sc[t][j]);
            float cs = 0.f;
            for (int j = 0; j < nj; j++) cs += __expf(s_sc[t][j] - cm);
            float om = row_m[t], nm = fmaxf(om, cm);
            row_s[t] = row_s[t] * __expf(om - nm) + cs * __expf(cm - nm);
            row_m[t] = nm;
        }
        for (int i = t; i < 64 * 32; i += 256) {
            int g = i >> 5, j = i & 31;
            if (j < nj) sc[(size_t)g * MS + j0 + j] = s_sc[g][j];
        }
        __syncthreads();
    }
    if (t < 64) g_pstat[((size_t)bh * 8 + sl) * 64 + t] = make_float2(row_m[t], row_s[t]);
}

// reduce 8 per-slice partials into final (m, inv) per row: grid (64 bh), 64 thr
__global__ void k_cross_stat() {
    int bh = blockIdx.x, b = bh >> 3;
    int cnt = g_mcnt[b];
    if (cnt == 0) return;
    int t = threadIdx.x;
    float m = -1e30f, s = 0.f;
#pragma unroll
    for (int sl = 0; sl < 8; sl++) {
        float2 p = g_pstat[((size_t)bh * 8 + sl) * 64 + t];
        float nm = fmaxf(m, p.x);
        s = s * __expf(m - nm) + p.y * __expf(p.x - nm);
        m = nm;
    }
    g_cstats[bh * 64 + t] = make_float2(m, 1.f / s);
}

// cross-attention output: grid (64 bh, 8 j-slices); applies exp inline, atomic accumulate
__global__ void k_cross_out() {
    int bh = blockIdx.x, b = bh >> 3, h = bh & 7;
    int cnt = g_mcnt[b], start = g_mstart[b];
    if (cnt == 0) return;
    int sl = blockIdx.y;
    int lo = (int)(((long long)cnt * sl) >> 3);
    int hi = (int)(((long long)cnt * (sl + 1)) >> 3);
    if (lo >= hi) return;
    __shared__ float s_kv[32][64];
    __shared__ float s_cw[64][33];
    __shared__ float2 s_st[64];
    __shared__ int mid[32];
    int t = threadIdx.x;
    int tx = t & 15, ty = t >> 4;
    if (t < 64) s_st[t] = g_cstats[bh * 64 + t];
    const float* sc = g_scores + (size_t)bh * 64 * MS;
    float acc[4][4] = {};
    for (int j0 = lo; j0 < hi; j0 += 32) {
        int nj = hi - j0; if (nj > 32) nj = 32;
        if (t < nj) mid[t] = g_mlist[start + j0 + t];
        __syncthreads();
        for (int i = t; i < nj * 64; i += 256) {
            int r = i >> 6, c = i & 63;
            s_kv[r][c] = g_vs[(size_t)mid[r] * DM + h * 64 + c];
        }
        for (int i = t; i < 64 * 32; i += 256) {
            int g = i >> 5, j = i & 31;
            float2 st = s_st[g];
            s_cw[g][j] = (j < nj) ? __expf(sc[(size_t)g * MS + j0 + j] - st.x) * st.y : 0.f;
        }
        __syncthreads();
        for (int j = 0; j < nj; j++) {
            float vvv[4];
#pragma unroll
            for (int jj = 0; jj < 4; jj++) vvv[jj] = s_kv[j][tx * 4 + jj];
#pragma unroll
            for (int i = 0; i < 4; i++) {
                float c = s_cw[ty * 4 + i][j];
#pragma unroll
                for (int jj = 0; jj < 4; jj++) acc[i][jj] = fmaf(c, vvv[jj], acc[i][jj]);
            }
        }
        __syncthreads();
    }
#pragma unroll
    for (int i = 0; i < 4; i++)
#pragma unroll
        for (int jj = 0; jj < 4; jj++)
            atomicAdd(&g_outtok[(size_t)bh * 4096 + (ty * 4 + i) * 64 + tx * 4 + jj], acc[i][jj]);
}

// P[b, h*64+g, c] = sum_d out_tok[b,h,g,d] * W_out[h*64+d, c], stored transposed bf16 hi/lo
__global__ void k_P(const float* __restrict__ Wout) {
    int bh = blockIdx.x, b = bh >> 3, h = bh & 7;
    int col0 = blockIdx.y * 64;
    __shared__ float s_a[64][65];
    __shared__ float s_b[64][64];
    int t = threadIdx.x;
    for (int i = t; i < 4096; i += 256) {
        int r = i >> 6, c = i & 63;
        s_a[r][c] = g_outtok[(size_t)bh * 4096 + i];
        s_b[r][c] = Wout[(size_t)(h * 64 + r) * DM + col0 + c];
    }
    __syncthreads();
    int tx = t & 15, ty = t >> 4;
    float acc[4][4] = {};
    for (int d = 0; d < 64; d++) {
        float av[4], bv[4];
#pragma unroll
        for (int i = 0; i < 4; i++) av[i] = s_a[ty * 4 + i][d];
#pragma unroll
        for (int j = 0; j < 4; j++) bv[j] = s_b[d][tx * 4 + j];
#pragma unroll
        for (int i = 0; i < 4; i++)
#pragma unroll
            for (int j = 0; j < 4; j++) acc[i][j] = fmaf(av[i], bv[j], acc[i][j]);
    }
#pragma unroll
    for (int i = 0; i < 4; i++)
#pragma unroll
        for (int j = 0; j < 4; j++) {
            int r = h * 64 + ty * 4 + i;       // k index of P
            int c = col0 + tx * 4 + j;         // output col
            __nv_bfloat16 hh, ll;
            bsplit(acc[i][j], hh, ll);
            g_Pthi[((size_t)b * DM + c) * DM + r] = hh;
            g_Ptlo[((size_t)b * DM + c) * DM + r] = ll;
        }
}

// out[n, :] = w[n, :] @ P[batch(n)] via mma.sync bf16x3, gathered rows, 3-stage pipeline
__global__ void __launch_bounds__(256, 2)
k_final_mma(float* __restrict__ out) {
    int b = blockIdx.z;
    int cnt = g_rowcnt[b];
    int r0 = blockIdx.y * 128;
    if (r0 >= cnt) return;
    int nr = cnt - r0; if (nr > 128) nr = 128;
    extern __shared__ char dynsmem[];
    uint32_t sb = smem_to_u32(dynsmem);
    __shared__ int rid[128];
    int t = threadIdx.x;
    int lane = t & 31, wid = t >> 5;
    int wm = (wid & 3) * 32, wn = (wid >> 2) * 64;
    int col0 = blockIdx.x * 128;
    int start = g_rowstart[b];
    if (t < 128) rid[t] = g_rowlist[start + r0 + (t < nr ? t : nr - 1)];
    __syncthreads();
    float acc[2][8][4] = {};
    int a_row = wm + (lane & 15);
    int a_u = lane >> 4;
    int b_row = wn + (lane & 7) + ((lane >> 4) << 3);
    int b_u = (lane >> 3) & 1;
    const __nv_bfloat16* Ph = g_Pthi + ((size_t)b * DM + col0) * DM;
    const __nv_bfloat16* Pl = g_Ptlo + ((size_t)b * DM + col0) * DM;

    auto load_slab = [&](int kc, int stg) {
        uint32_t sbase = sb + stg * STG_BYTES;
#pragma unroll
        for (int half = 0; half < 2; half++) {
            int idx = half * 256 + t;
            int r = idx >> 2, c = idx & 3;
            uint32_t o = SW64_((uint32_t)(r * 64 + c * 16));
            size_t offa = (size_t)rid[r] * DM + kc + c * 8;
            size_t offb = (size_t)r * DM + kc + c * 8;
            cp16(sbase + OFFS_AH + o, g_whi + offa);
            cp16(sbase + OFFS_AL + o, g_wlo + offa);
            cp16(sbase + OFFS_BH + o, Ph + offb);
            cp16(sbase + OFFS_BL + o, Pl + offb);
        }
        CP_COMMIT();
    };

    load_slab(0, 0);
    load_slab(KSLAB, 1);
#pragma unroll 1
    for (int ch = 0; ch < NSLAB; ch++) {
        if (ch + 2 < NSLAB) { load_slab((ch + 2) * KSLAB, (ch + 2) % 3); CP_WAIT2(); }
        else if (ch + 1 < NSLAB) { CP_WAIT1(); }
        else { CP_WAIT0(); }
        __syncthreads();
        uint32_t sbase = sb + (ch % 3) * STG_BYTES;
#pragma unroll
        for (int ks = 0; ks < 2; ks++) {
            uint32_t ah[2][4], al[2][4];
#pragma unroll
            for (int mt = 0; mt < 2; mt++) {
                uint32_t off = SW64_((uint32_t)((a_row + mt * 16) * 64 + ks * 32 + a_u * 16));
                ldsm4(ah[mt], sbase + OFFS_AH + off);
                ldsm4(al[mt], sbase + OFFS_AL + off);
            }
#pragma unroll
            for (int np = 0; np < 4; np++) {
                uint32_t bh[4], bl[4];
                uint32_t boff = SW64_((uint32_t)((b_row + np * 16) * 64 + ks * 32 + b_u * 16));
                ldsm4(bh, sbase + OFFS_BH + boff);
                ldsm4(bl, sbase + OFFS_BL + boff);
#pragma unroll
                for (int mt = 0; mt < 2; mt++) {
                    mma16816(acc[mt][np * 2 + 0], ah[mt], bh[0], bh[1]);
                    mma16816(acc[mt][np * 2 + 0], ah[mt], bl[0], bl[1]);
                    mma16816(acc[mt][np * 2 + 0], al[mt], bh[0], bh[1]);
                    mma16816(acc[mt][np * 2 + 1], ah[mt], bh[2], bh[3]);
                    mma16816(acc[mt][np * 2 + 1], ah[mt], bl[2], bl[3]);
                    mma16816(acc[mt][np * 2 + 1], al[mt], bh[2], bh[3]);
                }
            }
        }
        __syncthreads();
    }
    int g = lane >> 2, tig = lane & 3;
#pragma unroll
    for (int mt = 0; mt < 2; mt++)
#pragma unroll
        for (int nt = 0; nt < 8; nt++) {
            int ml = wm + mt * 16 + g;
            int c = col0 + wn + nt * 8 + tig * 2;
            if (ml < nr)
                *(float2*)(out + (size_t)rid[ml] * DM + c) =
                    make_float2(acc[mt][nt][0], acc[mt][nt][1]);
            if (ml + 8 < nr)
                *(float2*)(out + (size_t)rid[ml + 8] * DM + c) =
                    make_float2(acc[mt][nt][2], acc[mt][nt][3]);
        }
}

extern "C" void kernel_launch(void* const* d_in, const int* in_sizes, int n_in,
                              void* d_out, int out_size) {
    const float* x    = (const float*)d_in[0];
    const int*   bi   = (const int*)d_in[1];
    const float* son  = (const float*)d_in[2];
    const int*   sbi  = (const int*)d_in[3];
    const float* temp = (const float*)d_in[4];
    const float* Wfx  = (const float*)d_in[5];
    const float* bfx  = (const float*)d_in[6];
    const float* Wx   = (const float*)d_in[7];
    const float* bx   = (const float*)d_in[8];
    const float* Wsl  = (const float*)d_in[9];
    const float* bsl  = (const float*)d_in[10];
    const float* Wq   = (const float*)d_in[11];
    const float* bq   = (const float*)d_in[12];
    const float* Wk   = (const float*)d_in[13];
    const float* bk   = (const float*)d_in[14];
    const float* Wv   = (const float*)d_in[15];
    const float* bv   = (const float*)d_in[16];
    const float* Wck  = (const float*)d_in[17];
    const float* bck  = (const float*)d_in[18];
    const float* Wcv  = (const float*)d_in[19];
    const float* bcv  = (const float*)d_in[20];
    const float* Wout = (const float*)d_in[21];
    float* out = (float*)d_out;

    static cudaStream_t s1 = nullptr, s2 = nullptr;
    static cudaEvent_t eF = nullptr, e1 = nullptr, e2a = nullptr, e2b = nullptr;
    if (s1 == nullptr) {
        cudaStreamCreateWithFlags(&s1, cudaStreamNonBlocking);
        cudaStreamCreateWithFlags(&s2, cudaStreamNonBlocking);
        cudaEventCreateWithFlags(&eF, cudaEventDisableTiming);
        cudaEventCreateWithFlags(&e1, cudaEventDisableTiming);
        cudaEventCreateWithFlags(&e2a, cudaEventDisableTiming);
        cudaEventCreateWithFlags(&e2b, cudaEventDisableTiming);
        cudaFuncSetAttribute(k_gemm_mma, cudaFuncAttributeMaxDynamicSharedMemorySize, SMEM_MMA);
        cudaFuncSetAttribute(k_final_mma, cudaFuncAttributeMaxDynamicSharedMemorySize, SMEM_MMA);
        cudaFuncSetAttribute(k_qkvattn, cudaFuncAttributeMaxDynamicSharedMemorySize, QKV_SMEM);
    }

    // fork
    cudaEventRecord(eF, 0);
    cudaStreamWaitEvent(s1, eF, 0);
    cudaStreamWaitEvent(s2, eF, 0);

    // stream s1: batch bucketing chain (independent of x path)
    k_zero<<<1024, 256, 0, s1>>>();
    k_count<<<80, 256, 0, s1>>>(bi, sbi);
    k_prefix<<<1, 1, 0, s1>>>();
    k_scatter<<<80, 256, 0, s1>>>(bi, sbi);
    cudaEventRecord(e1, s1);

    // stream s2: bias fold + weight transpose (feed gemm), then sonata K/V projection
    k_bcomb<<<1, 512, 0, s2>>>(bx, Wsl, bsl);
    k_wcomb<<<dim3(512, 2), 256, 0, s2>>>(Wx, Wsl, Wfx);
    cudaEventRecord(e2a, s2);
    k_skv<<<dim3(512, 2), 256, 0, s2>>>(son, Wck, bck, Wcv, bcv);
    cudaEventRecord(e2b, s2);

    // main stream
    k_cvt_x<<<8192, 256>>>(x);
    cudaStreamWaitEvent(0, e2a, 0);
    k_gemm_mma<<<dim3(8, 128), 256, SMEM_MMA>>>(bfx, temp);
    cudaStreamWaitEvent(0, e1, 0);
    k_tokens<<<dim3(64, 32), 256>>>();
    k_qkvattn<<<64, 256, QKV_SMEM>>>(Wq, bq, Wk, bk, Wv, bv);
    cudaStreamWaitEvent(0, e2b, 0);
    k_cross_score<<<dim3(64, 8), 256>>>();
    k_cross_stat<<<64, 64>>>();
    k_cross_out<<<dim3(64, 8), 256>>>();
    k_P<<<dim3(64, 8), 256>>>(Wout);
    k_final_mma<<<dim3(4, 128, 8), 256, SMEM_MMA>>>(out);
}